// round 11
// baseline (speedup 1.0000x reference)
#include <cuda_runtime.h>
#include <cuda_bf16.h>
#include <math.h>
#include <stdint.h>

// ---------------- problem constants ----------------
#define Bn    32
#define Gn    512
#define Cn    768
#define Hn    12
#define HD    64
#define Tn    513              // G+1
#define MROWS (Bn*Tn)          // 16416
#define BG    16384
#define FFn   3072
#define ADn   16
#define MIDn  12
#define H1n   6
#define N1n   128
#define NB1   (BG/N1n)         // 128
#define NCL   2048
#define D1n   6272
#define NV    6
#define NQ1   (NV*3*MIDn)      // 216
#define EPSf  1e-5f

// ---------------- scratch (device globals; no allocation) ----------------
__device__ float  g_y   [MROWS*Cn];
__device__ float  g_qkv [MROWS*3*Cn];
__device__ float  g_att [MROWS*Cn];
__device__ float  g_x1  [MROWS*Cn];
__device__ float  g_hfc [MROWS*FFn];
__device__ float  g_xffn[MROWS*Cn];
__device__ float  g_x2  [MROWS*Cn];
__device__ float  g_g3   [NCL*Cn];
__device__ float  g_bview[NV*D1n*Cn];
__device__ float  g_z    [BG*Cn];          // nhat (un-affined LN of feat)
__device__ float  g_qkv1 [BG*NQ1];
__device__ float  g_weff [NQ1*Cn];
__device__ float  g_beff [NQ1];
__device__ float  g_wrnd [FFn*Cn];
// cluster (3d) pooling buffers
__device__ float  g_scomb [NCL*Cn];
__device__ double g_colsum[Cn];
__device__ double g_colsq [Cn];
__device__ float  g_mean[Cn];
__device__ float  g_rstd[Cn];
__device__ int    g_hist[NCL+1];
__device__ int    g_off [NCL+1];
__device__ int    g_cur [NCL+1];
__device__ int    g_ord [BG];
// batched view pooling buffers
__device__ int    g_hist6[NV*(D1n+1)];
__device__ int    g_off6 [NV*(D1n+1)];
__device__ int    g_cur6 [NV*(D1n+1)];
__device__ int    g_ord6 [NV*BG];
__device__ float  g_scomb6[(size_t)NV*D1n*Cn];
__device__ double g_colsum6[NV*Cn];
__device__ double g_colsq6 [NV*Cn];
__device__ float  g_mean6[NV*Cn];
__device__ float  g_rstd6[NV*Cn];
__device__ float  g_o16  [NV*BG*MIDn];

// ---------------- helpers ----------------
__device__ __forceinline__ float blockReduceSum256(float v, float* red) {
    int tid = threadIdx.x;
    red[tid] = v; __syncthreads();
    #pragma unroll
    for (int o = 128; o > 0; o >>= 1) {
        if (tid < o) red[tid] += red[tid + o];
        __syncthreads();
    }
    float r = red[0];
    __syncthreads();
    return r;
}
__device__ __forceinline__ float blockReduceMax256(float v, float* red) {
    int tid = threadIdx.x;
    red[tid] = v; __syncthreads();
    #pragma unroll
    for (int o = 128; o > 0; o >>= 1) {
        if (tid < o) red[tid] = fmaxf(red[tid], red[tid + o]);
        __syncthreads();
    }
    float r = red[0];
    __syncthreads();
    return r;
}
__device__ __forceinline__ float quick_gelu(float x) {
    return x / (1.f + expf(-1.702f * x));
}
__device__ __forceinline__ float gelu_exact(float x) {
    return 0.5f * x * (1.f + erff(x * 0.70710678118654752f));
}
__device__ __forceinline__ int featRow(int i) {
    return (i >> 9) * Tn + 1 + (i & 511);
}
__device__ __forceinline__ float tf32r(float f) {
    uint32_t u;
    asm volatile("cvt.rna.tf32.f32 %0, %1;" : "=r"(u) : "f"(f));
    return __uint_as_float(u);
}

// ---------------- weight tf32 rounding ----------------
__global__ void round_w(const float* __restrict__ src, float* __restrict__ dst, int n4)
{
    int i = blockIdx.x * 256 + threadIdx.x;
    if (i >= n4) return;
    float4 v = ((const float4*)src)[i];
    v.x = tf32r(v.x); v.y = tf32r(v.y); v.z = tf32r(v.z); v.w = tf32r(v.w);
    ((float4*)dst)[i] = v;
}

// ---------------- LayerNorm (tf32-rounded out) ----------------
__global__ void ln_kernel(const float* __restrict__ in, const float* __restrict__ g,
                          const float* __restrict__ b, float* __restrict__ out, int featmode)
{
    int r = blockIdx.x;
    int row = featmode ? featRow(r) : r;
    const float* x = in + (size_t)row * Cn;
    __shared__ float xs[Cn];
    __shared__ float red[256];
    int tid = threadIdx.x;
    float s0 = 0.f;
    for (int c = tid; c < Cn; c += 256) { float v = x[c]; xs[c] = v; s0 += v; }
    float mean = blockReduceSum256(s0, red) * (1.f / Cn);
    float s1 = 0.f;
    for (int c = tid; c < Cn; c += 256) { float d = xs[c] - mean; s1 += d * d; }
    float var = blockReduceSum256(s1, red) * (1.f / Cn);
    float inv = rsqrtf(var + EPSf);
    float* op = out + (size_t)r * Cn;
    for (int c = tid; c < Cn; c += 256)
        op[c] = tf32r((xs[c] - mean) * inv * g[c] + b[c]);
}

// ---------------- WIDE mma.sync tf32 NT GEMM: block 128x256, warp tile 64x64 ----------------
// 256 threads, 8 warps in 2(m) x 4(n). Requires N % 256 == 0, K % 16 == 0.
// 3-stage cp.async pipeline. 1.0 LDS per mma.
#define GEMMW_SMEM (3 * (128 + 256) * 20 * 4)   // 92160 bytes
template <int EPI>
__global__ void __launch_bounds__(256) gemm_wide(
    const float* __restrict__ A, const float* __restrict__ W,
    const float* __restrict__ bias, const float* __restrict__ res,
    float* __restrict__ C, int M, int N, int K)
{
    extern __shared__ float sm_[];
    int tid = threadIdx.x;
    int bm = blockIdx.x * 128, bn = blockIdx.y * 256;
    int lane = tid & 31, wid = tid >> 5;
    int wm = (wid & 1) * 64, wn = (wid >> 1) * 64;
    int gid = lane >> 2, tg = lane & 3;

    float acc[4][8][4];
    #pragma unroll
    for (int a = 0; a < 4; a++)
        #pragma unroll
        for (int b = 0; b < 8; b++)
            #pragma unroll
            for (int c = 0; c < 4; c++) acc[a][b][c] = 0.f;

    auto prefetch = [&](int kt, int s) {
        int k0 = kt * 16;
        float* As = sm_ + s * 2560;
        float* Bs = sm_ + 7680 + s * 5120;
        {   // A: 128 rows x 16 floats; 2 chunks per thread
            int r = tid >> 1;
            int c = (tid & 1) * 8;
            int arow = bm + r;
            const float* asrc = A + (size_t)(arow < M ? arow : 0) * K + k0 + c;
            int asz = (arow < M) ? 16 : 0;
            #pragma unroll
            for (int j = 0; j < 2; j++) {
                uint32_t adst = (uint32_t)__cvta_generic_to_shared(&As[r * 20 + c + j * 4]);
                asm volatile("cp.async.cg.shared.global [%0], [%1], 16, %2;\n"
                             :: "r"(adst), "l"(asrc + j * 4), "r"(asz));
            }
        }
        {   // B: 256 rows x 16 floats; 4 chunks per thread (N % 256 == 0 -> always valid)
            const float* bsrc = W + (size_t)(bn + tid) * K + k0;
            #pragma unroll
            for (int j = 0; j < 4; j++) {
                uint32_t bdst = (uint32_t)__cvta_generic_to_shared(&Bs[tid * 20 + j * 4]);
                asm volatile("cp.async.cg.shared.global [%0], [%1], 16;\n"
                             :: "r"(bdst), "l"(bsrc + j * 4));
            }
        }
    };

    int nt = K / 16;
    prefetch(0, 0);
    asm volatile("cp.async.commit_group;\n");
    if (nt > 1) prefetch(1, 1);
    asm volatile("cp.async.commit_group;\n");

    int buf = 0;
    for (int t = 0; t < nt; t++) {
        asm volatile("cp.async.wait_group 1;\n");
        __syncthreads();
        if (t + 2 < nt) prefetch(t + 2, (buf + 2) % 3);
        asm volatile("cp.async.commit_group;\n");
        const float* As = sm_ + buf * 2560;
        const float* Bs = sm_ + 7680 + buf * 5120;
        #pragma unroll
        for (int kk = 0; kk < 2; kk++) {
            int kb = kk * 8;
            uint32_t af[4][4], bf[8][2];
            #pragma unroll
            for (int mi = 0; mi < 4; mi++) {
                int r = wm + mi * 16 + gid;
                af[mi][0] = __float_as_uint(As[(r    ) * 20 + kb + tg    ]);
                af[mi][1] = __float_as_uint(As[(r + 8) * 20 + kb + tg    ]);
                af[mi][2] = __float_as_uint(As[(r    ) * 20 + kb + tg + 4]);
                af[mi][3] = __float_as_uint(As[(r + 8) * 20 + kb + tg + 4]);
            }
            #pragma unroll
            for (int ni = 0; ni < 8; ni++) {
                int n0 = wn + ni * 8 + gid;
                bf[ni][0] = __float_as_uint(Bs[n0 * 20 + kb + tg    ]);
                bf[ni][1] = __float_as_uint(Bs[n0 * 20 + kb + tg + 4]);
            }
            #pragma unroll
            for (int mi = 0; mi < 4; mi++)
                #pragma unroll
                for (int ni = 0; ni < 8; ni++)
                    asm volatile(
                        "mma.sync.aligned.m16n8k8.row.col.f32.tf32.tf32.f32 "
                        "{%0,%1,%2,%3}, {%4,%5,%6,%7}, {%8,%9}, {%0,%1,%2,%3};\n"
                        : "+f"(acc[mi][ni][0]), "+f"(acc[mi][ni][1]),
                          "+f"(acc[mi][ni][2]), "+f"(acc[mi][ni][3])
                        : "r"(af[mi][0]), "r"(af[mi][1]), "r"(af[mi][2]), "r"(af[mi][3]),
                          "r"(bf[ni][0]), "r"(bf[ni][1]));
        }
        __syncthreads();
        buf = (buf + 1) % 3;
    }

    #pragma unroll
    for (int mi = 0; mi < 4; mi++) {
        #pragma unroll
        for (int ni = 0; ni < 8; ni++) {
            int m0 = bm + wm + mi * 16 + gid;
            int n0 = bn + wn + ni * 8 + tg * 2;
            float b0 = bias[n0], b1 = bias[n0 + 1];
            #pragma unroll
            for (int hh = 0; hh < 2; hh++) {
                int m = m0 + hh * 8;
                if (m >= M) continue;
                float v0 = acc[mi][ni][hh * 2 + 0] + b0;
                float v1 = acc[mi][ni][hh * 2 + 1] + b1;
                if (EPI == 1) { v0 = tf32r(quick_gelu(v0)); v1 = tf32r(quick_gelu(v1)); }
                if (EPI == 2) {
                    float2 rr = *(const float2*)&res[(size_t)m * N + n0];
                    v0 += rr.x; v1 += rr.y;
                }
                float2 vv; vv.x = v0; vv.y = v1;
                *(float2*)&C[(size_t)m * N + n0] = vv;
            }
        }
    }
}

// ---------------- mma.sync tf32 NT GEMM, 128-wide (kept for N=216 view GEMM) ----------------
#define GEMM_SMEM (3 * 2 * 128 * 20 * 4)   // 61440 bytes
template <int EPI>
__global__ void __launch_bounds__(256, 2) gemm_tf32(
    const float* __restrict__ A, const float* __restrict__ W,
    const float* __restrict__ bias, const float* __restrict__ res,
    float* __restrict__ C, int M, int N, int K)
{
    extern __shared__ float sm_[];
    int tid = threadIdx.x;
    int bm = blockIdx.x * 128, bn = blockIdx.y * 128;
    int lane = tid & 31, wid = tid >> 5;
    int wm = (wid & 1) * 64, wn = (wid >> 1) * 32;
    int gid = lane >> 2, tg = lane & 3;

    float acc[4][4][4];
    #pragma unroll
    for (int a = 0; a < 4; a++)
        #pragma unroll
        for (int b = 0; b < 4; b++)
            #pragma unroll
            for (int c = 0; c < 4; c++) acc[a][b][c] = 0.f;

    auto prefetch = [&](int kt, int s) {
        int k0 = kt * 16;
        float* As = sm_ + s * 2560;
        float* Bs = sm_ + 7680 + s * 2560;
        #pragma unroll
        for (int i = 0; i < 2; i++) {
            int r = (tid >> 2) + i * 64;
            int c = (tid & 3) * 4;
            int arow = bm + r;
            const float* asrc = A + (size_t)(arow < M ? arow : 0) * K + k0 + c;
            uint32_t adst = (uint32_t)__cvta_generic_to_shared(&As[r * 20 + c]);
            int asz = (arow < M) ? 16 : 0;
            asm volatile("cp.async.cg.shared.global [%0], [%1], 16, %2;\n"
                         :: "r"(adst), "l"(asrc), "r"(asz));
            int brow = bn + r;
            const float* bsrc = W + (size_t)(brow < N ? brow : 0) * K + k0 + c;
            uint32_t bdst = (uint32_t)__cvta_generic_to_shared(&Bs[r * 20 + c]);
            int bsz = (brow < N) ? 16 : 0;
            asm volatile("cp.async.cg.shared.global [%0], [%1], 16, %2;\n"
                         :: "r"(bdst), "l"(bsrc), "r"(bsz));
        }
    };

    int nt = K / 16;
    prefetch(0, 0);
    asm volatile("cp.async.commit_group;\n");
    if (nt > 1) prefetch(1, 1);
    asm volatile("cp.async.commit_group;\n");

    int buf = 0;
    for (int t = 0; t < nt; t++) {
        asm volatile("cp.async.wait_group 1;\n");
        __syncthreads();
        if (t + 2 < nt) prefetch(t + 2, (buf + 2) % 3);
        asm volatile("cp.async.commit_group;\n");
        const float* As = sm_ + buf * 2560;
        const float* Bs = sm_ + 7680 + buf * 2560;
        #pragma unroll
        for (int kk = 0; kk < 2; kk++) {
            int kb = kk * 8;
            uint32_t af[4][4], bf[4][2];
            #pragma unroll
            for (int mi = 0; mi < 4; mi++) {
                int r = wm + mi * 16 + gid;
                af[mi][0] = __float_as_uint(As[(r    ) * 20 + kb + tg    ]);
                af[mi][1] = __float_as_uint(As[(r + 8) * 20 + kb + tg    ]);
                af[mi][2] = __float_as_uint(As[(r    ) * 20 + kb + tg + 4]);
                af[mi][3] = __float_as_uint(As[(r + 8) * 20 + kb + tg + 4]);
            }
            #pragma unroll
            for (int ni = 0; ni < 4; ni++) {
                int n0 = wn + ni * 8 + gid;
                bf[ni][0] = __float_as_uint(Bs[n0 * 20 + kb + tg    ]);
                bf[ni][1] = __float_as_uint(Bs[n0 * 20 + kb + tg + 4]);
            }
            #pragma unroll
            for (int mi = 0; mi < 4; mi++)
                #pragma unroll
                for (int ni = 0; ni < 4; ni++)
                    asm volatile(
                        "mma.sync.aligned.m16n8k8.row.col.f32.tf32.tf32.f32 "
                        "{%0,%1,%2,%3}, {%4,%5,%6,%7}, {%8,%9}, {%0,%1,%2,%3};\n"
                        : "+f"(acc[mi][ni][0]), "+f"(acc[mi][ni][1]),
                          "+f"(acc[mi][ni][2]), "+f"(acc[mi][ni][3])
                        : "r"(af[mi][0]), "r"(af[mi][1]), "r"(af[mi][2]), "r"(af[mi][3]),
                          "r"(bf[ni][0]), "r"(bf[ni][1]));
        }
        __syncthreads();
        buf = (buf + 1) % 3;
    }

    #pragma unroll
    for (int mi = 0; mi < 4; mi++) {
        #pragma unroll
        for (int ni = 0; ni < 4; ni++) {
            int m0 = bm + wm + mi * 16 + gid;
            int n0 = bn + wn + ni * 8 + tg * 2;
            if (n0 >= N) continue;
            float b0 = bias[n0], b1 = bias[n0 + 1];
            #pragma unroll
            for (int hh = 0; hh < 2; hh++) {
                int m = m0 + hh * 8;
                if (m >= M) continue;
                float v0 = acc[mi][ni][hh * 2 + 0] + b0;
                float v1 = acc[mi][ni][hh * 2 + 1] + b1;
                if (EPI == 1) { v0 = tf32r(quick_gelu(v0)); v1 = tf32r(quick_gelu(v1)); }
                if (EPI == 2) {
                    float2 rr = *(const float2*)&res[(size_t)m * N + n0];
                    v0 += rr.x; v1 += rr.y;
                }
                float2 vv; vv.x = v0; vv.y = v1;
                *(float2*)&C[(size_t)m * N + n0] = vv;
            }
        }
    }
}

// ---------------- tensor-core flash attention (proven R6 version) ----------------
#define ATTN_SMEM ((128 + 64 + 64) * 68 * 4)
__global__ void __launch_bounds__(256) attn_tc(const float* __restrict__ qkv,
                                               float* __restrict__ out)
{
    extern __shared__ float sm[];
    float* Qs = sm;
    float* Ks = sm + 128 * 68;
    float* Vt = sm + 192 * 68;

    int qb = blockIdx.x, h = blockIdx.y, b = blockIdx.z;
    int tid = threadIdx.x, lane = tid & 31, wid = tid >> 5;
    int gid = lane >> 2, tg = lane & 3;
    int wm = wid * 16;
    int qbase = qb * 128;

    {
        int r = tid >> 1, c0 = (tid & 1) * 32;
        int t = qbase + r;
        bool valid = (t < Tn);
        const float* qp = qkv + (size_t)(b * Tn + (valid ? t : 0)) * (3 * Cn) + h * HD + c0;
        #pragma unroll
        for (int i = 0; i < 8; i++) {
            float4 v = *(const float4*)(qp + i * 4);
            float4 w;
            w.x = valid ? tf32r(v.x * 0.125f) : 0.f;
            w.y = valid ? tf32r(v.y * 0.125f) : 0.f;
            w.z = valid ? tf32r(v.z * 0.125f) : 0.f;
            w.w = valid ? tf32r(v.w * 0.125f) : 0.f;
            *(float4*)&Qs[r * 68 + c0 + i * 4] = w;
        }
    }

    float m0 = -1e30f, m1 = -1e30f, l0 = 0.f, l1 = 0.f;
    float o[8][4];
    #pragma unroll
    for (int ni = 0; ni < 8; ni++)
        #pragma unroll
        for (int j = 0; j < 4; j++) o[ni][j] = 0.f;

    for (int kb = 0; kb < 9; kb++) {
        int kbase = kb * 64;
        __syncthreads();
        {
            int r = tid >> 2, c0 = (tid & 3) * 16;
            int t = kbase + r;
            bool valid = (t < Tn);
            const float* kp = qkv + (size_t)(b * Tn + (valid ? t : 0)) * (3 * Cn) + Cn + h * HD + c0;
            const float* vp = kp + Cn;
            int low = r & 7;
            int pr = (r & ~7) | (((low & 3) << 1) | (low >> 2));
            #pragma unroll
            for (int i = 0; i < 16; i += 4) {
                float4 kv4 = *(const float4*)(kp + i);
                float4 w;
                w.x = valid ? tf32r(kv4.x) : 0.f;
                w.y = valid ? tf32r(kv4.y) : 0.f;
                w.z = valid ? tf32r(kv4.z) : 0.f;
                w.w = valid ? tf32r(kv4.w) : 0.f;
                *(float4*)&Ks[pr * 68 + c0 + i] = w;
            }
            #pragma unroll
            for (int i = 0; i < 16; i++)
                Vt[(c0 + i) * 68 + r] = valid ? tf32r(vp[i]) : 0.f;
        }
        __syncthreads();

        float s[8][4];
        #pragma unroll
        for (int ni = 0; ni < 8; ni++)
            #pragma unroll
            for (int j = 0; j < 4; j++) s[ni][j] = 0.f;
        #pragma unroll
        for (int ks = 0; ks < 8; ks++) {
            int k8 = ks * 8;
            uint32_t af[4];
            int r = wm + gid;
            af[0] = __float_as_uint(Qs[(r    ) * 68 + k8 + tg    ]);
            af[1] = __float_as_uint(Qs[(r + 8) * 68 + k8 + tg    ]);
            af[2] = __float_as_uint(Qs[(r    ) * 68 + k8 + tg + 4]);
            af[3] = __float_as_uint(Qs[(r + 8) * 68 + k8 + tg + 4]);
            #pragma unroll
            for (int ni = 0; ni < 8; ni++) {
                uint32_t b0 = __float_as_uint(Ks[(ni * 8 + gid) * 68 + k8 + tg    ]);
                uint32_t b1 = __float_as_uint(Ks[(ni * 8 + gid) * 68 + k8 + tg + 4]);
                asm volatile(
                    "mma.sync.aligned.m16n8k8.row.col.f32.tf32.tf32.f32 "
                    "{%0,%1,%2,%3}, {%4,%5,%6,%7}, {%8,%9}, {%0,%1,%2,%3};\n"
                    : "+f"(s[ni][0]), "+f"(s[ni][1]), "+f"(s[ni][2]), "+f"(s[ni][3])
                    : "r"(af[0]), "r"(af[1]), "r"(af[2]), "r"(af[3]),
                      "r"(b0), "r"(b1));
            }
        }

        float vmax0 = -1e30f, vmax1 = -1e30f;
        #pragma unroll
        for (int ni = 0; ni < 8; ni++) {
            if (kbase + ni * 8 + tg >= Tn)     { s[ni][0] = -1e30f; s[ni][2] = -1e30f; }
            if (kbase + ni * 8 + tg + 4 >= Tn) { s[ni][1] = -1e30f; s[ni][3] = -1e30f; }
            vmax0 = fmaxf(vmax0, fmaxf(s[ni][0], s[ni][1]));
            vmax1 = fmaxf(vmax1, fmaxf(s[ni][2], s[ni][3]));
        }
        vmax0 = fmaxf(vmax0, __shfl_xor_sync(0xffffffffu, vmax0, 1));
        vmax0 = fmaxf(vmax0, __shfl_xor_sync(0xffffffffu, vmax0, 2));
        vmax1 = fmaxf(vmax1, __shfl_xor_sync(0xffffffffu, vmax1, 1));
        vmax1 = fmaxf(vmax1, __shfl_xor_sync(0xffffffffu, vmax1, 2));
        float mn0 = fmaxf(m0, vmax0), mn1 = fmaxf(m1, vmax1);
        float sc0 = expf(m0 - mn0), sc1 = expf(m1 - mn1);
        float rs0 = 0.f, rs1 = 0.f;
        #pragma unroll
        for (int ni = 0; ni < 8; ni++) {
            s[ni][0] = expf(s[ni][0] - mn0); rs0 += s[ni][0];
            s[ni][1] = expf(s[ni][1] - mn0); rs0 += s[ni][1];
            s[ni][2] = expf(s[ni][2] - mn1); rs1 += s[ni][2];
            s[ni][3] = expf(s[ni][3] - mn1); rs1 += s[ni][3];
        }
        rs0 += __shfl_xor_sync(0xffffffffu, rs0, 1);
        rs0 += __shfl_xor_sync(0xffffffffu, rs0, 2);
        rs1 += __shfl_xor_sync(0xffffffffu, rs1, 1);
        rs1 += __shfl_xor_sync(0xffffffffu, rs1, 2);
        l0 = l0 * sc0 + rs0; m0 = mn0;
        l1 = l1 * sc1 + rs1; m1 = mn1;
        #pragma unroll
        for (int ni = 0; ni < 8; ni++) {
            o[ni][0] *= sc0; o[ni][1] *= sc0;
            o[ni][2] *= sc1; o[ni][3] *= sc1;
        }

        #pragma unroll
        for (int kb2 = 0; kb2 < 8; kb2++) {
            int k8 = kb2 * 8;
            uint32_t af[4];
            af[0] = __float_as_uint(s[kb2][0]);
            af[1] = __float_as_uint(s[kb2][2]);
            af[2] = __float_as_uint(s[kb2][1]);
            af[3] = __float_as_uint(s[kb2][3]);
            #pragma unroll
            for (int ni = 0; ni < 8; ni++) {
                uint32_t b0 = __float_as_uint(Vt[(ni * 8 + gid) * 68 + k8 + tg    ]);
                uint32_t b1 = __float_as_uint(Vt[(ni * 8 + gid) * 68 + k8 + tg + 4]);
                asm volatile(
                    "mma.sync.aligned.m16n8k8.row.col.f32.tf32.tf32.f32 "
                    "{%0,%1,%2,%3}, {%4,%5,%6,%7}, {%8,%9}, {%0,%1,%2,%3};\n"
                    : "+f"(o[ni][0]), "+f"(o[ni][1]), "+f"(o[ni][2]), "+f"(o[ni][3])
                    : "r"(af[0]), "r"(af[1]), "r"(af[2]), "r"(af[3]),
                      "r"(b0), "r"(b1));
            }
        }
    }

    float inv0 = 1.f / l0, inv1 = 1.f / l1;
    int t0 = qbase + wm + gid;
    int t1 = t0 + 8;
    #pragma unroll
    for (int ni = 0; ni < 8; ni++) {
        int c = h * HD + ni * 8 + tg * 2;
        if (t0 < Tn) {
            float2 vv;
            vv.x = tf32r(o[ni][0] * inv0);
            vv.y = tf32r(o[ni][1] * inv0);
            *(float2*)&out[(size_t)(b * Tn + t0) * Cn + c] = vv;
        }
        if (t1 < Tn) {
            float2 vv;
            vv.x = tf32r(o[ni][2] * inv1);
            vv.y = tf32r(o[ni][3] * inv1);
            *(float2*)&out[(size_t)(b * Tn + t1) * Cn + c] = vv;
        }
    }
}

__global__ void attn_tail(const float* __restrict__ qkv, float* __restrict__ out)
{
    int h = blockIdx.x, b = blockIdx.y;
    int tid = threadIdx.x;
    __shared__ float q[64];
    __shared__ float p[Tn];
    __shared__ float red[256];
    const float* qp = qkv + (size_t)(b * Tn + Tn - 1) * (3 * Cn) + h * HD;
    if (tid < 64) q[tid] = qp[tid] * 0.125f;
    __syncthreads();
    float lmax = -1e30f;
    for (int j = tid; j < Tn; j += 256) {
        const float* kp = qkv + (size_t)(b * Tn + j) * (3 * Cn) + Cn + h * HD;
        float s = 0.f;
        #pragma unroll 8
        for (int d = 0; d < 64; d++) s += q[d] * kp[d];
        p[j] = s;
        lmax = fmaxf(lmax, s);
    }
    float rmax = blockReduceMax256(lmax, red);
    float lsum = 0.f;
    for (int j = tid; j < Tn; j += 256) {
        float e = expf(p[j] - rmax);
        p[j] = e; lsum += e;
    }
    float rsum = blockReduceSum256(lsum, red);
    int d = tid & 63, part = tid >> 6;
    float acc = 0.f;
    for (int j = part; j < Tn; j += 4)
        acc += p[j] * qkv[(size_t)(b * Tn + j) * (3 * Cn) + 2 * Cn + h * HD + d];
    red[tid] = acc;
    __syncthreads();
    if (part == 0) {
        float v = red[d] + red[d + 64] + red[d + 128] + red[d + 192];
        out[(size_t)(b * Tn + Tn - 1) * Cn + h * HD + d] = tf32r(v / rsum);
    }
}

// ---------------- adapter (+ fused plain-LN producing z) ----------------
__global__ void adapter_kernel(const float* __restrict__ xffn, const float* __restrict__ x1,
                               const float* __restrict__ Wa1, const float* __restrict__ ba1,
                               const float* __restrict__ Wa2, const float* __restrict__ ba2,
                               float* __restrict__ x2, float* __restrict__ z)
{
    int r = blockIdx.x;
    int tid = threadIdx.x;
    __shared__ float xr[Cn];
    __shared__ float x2s[Cn];
    __shared__ float tg[ADn];
    __shared__ float red[256];
    const float* xp = xffn + (size_t)r * Cn;
    for (int c = tid; c < Cn; c += 256) xr[c] = xp[c];
    __syncthreads();
    int w = tid >> 5, lane = tid & 31;
    for (int a = w; a < ADn; a += 8) {
        float p = 0.f;
        const float* ww = Wa1 + (size_t)a * Cn;
        for (int c = lane; c < Cn; c += 32) p += xr[c] * ww[c];
        #pragma unroll
        for (int off = 16; off > 0; off >>= 1) p += __shfl_xor_sync(0xffffffffu, p, off);
        if (lane == 0) tg[a] = quick_gelu(p + ba1[a]);
    }
    __syncthreads();
    const float* x1p = x1 + (size_t)r * Cn;
    float s0 = 0.f;
    for (int c = tid; c < Cn; c += 256) {
        float acc = ba2[c];
        const float* w2 = Wa2 + (size_t)c * ADn;
        #pragma unroll
        for (int a = 0; a < ADn; a++) acc += tg[a] * w2[a];
        float v = x1p[c] + xr[c] + 0.5f * acc;
        x2s[c] = v;
        x2[(size_t)r * Cn + c] = v;
        s0 += v;
    }
    int t = r % Tn;
    if (t == 0) return;
    float mean = blockReduceSum256(s0, red) * (1.f / Cn);
    float s1 = 0.f;
    for (int c = tid; c < Cn; c += 256) { float d = x2s[c] - mean; s1 += d * d; }
    float var = blockReduceSum256(s1, red) * (1.f / Cn);
    float inv = rsqrtf(var + EPSf);
    int zi = (r / Tn) * 512 + (t - 1);
    float* zp = z + (size_t)zi * Cn;
    for (int c = tid; c < Cn; c += 256)
        zp[c] = tf32r((x2s[c] - mean) * inv);
}

// ---------------- view weight prep ----------------
__global__ void wprep_kernel(const float* __restrict__ aqw, const float* __restrict__ aqb,
                             const float* __restrict__ n3g, const float* __restrict__ n3b)
{
    int vj = blockIdx.x;
    int v = vj / 36;
    int tid = threadIdx.x;
    __shared__ float red[256];
    const float* w = aqw + (size_t)vj * Cn;
    const float* gg = n3g + (size_t)v * Cn;
    const float* bb = n3b + (size_t)v * Cn;
    float s = 0.f;
    for (int c = tid; c < Cn; c += 256) {
        float wv = w[c];
        g_weff[(size_t)vj * Cn + c] = tf32r(wv * gg[c]);
        s += wv * bb[c];
    }
    s = blockReduceSum256(s, red);
    if (tid == 0) g_beff[vj] = aqb[vj] + s;
}

// ---------------- cluster (3d) pooling chain ----------------
__global__ void pool_init(int R)
{
    int i = blockIdx.x * blockDim.x + threadIdx.x;
    if (i <= R) g_hist[i] = 0;
    if (i < Cn) { g_colsum[i] = 0.0; g_colsq[i] = 0.0; }
}
__global__ void hist_count(const int* __restrict__ idx)
{
    int i = blockIdx.x * blockDim.x + threadIdx.x;
    if (i < BG) atomicAdd(&g_hist[idx[i]], 1);
}
__global__ void scan_kernel(int R)
{
    __shared__ int part[1024];
    int tid = threadIdx.x;
    int chunk = (R + 1023) / 1024;
    int t0 = tid * chunk;
    int s = 0;
    for (int j = 0; j < chunk; j++)
        if (t0 + j < R) s += g_hist[t0 + j];
    part[tid] = s;
    __syncthreads();
    for (int off = 1; off < 1024; off <<= 1) {
        int v = (tid >= off) ? part[tid - off] : 0;
        __syncthreads();
        part[tid] += v;
        __syncthreads();
    }
    int run = (tid > 0) ? part[tid - 1] : 0;
    for (int j = 0; j < chunk; j++) {
        if (t0 + j < R) {
            int c = g_hist[t0 + j];
            g_off[t0 + j] = run;
            g_cur[t0 + j] = run;
            run += c;
        }
    }
    if (tid == 1023) g_off[R] = part[1023];
}
__global__ void seg_place(const int* __restrict__ idx)
{
    int i = blockIdx.x * blockDim.x + threadIdx.x;
    if (i >= BG) return;
    int p = atomicAdd(&g_cur[idx[i]], 1);
    g_ord[p] = i;
}
__global__ void seg_reduce(const float* __restrict__ src)
{
    int r = blockIdx.x;
    int tid = threadIdx.x;
    int s0 = g_off[r], s1 = g_off[r + 1];
    float mx0 = -1e30f, mx1 = -1e30f, mx2 = -1e30f;
    float sm0 = 0.f, sm1 = 0.f, sm2 = 0.f;
    for (int j = s0; j < s1; j++) {
        int i = g_ord[j];
        const float* p = src + (size_t)featRow(i) * Cn;
        float v0 = p[tid], v1 = p[tid + 256], v2 = p[tid + 512];
        mx0 = fmaxf(mx0, v0); sm0 += v0;
        mx1 = fmaxf(mx1, v1); sm1 += v1;
        mx2 = fmaxf(mx2, v2); sm2 += v2;
    }
    int cnt = s1 - s0;
    float inv = 1.f / (float)(cnt > 0 ? cnt : 1);
    float* op = g_scomb + (size_t)r * Cn;
    op[tid]       = (cnt > 0 ? mx0 : 0.f) + sm0 * inv;
    op[tid + 256] = (cnt > 0 ? mx1 : 0.f) + sm1 * inv;
    op[tid + 512] = (cnt > 0 ? mx2 : 0.f) + sm2 * inv;
}
__global__ void colstats(int R)
{
    int col = blockIdx.x * blockDim.x + threadIdx.x;
    if (col >= Cn) return;
    int chunk = (R + gridDim.y - 1) / gridDim.y;
    int r0 = blockIdx.y * chunk;
    int r1 = min(r0 + chunk, R);
    float sum = 0.f, sq = 0.f;
    for (int r = r0; r < r1; r++) {
        float v = g_scomb[(size_t)r * Cn + col];
        sum += v; sq += v * v;
    }
    atomicAdd(&g_colsum[col], (double)sum);
    atomicAdd(&g_colsq[col], (double)sq);
}
__global__ void colfinal(int R)
{
    int col = blockIdx.x * blockDim.x + threadIdx.x;
    if (col >= Cn) return;
    double mean = g_colsum[col] / R;
    double var = g_colsq[col] / R - mean * mean;
    if (var < 0.0) var = 0.0;
    g_mean[col] = (float)mean;
    g_rstd[col] = rsqrtf((float)var + EPSf);
}
__global__ void bn_apply(const float* __restrict__ gam, const float* __restrict__ bet,
                         float* __restrict__ out, int R)
{
    int i = blockIdx.x * blockDim.x + threadIdx.x;
    if (i >= R * Cn) return;
    int col = i % Cn;
    float v = (g_scomb[i] - g_mean[col]) * g_rstd[col] * gam[col] + bet[col];
    out[i] = gelu_exact(v);
}

// ---------------- batched (x6 views) pooling chain ----------------
__global__ void pool_init6()
{
    int v = blockIdx.y;
    int i = blockIdx.x * blockDim.x + threadIdx.x;
    if (i <= D1n) g_hist6[v * (D1n + 1) + i] = 0;
    if (i < Cn) { g_colsum6[v * Cn + i] = 0.0; g_colsq6[v * Cn + i] = 0.0; }
}
__global__ void hist_count6(const int* __restrict__ fgi)
{
    int v = blockIdx.y;
    int i = blockIdx.x * blockDim.x + threadIdx.x;
    if (i < BG) atomicAdd(&g_hist6[v * (D1n + 1) + fgi[(size_t)v * BG + i]], 1);
}
__global__ void scan6()
{
    int v = blockIdx.x;
    int* hist = g_hist6 + v * (D1n + 1);
    int* off  = g_off6  + v * (D1n + 1);
    int* cur  = g_cur6  + v * (D1n + 1);
    __shared__ int part[1024];
    int tid = threadIdx.x;
    const int R = D1n;
    int chunk = (R + 1023) / 1024;
    int t0 = tid * chunk;
    int s = 0;
    for (int j = 0; j < chunk; j++)
        if (t0 + j < R) s += hist[t0 + j];
    part[tid] = s;
    __syncthreads();
    for (int off2 = 1; off2 < 1024; off2 <<= 1) {
        int vv = (tid >= off2) ? part[tid - off2] : 0;
        __syncthreads();
        part[tid] += vv;
        __syncthreads();
    }
    int run = (tid > 0) ? part[tid - 1] : 0;
    for (int j = 0; j < chunk; j++) {
        if (t0 + j < R) {
            int c = hist[t0 + j];
            off[t0 + j] = run;
            cur[t0 + j] = run;
            run += c;
        }
    }
    if (tid == 1023) off[R] = part[1023];
}
__global__ void seg_place6(const int* __restrict__ fgi)
{
    int v = blockIdx.y;
    int i = blockIdx.x * blockDim.x + threadIdx.x;
    if (i >= BG) return;
    int p = atomicAdd(&g_cur6[v * (D1n + 1) + fgi[(size_t)v * BG + i]], 1);
    g_ord6[(size_t)v * BG + p] = i;
}
__global__ void view_attn6(const float* __restrict__ qkv1, const unsigned char* __restrict__ mask)
{
    int blk = blockIdx.x, h = blockIdx.y, v = blockIdx.z;
    int t = threadIdx.x;
    __shared__ float kk[N1n][2];
    __shared__ float vv[N1n][2];
    int row = blk * N1n + t;
    const float* base = qkv1 + (size_t)row * NQ1 + v * 36;
    float q0 = base[h * 2]     * 0.28867513459481287f;
    float q1 = base[h * 2 + 1] * 0.28867513459481287f;
    kk[t][0] = base[12 + h * 2]; kk[t][1] = base[13 + h * 2];
    vv[t][0] = base[24 + h * 2]; vv[t][1] = base[25 + h * 2];
    __syncthreads();
    const unsigned char* mrow = mask + (size_t)v * NB1 * N1n * N1n + ((size_t)blk * N1n + t) * N1n;
    float mmax = -1e30f;
    #pragma unroll 4
    for (int j = 0; j < N1n; j++) {
        float s = q0 * kk[j][0] + q1 * kk[j][1] + (mrow[j] ? -100000.f : 0.f);
        mmax = fmaxf(mmax, s);
    }
    float l = 0.f, a0 = 0.f, a1 = 0.f;
    #pragma unroll 4
    for (int j = 0; j < N1n; j++) {
        float s = q0 * kk[j][0] + q1 * kk[j][1] + (mrow[j] ? -100000.f : 0.f);
        float p = expf(s - mmax);
        l += p; a0 += p * vv[j][0]; a1 += p * vv[j][1];
    }
    float* o1 = g_o16 + (size_t)v * BG * MIDn;
    o1[(size_t)row * MIDn + h * 2]     = a0 / l;
    o1[(size_t)row * MIDn + h * 2 + 1] = a1 / l;
}
__global__ void seg_reduce_view6(const float* __restrict__ apw, const float* __restrict__ apb,
                                 const float* __restrict__ x2)
{
    int r = blockIdx.x, v = blockIdx.y;
    int tid = threadIdx.x;
    const int* off = g_off6 + v * (D1n + 1);
    const int* ord = g_ord6 + (size_t)v * BG;
    const float* o1 = g_o16 + (size_t)v * BG * MIDn;
    const float* pw = apw + (size_t)v * Cn * MIDn;
    const float* pb = apb + (size_t)v * Cn;
    int s0 = off[r], s1 = off[r + 1];
    float wr[3][MIDn], pbv[3];
    #pragma unroll
    for (int ch = 0; ch < 3; ch++) {
        int c = tid + ch * 256;
        pbv[ch] = pb[c];
        #pragma unroll
        for (int k = 0; k < MIDn; k++) wr[ch][k] = __ldg(&pw[(size_t)c * MIDn + k]);
    }
    float mx[3] = {-1e30f, -1e30f, -1e30f};
    float sm[3] = {0.f, 0.f, 0.f};
    for (int j = s0; j < s1; j++) {
        int i = ord[j];
        const float4* ob = (const float4*)&o1[(size_t)i * MIDn];
        float4 o0 = __ldg(ob), o1v = __ldg(ob + 1), o2 = __ldg(ob + 2);
        float os[MIDn] = {o0.x, o0.y, o0.z, o0.w, o1v.x, o1v.y, o1v.z, o1v.w,
                          o2.x, o2.y, o2.z, o2.w};
        const float* xp = x2 + (size_t)featRow(i) * Cn;
        #pragma unroll
        for (int ch = 0; ch < 3; ch++) {
            float vv = pbv[ch] + xp[tid + ch * 256];
            #pragma unroll
            for (int k = 0; k < MIDn; k++) vv += os[k] * wr[ch][k];
            mx[ch] = fmaxf(mx[ch], vv);
            sm[ch] += vv;
        }
    }
    int cnt = s1 - s0;
    float inv = 1.f / (float)(cnt > 0 ? cnt : 1);
    float* op = g_scomb6 + ((size_t)v * D1n + r) * Cn;
    #pragma unroll
    for (int ch = 0; ch < 3; ch++)
        op[tid + ch * 256] = (cnt > 0 ? mx[ch] : 0.f) + sm[ch] * inv;
}
__global__ void colstats6()
{
    int col = blockIdx.x * blockDim.x + threadIdx.x;
    int v = blockIdx.z;
    if (col >= Cn) return;
    const int R = D1n;
    int chunk = (R + gridDim.y - 1) / gridDim.y;
    int r0 = blockIdx.y * chunk;
    int r1 = min(r0 + chunk, R);
    float sum = 0.f, sq = 0.f;
    const float* sc = g_scomb6 + (size_t)v * D1n * Cn;
    for (int r = r0; r < r1; r++) {
        float vv = sc[(size_t)r * Cn + col];
        sum += vv; sq += vv * vv;
    }
    atomicAdd(&g_colsum6[v * Cn + col], (double)sum);
    atomicAdd(&g_colsq6[v * Cn + col], (double)sq);
}
__global__ void colfinal6()
{
    int col = blockIdx.x * blockDim.x + threadIdx.x;
    int v = blockIdx.y;
    if (col >= Cn) return;
    double mean = g_colsum6[v * Cn + col] / D1n;
    double var = g_colsq6[v * Cn + col] / D1n - mean * mean;
    if (var < 0.0) var = 0.0;
    g_mean6[v * Cn + col] = (float)mean;
    g_rstd6[v * Cn + col] = rsqrtf((float)var + EPSf);
}
__global__ void bn_apply6(const float* __restrict__ bn1dg, const float* __restrict__ bn1db,
                          float* __restrict__ bview)
{
    int v = blockIdx.y;
    int i = blockIdx.x * blockDim.x + threadIdx.x;
    if (i >= D1n * Cn) return;
    int col = i % Cn;
    float vv = (g_scomb6[(size_t)v * D1n * Cn + i] - g_mean6[v * Cn + col]) * g_rstd6[v * Cn + col]
               * bn1dg[v * Cn + col] + bn1db[v * Cn + col];
    bview[(size_t)v * D1n * Cn + i] = gelu_exact(vv);
}

// ---------------- final fusion ----------------
__global__ void final_kernel(const float* __restrict__ x2, const float* __restrict__ g3,
                             const float* __restrict__ bview, const int* __restrict__ cluster,
                             const int* __restrict__ fgi, float* __restrict__ out)
{
    int i = blockIdx.x;
    int tid = threadIdx.x;
    size_t xrow = (size_t)featRow(i);
    __shared__ float x3[Cn];
    __shared__ float pv[NV][Cn];
    __shared__ float red[256];
    __shared__ float sims[NV];
    int cl = cluster[i];
    const float* x3p = g3 + (size_t)cl * Cn;
    for (int c = tid; c < Cn; c += 256) x3[c] = x3p[c];
    for (int v = 0; v < NV; v++) {
        int id = fgi[(size_t)v * BG + i];
        const float* pp = bview + ((size_t)v * D1n + id) * Cn;
        for (int c = tid; c < Cn; c += 256) pv[v][c] = pp[c];
    }
    __syncthreads();
    float p = 0.f;
    for (int c = tid; c < Cn; c += 256) p += x3[c] * x3[c];
    float nx3 = fmaxf(sqrtf(blockReduceSum256(p, red)), 1e-8f);
    for (int v = 0; v < NV; v++) {
        float d = 0.f, n = 0.f;
        for (int c = tid; c < Cn; c += 256) {
            float a = pv[v][c];
            d += a * x3[c]; n += a * a;
        }
        d = blockReduceSum256(d, red);
        n = blockReduceSum256(n, red);
        if (tid == 0) {
            float np = fmaxf(sqrtf(n), 1e-8f);
            float cs = d / (np * nx3);
            sims[v] = (cs + 1.f) * 0.5f;
        }
        __syncthreads();
    }
    float ssum = 0.f;
    #pragma unroll
    for (int v = 0; v < NV; v++) ssum += sims[v];
    float inv = 1.f / ssum;
    const float* x2p = x2 + xrow * Cn;
    float* op = out + xrow * Cn;
    for (int c = tid; c < Cn; c += 256) {
        float sup = 0.f;
        #pragma unroll
        for (int v = 0; v < NV; v++) sup += pv[v][c] * sims[v];
        op[c] = x2p[c] + 0.3f * sup * inv;
    }
}

__global__ void cls_copy(const float* __restrict__ x2, float* __restrict__ out)
{
    size_t row = (size_t)blockIdx.x * Tn;
    for (int c = threadIdx.x; c < Cn; c += blockDim.x)
        out[row * Cn + c] = x2[row * Cn + c];
}

// ---------------- host launch ----------------
extern "C" void kernel_launch(void* const* d_in, const int* in_sizes, int n_in,
                              void* d_out, int out_size)
{
    const float* x    = (const float*)d_in[0];
    const float* ln1g = (const float*)d_in[1];
    const float* ln1b = (const float*)d_in[2];
    const float* ln2g = (const float*)d_in[3];
    const float* ln2b = (const float*)d_in[4];
    const float* Wqkv = (const float*)d_in[5];
    const float* bqkv = (const float*)d_in[6];
    const float* Wo   = (const float*)d_in[7];
    const float* bo   = (const float*)d_in[8];
    const float* Wfc  = (const float*)d_in[9];
    const float* bfc  = (const float*)d_in[10];
    const float* Wproj= (const float*)d_in[11];
    const float* bproj= (const float*)d_in[12];
    const float* Wa1  = (const float*)d_in[13];
    const float* ba1  = (const float*)d_in[14];
    const float* Wa2  = (const float*)d_in[15];
    const float* ba2  = (const float*)d_in[16];
    const float* bn3dg= (const float*)d_in[17];
    const float* bn3db= (const float*)d_in[18];
    const float* bn1dg= (const float*)d_in[19];
    const float* bn1db= (const float*)d_in[20];
    const float* n3g  = (const float*)d_in[21];
    const float* n3b  = (const float*)d_in[22];
    const float* aqw  = (const float*)d_in[23];
    const float* aqb  = (const float*)d_in[24];
    const float* apw  = (const float*)d_in[25];
    const float* apb  = (const float*)d_in[26];
    const int*   cluster = (const int*)d_in[27];
    const int*   fgi  = (const int*)d_in[28];
    const unsigned char* mask = (const unsigned char*)d_in[29];
    float* out = (float*)d_out;

    float *y, *qkv, *att, *x1, *hfc, *xffn, *x2, *g3, *bview, *z, *qkv1, *weff, *beff, *wrnd;
    cudaGetSymbolAddress((void**)&y,     g_y);
    cudaGetSymbolAddress((void**)&qkv,   g_qkv);
    cudaGetSymbolAddress((void**)&att,   g_att);
    cudaGetSymbolAddress((void**)&x1,    g_x1);
    cudaGetSymbolAddress((void**)&hfc,   g_hfc);
    cudaGetSymbolAddress((void**)&xffn,  g_xffn);
    cudaGetSymbolAddress((void**)&x2,    g_x2);
    cudaGetSymbolAddress((void**)&g3,    g_g3);
    cudaGetSymbolAddress((void**)&bview, g_bview);
    cudaGetSymbolAddress((void**)&z,     g_z);
    cudaGetSymbolAddress((void**)&qkv1,  g_qkv1);
    cudaGetSymbolAddress((void**)&weff,  g_weff);
    cudaGetSymbolAddress((void**)&beff,  g_beff);
    cudaGetSymbolAddress((void**)&wrnd,  g_wrnd);

    cudaFuncSetAttribute(attn_tc, cudaFuncAttributeMaxDynamicSharedMemorySize, ATTN_SMEM);
    cudaFuncSetAttribute(gemm_tf32<0>, cudaFuncAttributeMaxDynamicSharedMemorySize, GEMM_SMEM);
    cudaFuncSetAttribute(gemm_wide<0>, cudaFuncAttributeMaxDynamicSharedMemorySize, GEMMW_SMEM);
    cudaFuncSetAttribute(gemm_wide<1>, cudaFuncAttributeMaxDynamicSharedMemorySize, GEMMW_SMEM);
    cudaFuncSetAttribute(gemm_wide<2>, cudaFuncAttributeMaxDynamicSharedMemorySize, GEMMW_SMEM);

    const int GMB = (MROWS + 127) / 128;  // 129

    // 1) LN1 -> y (tf32-rounded)
    ln_kernel<<<MROWS, 256>>>(x, ln1g, ln1b, y, 0);
    // 2) QKV GEMM (wide tile)
    round_w<<<(3 * Cn * Cn / 4 + 255) / 256, 256>>>(Wqkv, wrnd, 3 * Cn * Cn / 4);
    gemm_wide<0><<<dim3(GMB, (3 * Cn) / 256), 256, GEMMW_SMEM>>>(y, wrnd, bqkv, nullptr, qkv, MROWS, 3 * Cn, Cn);
    // 3) attention + tail
    attn_tc<<<dim3(4, Hn, Bn), 256, ATTN_SMEM>>>(qkv, att);
    attn_tail<<<dim3(Hn, Bn), 256>>>(qkv, att);
    // 4) output proj + residual (wide tile)
    round_w<<<(Cn * Cn / 4 + 255) / 256, 256>>>(Wo, wrnd, Cn * Cn / 4);
    gemm_wide<2><<<dim3(GMB, Cn / 256), 256, GEMMW_SMEM>>>(att, wrnd, bo, x, x1, MROWS, Cn, Cn);
    // 5) LN2 -> y
    ln_kernel<<<MROWS, 256>>>(x1, ln2g, ln2b, y, 0);
    // 6) FC + quick_gelu (wide tile)
    round_w<<<(FFn * Cn / 4 + 255) / 256, 256>>>(Wfc, wrnd, FFn * Cn / 4);
    gemm_wide<1><<<dim3(GMB, FFn / 256), 256, GEMMW_SMEM>>>(y, wrnd, bfc, nullptr, hfc, MROWS, FFn, Cn);
    // 7) proj (wide tile, K=3072)
    round_w<<<(Cn * FFn / 4 + 255) / 256, 256>>>(Wproj, wrnd, Cn * FFn / 4);
    gemm_wide<0><<<dim3(GMB, Cn / 256), 256, GEMMW_SMEM>>>(hfc, wrnd, bproj, nullptr, xffn, MROWS, Cn, FFn);
    // 8) adapter + residuals -> x2, fused plain LN -> z
    adapter_kernel<<<MROWS, 256>>>(xffn, x1, Wa1, ba1, Wa2, ba2, x2, z);

    // 9) 3d segment pool + BN over clusters
    {
        pool_init<<<(NCL + 1 + 255) / 256, 256>>>(NCL);
        hist_count<<<(BG + 255) / 256, 256>>>(cluster);
        scan_kernel<<<1, 1024>>>(NCL);
        seg_place<<<(BG + 255) / 256, 256>>>(cluster);
        seg_reduce<<<NCL, 256>>>(x2);
        colstats<<<dim3(3, 16), 256>>>(NCL);
        colfinal<<<3, 256>>>(NCL);
        bn_apply<<<(NCL * Cn + 255) / 256, 256>>>(bn3dg, bn3db, g3, NCL);
    }

    // 10) view branches (batched; z produced by adapter)
    wprep_kernel<<<NQ1, 256>>>(aqw, aqb, n3g, n3b);
    gemm_tf32<0><<<dim3(BG / 128, (NQ1 + 127) / 128), 256, GEMM_SMEM>>>(z, weff, beff, nullptr, qkv1,
                                                                        BG, NQ1, Cn);
    view_attn6<<<dim3(NB1, H1n, NV), N1n>>>(qkv1, mask);
    pool_init6<<<dim3((D1n + 1 + 255) / 256, NV), 256>>>();
    hist_count6<<<dim3((BG + 255) / 256, NV), 256>>>(fgi);
    scan6<<<NV, 1024>>>();
    seg_place6<<<dim3((BG + 255) / 256, NV), 256>>>(fgi);
    seg_reduce_view6<<<dim3(D1n, NV), 256>>>(apw, apb, x2);
    colstats6<<<dim3(3, 16, NV), 256>>>();
    colfinal6<<<dim3(3, NV), 256>>>();
    bn_apply6<<<dim3((D1n * Cn + 255) / 256, NV), 256>>>(bn1dg, bn1db, bview);

    // 11) cossim fusion + output
    final_kernel<<<BG, 256>>>(x2, g3, bview, cluster, fgi, out);
    cls_copy<<<Bn, 256>>>(x2, out);
}

// round 12
// speedup vs baseline: 1.1705x; 1.1705x over previous
#include <cuda_runtime.h>
#include <cuda_bf16.h>
#include <math.h>
#include <stdint.h>

// ---------------- problem constants ----------------
#define Bn    32
#define Gn    512
#define Cn    768
#define Hn    12
#define HD    64
#define Tn    513              // G+1
#define MROWS (Bn*Tn)          // 16416
#define BG    16384
#define FFn   3072
#define ADn   16
#define MIDn  12
#define H1n   6
#define N1n   128
#define NB1   (BG/N1n)         // 128
#define NCL   2048
#define D1n   6272
#define NV    6
#define NQ1   (NV*3*MIDn)      // 216
#define EPSf  1e-5f

// ---------------- scratch (device globals; no allocation) ----------------
__device__ float  g_y   [MROWS*Cn];
__device__ float  g_qkv [MROWS*3*Cn];
__device__ float  g_att [MROWS*Cn];
__device__ float  g_x1  [MROWS*Cn];
__device__ float  g_hfc [MROWS*FFn];
__device__ float  g_xffn[MROWS*Cn];
__device__ float  g_x2  [MROWS*Cn];
__device__ float  g_g3   [NCL*Cn];
__device__ float  g_bview[NV*D1n*Cn];
__device__ float  g_z    [BG*Cn];          // nhat (un-affined LN of feat)
__device__ float  g_qkv1 [BG*NQ1];
__device__ float  g_weff [NQ1*Cn];
__device__ float  g_beff [NQ1];
// cluster (3d) pooling buffers
__device__ float  g_scomb [NCL*Cn];
__device__ double g_colsum[Cn];
__device__ double g_colsq [Cn];
__device__ float  g_mean[Cn];
__device__ float  g_rstd[Cn];
__device__ int    g_hist[NCL+1];
__device__ int    g_off [NCL+1];
__device__ int    g_cur [NCL+1];
__device__ int    g_ord [BG];
// batched view pooling buffers
__device__ int    g_hist6[NV*(D1n+1)];
__device__ int    g_off6 [NV*(D1n+1)];
__device__ int    g_cur6 [NV*(D1n+1)];
__device__ int    g_ord6 [NV*BG];
__device__ float  g_scomb6[(size_t)NV*D1n*Cn];
__device__ double g_colsum6[NV*Cn];
__device__ double g_colsq6 [NV*Cn];
__device__ float  g_mean6[NV*Cn];
__device__ float  g_rstd6[NV*Cn];
__device__ float  g_o16  [NV*BG*MIDn];

// ---------------- helpers ----------------
__device__ __forceinline__ float blockReduceSum256(float v, float* red) {
    int tid = threadIdx.x;
    red[tid] = v; __syncthreads();
    #pragma unroll
    for (int o = 128; o > 0; o >>= 1) {
        if (tid < o) red[tid] += red[tid + o];
        __syncthreads();
    }
    float r = red[0];
    __syncthreads();
    return r;
}
__device__ __forceinline__ float blockReduceMax256(float v, float* red) {
    int tid = threadIdx.x;
    red[tid] = v; __syncthreads();
    #pragma unroll
    for (int o = 128; o > 0; o >>= 1) {
        if (tid < o) red[tid] = fmaxf(red[tid], red[tid + o]);
        __syncthreads();
    }
    float r = red[0];
    __syncthreads();
    return r;
}
__device__ __forceinline__ float quick_gelu(float x) {
    return x / (1.f + expf(-1.702f * x));
}
__device__ __forceinline__ float gelu_exact(float x) {
    return 0.5f * x * (1.f + erff(x * 0.70710678118654752f));
}
__device__ __forceinline__ int featRow(int i) {
    return (i >> 9) * Tn + 1 + (i & 511);
}
__device__ __forceinline__ float tf32r(float f) {
    uint32_t u;
    asm volatile("cvt.rna.tf32.f32 %0, %1;" : "=r"(u) : "f"(f));
    return __uint_as_float(u);
}

// ---------------- LayerNorm (tf32-rounded out) ----------------
__global__ void ln_kernel(const float* __restrict__ in, const float* __restrict__ g,
                          const float* __restrict__ b, float* __restrict__ out, int featmode)
{
    int r = blockIdx.x;
    int row = featmode ? featRow(r) : r;
    const float* x = in + (size_t)row * Cn;
    __shared__ float xs[Cn];
    __shared__ float red[256];
    int tid = threadIdx.x;
    float s0 = 0.f;
    for (int c = tid; c < Cn; c += 256) { float v = x[c]; xs[c] = v; s0 += v; }
    float mean = blockReduceSum256(s0, red) * (1.f / Cn);
    float s1 = 0.f;
    for (int c = tid; c < Cn; c += 256) { float d = xs[c] - mean; s1 += d * d; }
    float var = blockReduceSum256(s1, red) * (1.f / Cn);
    float inv = rsqrtf(var + EPSf);
    float* op = out + (size_t)r * Cn;
    for (int c = tid; c < Cn; c += 256)
        op[c] = tf32r((xs[c] - mean) * inv * g[c] + b[c]);
}

// ---------------- mma.sync tf32 NT GEMM, 3-stage cp.async pipeline (proven R4/R6) ----------------
// Weights (B operand) fed raw fp32 bits -> HW truncation to tf32. Activations pre-rounded RNA.
#define GEMM_SMEM (3 * 2 * 128 * 20 * 4)   // 61440 bytes
template <int EPI>
__global__ void __launch_bounds__(256, 2) gemm_tf32(
    const float* __restrict__ A, const float* __restrict__ W,
    const float* __restrict__ bias, const float* __restrict__ res,
    float* __restrict__ C, int M, int N, int K)
{
    extern __shared__ float sm_[];
    int tid = threadIdx.x;
    int bm = blockIdx.x * 128, bn = blockIdx.y * 128;
    int lane = tid & 31, wid = tid >> 5;
    int wm = (wid & 1) * 64, wn = (wid >> 1) * 32;
    int gid = lane >> 2, tg = lane & 3;

    float acc[4][4][4];
    #pragma unroll
    for (int a = 0; a < 4; a++)
        #pragma unroll
        for (int b = 0; b < 4; b++)
            #pragma unroll
            for (int c = 0; c < 4; c++) acc[a][b][c] = 0.f;

    auto prefetch = [&](int kt, int s) {
        int k0 = kt * 16;
        float* As = sm_ + s * 2560;
        float* Bs = sm_ + 7680 + s * 2560;
        #pragma unroll
        for (int i = 0; i < 2; i++) {
            int r = (tid >> 2) + i * 64;
            int c = (tid & 3) * 4;
            int arow = bm + r;
            const float* asrc = A + (size_t)(arow < M ? arow : 0) * K + k0 + c;
            uint32_t adst = (uint32_t)__cvta_generic_to_shared(&As[r * 20 + c]);
            int asz = (arow < M) ? 16 : 0;
            asm volatile("cp.async.cg.shared.global [%0], [%1], 16, %2;\n"
                         :: "r"(adst), "l"(asrc), "r"(asz));
            int brow = bn + r;
            const float* bsrc = W + (size_t)(brow < N ? brow : 0) * K + k0 + c;
            uint32_t bdst = (uint32_t)__cvta_generic_to_shared(&Bs[r * 20 + c]);
            int bsz = (brow < N) ? 16 : 0;
            asm volatile("cp.async.cg.shared.global [%0], [%1], 16, %2;\n"
                         :: "r"(bdst), "l"(bsrc), "r"(bsz));
        }
    };

    int nt = K / 16;
    prefetch(0, 0);
    asm volatile("cp.async.commit_group;\n");
    if (nt > 1) prefetch(1, 1);
    asm volatile("cp.async.commit_group;\n");

    int buf = 0;
    for (int t = 0; t < nt; t++) {
        asm volatile("cp.async.wait_group 1;\n");
        __syncthreads();
        if (t + 2 < nt) prefetch(t + 2, (buf + 2) % 3);
        asm volatile("cp.async.commit_group;\n");
        const float* As = sm_ + buf * 2560;
        const float* Bs = sm_ + 7680 + buf * 2560;
        #pragma unroll
        for (int kk = 0; kk < 2; kk++) {
            int kb = kk * 8;
            uint32_t af[4][4], bf[4][2];
            #pragma unroll
            for (int mi = 0; mi < 4; mi++) {
                int r = wm + mi * 16 + gid;
                af[mi][0] = __float_as_uint(As[(r    ) * 20 + kb + tg    ]);
                af[mi][1] = __float_as_uint(As[(r + 8) * 20 + kb + tg    ]);
                af[mi][2] = __float_as_uint(As[(r    ) * 20 + kb + tg + 4]);
                af[mi][3] = __float_as_uint(As[(r + 8) * 20 + kb + tg + 4]);
            }
            #pragma unroll
            for (int ni = 0; ni < 4; ni++) {
                int n0 = wn + ni * 8 + gid;
                bf[ni][0] = __float_as_uint(Bs[n0 * 20 + kb + tg    ]);
                bf[ni][1] = __float_as_uint(Bs[n0 * 20 + kb + tg + 4]);
            }
            #pragma unroll
            for (int mi = 0; mi < 4; mi++)
                #pragma unroll
                for (int ni = 0; ni < 4; ni++)
                    asm volatile(
                        "mma.sync.aligned.m16n8k8.row.col.f32.tf32.tf32.f32 "
                        "{%0,%1,%2,%3}, {%4,%5,%6,%7}, {%8,%9}, {%0,%1,%2,%3};\n"
                        : "+f"(acc[mi][ni][0]), "+f"(acc[mi][ni][1]),
                          "+f"(acc[mi][ni][2]), "+f"(acc[mi][ni][3])
                        : "r"(af[mi][0]), "r"(af[mi][1]), "r"(af[mi][2]), "r"(af[mi][3]),
                          "r"(bf[ni][0]), "r"(bf[ni][1]));
        }
        __syncthreads();
        buf = (buf + 1) % 3;
    }

    #pragma unroll
    for (int mi = 0; mi < 4; mi++) {
        #pragma unroll
        for (int ni = 0; ni < 4; ni++) {
            int m0 = bm + wm + mi * 16 + gid;
            int n0 = bn + wn + ni * 8 + tg * 2;
            if (n0 >= N) continue;
            float b0 = bias[n0], b1 = bias[n0 + 1];
            #pragma unroll
            for (int hh = 0; hh < 2; hh++) {
                int m = m0 + hh * 8;
                if (m >= M) continue;
                float v0 = acc[mi][ni][hh * 2 + 0] + b0;
                float v1 = acc[mi][ni][hh * 2 + 1] + b1;
                if (EPI == 1) { v0 = tf32r(quick_gelu(v0)); v1 = tf32r(quick_gelu(v1)); }
                if (EPI == 2) {
                    float2 rr = *(const float2*)&res[(size_t)m * N + n0];
                    v0 += rr.x; v1 += rr.y;
                }
                float2 vv; vv.x = v0; vv.y = v1;
                *(float2*)&C[(size_t)m * N + n0] = vv;
            }
        }
    }
}

// ---------------- tensor-core flash attention (proven R6 version) ----------------
#define ATTN_SMEM ((128 + 64 + 64) * 68 * 4)
__global__ void __launch_bounds__(256) attn_tc(const float* __restrict__ qkv,
                                               float* __restrict__ out)
{
    extern __shared__ float sm[];
    float* Qs = sm;
    float* Ks = sm + 128 * 68;
    float* Vt = sm + 192 * 68;

    int qb = blockIdx.x, h = blockIdx.y, b = blockIdx.z;
    int tid = threadIdx.x, lane = tid & 31, wid = tid >> 5;
    int gid = lane >> 2, tg = lane & 3;
    int wm = wid * 16;
    int qbase = qb * 128;

    {
        int r = tid >> 1, c0 = (tid & 1) * 32;
        int t = qbase + r;
        bool valid = (t < Tn);
        const float* qp = qkv + (size_t)(b * Tn + (valid ? t : 0)) * (3 * Cn) + h * HD + c0;
        #pragma unroll
        for (int i = 0; i < 8; i++) {
            float4 v = *(const float4*)(qp + i * 4);
            float4 w;
            w.x = valid ? tf32r(v.x * 0.125f) : 0.f;
            w.y = valid ? tf32r(v.y * 0.125f) : 0.f;
            w.z = valid ? tf32r(v.z * 0.125f) : 0.f;
            w.w = valid ? tf32r(v.w * 0.125f) : 0.f;
            *(float4*)&Qs[r * 68 + c0 + i * 4] = w;
        }
    }

    float m0 = -1e30f, m1 = -1e30f, l0 = 0.f, l1 = 0.f;
    float o[8][4];
    #pragma unroll
    for (int ni = 0; ni < 8; ni++)
        #pragma unroll
        for (int j = 0; j < 4; j++) o[ni][j] = 0.f;

    for (int kb = 0; kb < 9; kb++) {
        int kbase = kb * 64;
        __syncthreads();
        {
            int r = tid >> 2, c0 = (tid & 3) * 16;
            int t = kbase + r;
            bool valid = (t < Tn);
            const float* kp = qkv + (size_t)(b * Tn + (valid ? t : 0)) * (3 * Cn) + Cn + h * HD + c0;
            const float* vp = kp + Cn;
            int low = r & 7;
            int pr = (r & ~7) | (((low & 3) << 1) | (low >> 2));
            #pragma unroll
            for (int i = 0; i < 16; i += 4) {
                float4 kv4 = *(const float4*)(kp + i);
                float4 w;
                w.x = valid ? tf32r(kv4.x) : 0.f;
                w.y = valid ? tf32r(kv4.y) : 0.f;
                w.z = valid ? tf32r(kv4.z) : 0.f;
                w.w = valid ? tf32r(kv4.w) : 0.f;
                *(float4*)&Ks[pr * 68 + c0 + i] = w;
            }
            #pragma unroll
            for (int i = 0; i < 16; i++)
                Vt[(c0 + i) * 68 + r] = valid ? tf32r(vp[i]) : 0.f;
        }
        __syncthreads();

        float s[8][4];
        #pragma unroll
        for (int ni = 0; ni < 8; ni++)
            #pragma unroll
            for (int j = 0; j < 4; j++) s[ni][j] = 0.f;
        #pragma unroll
        for (int ks = 0; ks < 8; ks++) {
            int k8 = ks * 8;
            uint32_t af[4];
            int r = wm + gid;
            af[0] = __float_as_uint(Qs[(r    ) * 68 + k8 + tg    ]);
            af[1] = __float_as_uint(Qs[(r + 8) * 68 + k8 + tg    ]);
            af[2] = __float_as_uint(Qs[(r    ) * 68 + k8 + tg + 4]);
            af[3] = __float_as_uint(Qs[(r + 8) * 68 + k8 + tg + 4]);
            #pragma unroll
            for (int ni = 0; ni < 8; ni++) {
                uint32_t b0 = __float_as_uint(Ks[(ni * 8 + gid) * 68 + k8 + tg    ]);
                uint32_t b1 = __float_as_uint(Ks[(ni * 8 + gid) * 68 + k8 + tg + 4]);
                asm volatile(
                    "mma.sync.aligned.m16n8k8.row.col.f32.tf32.tf32.f32 "
                    "{%0,%1,%2,%3}, {%4,%5,%6,%7}, {%8,%9}, {%0,%1,%2,%3};\n"
                    : "+f"(s[ni][0]), "+f"(s[ni][1]), "+f"(s[ni][2]), "+f"(s[ni][3])
                    : "r"(af[0]), "r"(af[1]), "r"(af[2]), "r"(af[3]),
                      "r"(b0), "r"(b1));
            }
        }

        float vmax0 = -1e30f, vmax1 = -1e30f;
        #pragma unroll
        for (int ni = 0; ni < 8; ni++) {
            if (kbase + ni * 8 + tg >= Tn)     { s[ni][0] = -1e30f; s[ni][2] = -1e30f; }
            if (kbase + ni * 8 + tg + 4 >= Tn) { s[ni][1] = -1e30f; s[ni][3] = -1e30f; }
            vmax0 = fmaxf(vmax0, fmaxf(s[ni][0], s[ni][1]));
            vmax1 = fmaxf(vmax1, fmaxf(s[ni][2], s[ni][3]));
        }
        vmax0 = fmaxf(vmax0, __shfl_xor_sync(0xffffffffu, vmax0, 1));
        vmax0 = fmaxf(vmax0, __shfl_xor_sync(0xffffffffu, vmax0, 2));
        vmax1 = fmaxf(vmax1, __shfl_xor_sync(0xffffffffu, vmax1, 1));
        vmax1 = fmaxf(vmax1, __shfl_xor_sync(0xffffffffu, vmax1, 2));
        float mn0 = fmaxf(m0, vmax0), mn1 = fmaxf(m1, vmax1);
        float sc0 = expf(m0 - mn0), sc1 = expf(m1 - mn1);
        float rs0 = 0.f, rs1 = 0.f;
        #pragma unroll
        for (int ni = 0; ni < 8; ni++) {
            s[ni][0] = expf(s[ni][0] - mn0); rs0 += s[ni][0];
            s[ni][1] = expf(s[ni][1] - mn0); rs0 += s[ni][1];
            s[ni][2] = expf(s[ni][2] - mn1); rs1 += s[ni][2];
            s[ni][3] = expf(s[ni][3] - mn1); rs1 += s[ni][3];
        }
        rs0 += __shfl_xor_sync(0xffffffffu, rs0, 1);
        rs0 += __shfl_xor_sync(0xffffffffu, rs0, 2);
        rs1 += __shfl_xor_sync(0xffffffffu, rs1, 1);
        rs1 += __shfl_xor_sync(0xffffffffu, rs1, 2);
        l0 = l0 * sc0 + rs0; m0 = mn0;
        l1 = l1 * sc1 + rs1; m1 = mn1;
        #pragma unroll
        for (int ni = 0; ni < 8; ni++) {
            o[ni][0] *= sc0; o[ni][1] *= sc0;
            o[ni][2] *= sc1; o[ni][3] *= sc1;
        }

        #pragma unroll
        for (int kb2 = 0; kb2 < 8; kb2++) {
            int k8 = kb2 * 8;
            uint32_t af[4];
            af[0] = __float_as_uint(s[kb2][0]);
            af[1] = __float_as_uint(s[kb2][2]);
            af[2] = __float_as_uint(s[kb2][1]);
            af[3] = __float_as_uint(s[kb2][3]);
            #pragma unroll
            for (int ni = 0; ni < 8; ni++) {
                uint32_t b0 = __float_as_uint(Vt[(ni * 8 + gid) * 68 + k8 + tg    ]);
                uint32_t b1 = __float_as_uint(Vt[(ni * 8 + gid) * 68 + k8 + tg + 4]);
                asm volatile(
                    "mma.sync.aligned.m16n8k8.row.col.f32.tf32.tf32.f32 "
                    "{%0,%1,%2,%3}, {%4,%5,%6,%7}, {%8,%9}, {%0,%1,%2,%3};\n"
                    : "+f"(o[ni][0]), "+f"(o[ni][1]), "+f"(o[ni][2]), "+f"(o[ni][3])
                    : "r"(af[0]), "r"(af[1]), "r"(af[2]), "r"(af[3]),
                      "r"(b0), "r"(b1));
            }
        }
    }

    float inv0 = 1.f / l0, inv1 = 1.f / l1;
    int t0 = qbase + wm + gid;
    int t1 = t0 + 8;
    #pragma unroll
    for (int ni = 0; ni < 8; ni++) {
        int c = h * HD + ni * 8 + tg * 2;
        if (t0 < Tn) {
            float2 vv;
            vv.x = tf32r(o[ni][0] * inv0);
            vv.y = tf32r(o[ni][1] * inv0);
            *(float2*)&out[(size_t)(b * Tn + t0) * Cn + c] = vv;
        }
        if (t1 < Tn) {
            float2 vv;
            vv.x = tf32r(o[ni][2] * inv1);
            vv.y = tf32r(o[ni][3] * inv1);
            *(float2*)&out[(size_t)(b * Tn + t1) * Cn + c] = vv;
        }
    }
}

__global__ void attn_tail(const float* __restrict__ qkv, float* __restrict__ out)
{
    int h = blockIdx.x, b = blockIdx.y;
    int tid = threadIdx.x;
    __shared__ float q[64];
    __shared__ float p[Tn];
    __shared__ float red[256];
    const float* qp = qkv + (size_t)(b * Tn + Tn - 1) * (3 * Cn) + h * HD;
    if (tid < 64) q[tid] = qp[tid] * 0.125f;
    __syncthreads();
    float lmax = -1e30f;
    for (int j = tid; j < Tn; j += 256) {
        const float* kp = qkv + (size_t)(b * Tn + j) * (3 * Cn) + Cn + h * HD;
        float s = 0.f;
        #pragma unroll 8
        for (int d = 0; d < 64; d++) s += q[d] * kp[d];
        p[j] = s;
        lmax = fmaxf(lmax, s);
    }
    float rmax = blockReduceMax256(lmax, red);
    float lsum = 0.f;
    for (int j = tid; j < Tn; j += 256) {
        float e = expf(p[j] - rmax);
        p[j] = e; lsum += e;
    }
    float rsum = blockReduceSum256(lsum, red);
    int d = tid & 63, part = tid >> 6;
    float acc = 0.f;
    for (int j = part; j < Tn; j += 4)
        acc += p[j] * qkv[(size_t)(b * Tn + j) * (3 * Cn) + 2 * Cn + h * HD + d];
    red[tid] = acc;
    __syncthreads();
    if (part == 0) {
        float v = red[d] + red[d + 64] + red[d + 128] + red[d + 192];
        out[(size_t)(b * Tn + Tn - 1) * Cn + h * HD + d] = tf32r(v / rsum);
    }
}

// ---------------- adapter (+ fused plain-LN producing z) ----------------
__global__ void adapter_kernel(const float* __restrict__ xffn, const float* __restrict__ x1,
                               const float* __restrict__ Wa1, const float* __restrict__ ba1,
                               const float* __restrict__ Wa2, const float* __restrict__ ba2,
                               float* __restrict__ x2, float* __restrict__ z)
{
    int r = blockIdx.x;
    int tid = threadIdx.x;
    __shared__ float xr[Cn];
    __shared__ float x2s[Cn];
    __shared__ float tg[ADn];
    __shared__ float red[256];
    const float* xp = xffn + (size_t)r * Cn;
    for (int c = tid; c < Cn; c += 256) xr[c] = xp[c];
    __syncthreads();
    int w = tid >> 5, lane = tid & 31;
    for (int a = w; a < ADn; a += 8) {
        float p = 0.f;
        const float* ww = Wa1 + (size_t)a * Cn;
        for (int c = lane; c < Cn; c += 32) p += xr[c] * ww[c];
        #pragma unroll
        for (int off = 16; off > 0; off >>= 1) p += __shfl_xor_sync(0xffffffffu, p, off);
        if (lane == 0) tg[a] = quick_gelu(p + ba1[a]);
    }
    __syncthreads();
    const float* x1p = x1 + (size_t)r * Cn;
    float s0 = 0.f;
    for (int c = tid; c < Cn; c += 256) {
        float acc = ba2[c];
        const float* w2 = Wa2 + (size_t)c * ADn;
        #pragma unroll
        for (int a = 0; a < ADn; a++) acc += tg[a] * w2[a];
        float v = x1p[c] + xr[c] + 0.5f * acc;
        x2s[c] = v;
        x2[(size_t)r * Cn + c] = v;
        s0 += v;
    }
    int t = r % Tn;
    if (t == 0) return;
    float mean = blockReduceSum256(s0, red) * (1.f / Cn);
    float s1 = 0.f;
    for (int c = tid; c < Cn; c += 256) { float d = x2s[c] - mean; s1 += d * d; }
    float var = blockReduceSum256(s1, red) * (1.f / Cn);
    float inv = rsqrtf(var + EPSf);
    int zi = (r / Tn) * 512 + (t - 1);
    float* zp = z + (size_t)zi * Cn;
    for (int c = tid; c < Cn; c += 256)
        zp[c] = tf32r((x2s[c] - mean) * inv);
}

// ---------------- view weight prep ----------------
__global__ void wprep_kernel(const float* __restrict__ aqw, const float* __restrict__ aqb,
                             const float* __restrict__ n3g, const float* __restrict__ n3b)
{
    int vj = blockIdx.x;
    int v = vj / 36;
    int tid = threadIdx.x;
    __shared__ float red[256];
    const float* w = aqw + (size_t)vj * Cn;
    const float* gg = n3g + (size_t)v * Cn;
    const float* bb = n3b + (size_t)v * Cn;
    float s = 0.f;
    for (int c = tid; c < Cn; c += 256) {
        float wv = w[c];
        g_weff[(size_t)vj * Cn + c] = tf32r(wv * gg[c]);
        s += wv * bb[c];
    }
    s = blockReduceSum256(s, red);
    if (tid == 0) g_beff[vj] = aqb[vj] + s;
}

// ---------------- cluster (3d) pooling chain ----------------
__global__ void pool_init(int R)
{
    int i = blockIdx.x * blockDim.x + threadIdx.x;
    if (i <= R) g_hist[i] = 0;
    if (i < Cn) { g_colsum[i] = 0.0; g_colsq[i] = 0.0; }
}
__global__ void hist_count(const int* __restrict__ idx)
{
    int i = blockIdx.x * blockDim.x + threadIdx.x;
    if (i < BG) atomicAdd(&g_hist[idx[i]], 1);
}
__global__ void scan_kernel(int R)
{
    __shared__ int part[1024];
    int tid = threadIdx.x;
    int chunk = (R + 1023) / 1024;
    int t0 = tid * chunk;
    int s = 0;
    for (int j = 0; j < chunk; j++)
        if (t0 + j < R) s += g_hist[t0 + j];
    part[tid] = s;
    __syncthreads();
    for (int off = 1; off < 1024; off <<= 1) {
        int v = (tid >= off) ? part[tid - off] : 0;
        __syncthreads();
        part[tid] += v;
        __syncthreads();
    }
    int run = (tid > 0) ? part[tid - 1] : 0;
    for (int j = 0; j < chunk; j++) {
        if (t0 + j < R) {
            int c = g_hist[t0 + j];
            g_off[t0 + j] = run;
            g_cur[t0 + j] = run;
            run += c;
        }
    }
    if (tid == 1023) g_off[R] = part[1023];
}
__global__ void seg_place(const int* __restrict__ idx)
{
    int i = blockIdx.x * blockDim.x + threadIdx.x;
    if (i >= BG) return;
    int p = atomicAdd(&g_cur[idx[i]], 1);
    g_ord[p] = i;
}
__global__ void seg_reduce(const float* __restrict__ src)
{
    int r = blockIdx.x;
    int tid = threadIdx.x;
    int s0 = g_off[r], s1 = g_off[r + 1];
    float mx0 = -1e30f, mx1 = -1e30f, mx2 = -1e30f;
    float sm0 = 0.f, sm1 = 0.f, sm2 = 0.f;
    for (int j = s0; j < s1; j++) {
        int i = g_ord[j];
        const float* p = src + (size_t)featRow(i) * Cn;
        float v0 = p[tid], v1 = p[tid + 256], v2 = p[tid + 512];
        mx0 = fmaxf(mx0, v0); sm0 += v0;
        mx1 = fmaxf(mx1, v1); sm1 += v1;
        mx2 = fmaxf(mx2, v2); sm2 += v2;
    }
    int cnt = s1 - s0;
    float inv = 1.f / (float)(cnt > 0 ? cnt : 1);
    float* op = g_scomb + (size_t)r * Cn;
    op[tid]       = (cnt > 0 ? mx0 : 0.f) + sm0 * inv;
    op[tid + 256] = (cnt > 0 ? mx1 : 0.f) + sm1 * inv;
    op[tid + 512] = (cnt > 0 ? mx2 : 0.f) + sm2 * inv;
}
__global__ void colstats(int R)
{
    int col = blockIdx.x * blockDim.x + threadIdx.x;
    if (col >= Cn) return;
    int chunk = (R + gridDim.y - 1) / gridDim.y;
    int r0 = blockIdx.y * chunk;
    int r1 = min(r0 + chunk, R);
    float sum = 0.f, sq = 0.f;
    for (int r = r0; r < r1; r++) {
        float v = g_scomb[(size_t)r * Cn + col];
        sum += v; sq += v * v;
    }
    atomicAdd(&g_colsum[col], (double)sum);
    atomicAdd(&g_colsq[col], (double)sq);
}
__global__ void colfinal(int R)
{
    int col = blockIdx.x * blockDim.x + threadIdx.x;
    if (col >= Cn) return;
    double mean = g_colsum[col] / R;
    double var = g_colsq[col] / R - mean * mean;
    if (var < 0.0) var = 0.0;
    g_mean[col] = (float)mean;
    g_rstd[col] = rsqrtf((float)var + EPSf);
}
__global__ void bn_apply(const float* __restrict__ gam, const float* __restrict__ bet,
                         float* __restrict__ out, int R)
{
    int i = blockIdx.x * blockDim.x + threadIdx.x;
    if (i >= R * Cn) return;
    int col = i % Cn;
    float v = (g_scomb[i] - g_mean[col]) * g_rstd[col] * gam[col] + bet[col];
    out[i] = gelu_exact(v);
}

// ---------------- batched (x6 views) pooling chain ----------------
__global__ void pool_init6()
{
    int v = blockIdx.y;
    int i = blockIdx.x * blockDim.x + threadIdx.x;
    if (i <= D1n) g_hist6[v * (D1n + 1) + i] = 0;
    if (i < Cn) { g_colsum6[v * Cn + i] = 0.0; g_colsq6[v * Cn + i] = 0.0; }
}
__global__ void hist_count6(const int* __restrict__ fgi)
{
    int v = blockIdx.y;
    int i = blockIdx.x * blockDim.x + threadIdx.x;
    if (i < BG) atomicAdd(&g_hist6[v * (D1n + 1) + fgi[(size_t)v * BG + i]], 1);
}
__global__ void scan6()
{
    int v = blockIdx.x;
    int* hist = g_hist6 + v * (D1n + 1);
    int* off  = g_off6  + v * (D1n + 1);
    int* cur  = g_cur6  + v * (D1n + 1);
    __shared__ int part[1024];
    int tid = threadIdx.x;
    const int R = D1n;
    int chunk = (R + 1023) / 1024;
    int t0 = tid * chunk;
    int s = 0;
    for (int j = 0; j < chunk; j++)
        if (t0 + j < R) s += hist[t0 + j];
    part[tid] = s;
    __syncthreads();
    for (int off2 = 1; off2 < 1024; off2 <<= 1) {
        int vv = (tid >= off2) ? part[tid - off2] : 0;
        __syncthreads();
        part[tid] += vv;
        __syncthreads();
    }
    int run = (tid > 0) ? part[tid - 1] : 0;
    for (int j = 0; j < chunk; j++) {
        if (t0 + j < R) {
            int c = hist[t0 + j];
            off[t0 + j] = run;
            cur[t0 + j] = run;
            run += c;
        }
    }
    if (tid == 1023) off[R] = part[1023];
}
__global__ void seg_place6(const int* __restrict__ fgi)
{
    int v = blockIdx.y;
    int i = blockIdx.x * blockDim.x + threadIdx.x;
    if (i >= BG) return;
    int p = atomicAdd(&g_cur6[v * (D1n + 1) + fgi[(size_t)v * BG + i]], 1);
    g_ord6[(size_t)v * BG + p] = i;
}
__global__ void view_attn6(const float* __restrict__ qkv1, const unsigned char* __restrict__ mask)
{
    int blk = blockIdx.x, h = blockIdx.y, v = blockIdx.z;
    int t = threadIdx.x;
    __shared__ float kk[N1n][2];
    __shared__ float vv[N1n][2];
    int row = blk * N1n + t;
    const float* base = qkv1 + (size_t)row * NQ1 + v * 36;
    float q0 = base[h * 2]     * 0.28867513459481287f;
    float q1 = base[h * 2 + 1] * 0.28867513459481287f;
    kk[t][0] = base[12 + h * 2]; kk[t][1] = base[13 + h * 2];
    vv[t][0] = base[24 + h * 2]; vv[t][1] = base[25 + h * 2];
    __syncthreads();
    const unsigned char* mrow = mask + (size_t)v * NB1 * N1n * N1n + ((size_t)blk * N1n + t) * N1n;
    float mmax = -1e30f;
    #pragma unroll 4
    for (int j = 0; j < N1n; j++) {
        float s = q0 * kk[j][0] + q1 * kk[j][1] + (mrow[j] ? -100000.f : 0.f);
        mmax = fmaxf(mmax, s);
    }
    float l = 0.f, a0 = 0.f, a1 = 0.f;
    #pragma unroll 4
    for (int j = 0; j < N1n; j++) {
        float s = q0 * kk[j][0] + q1 * kk[j][1] + (mrow[j] ? -100000.f : 0.f);
        float p = expf(s - mmax);
        l += p; a0 += p * vv[j][0]; a1 += p * vv[j][1];
    }
    float* o1 = g_o16 + (size_t)v * BG * MIDn;
    o1[(size_t)row * MIDn + h * 2]     = a0 / l;
    o1[(size_t)row * MIDn + h * 2 + 1] = a1 / l;
}
__global__ void seg_reduce_view6(const float* __restrict__ apw, const float* __restrict__ apb,
                                 const float* __restrict__ x2)
{
    int r = blockIdx.x, v = blockIdx.y;
    int tid = threadIdx.x;
    const int* off = g_off6 + v * (D1n + 1);
    const int* ord = g_ord6 + (size_t)v * BG;
    const float* o1 = g_o16 + (size_t)v * BG * MIDn;
    const float* pw = apw + (size_t)v * Cn * MIDn;
    const float* pb = apb + (size_t)v * Cn;
    int s0 = off[r], s1 = off[r + 1];
    float wr[3][MIDn], pbv[3];
    #pragma unroll
    for (int ch = 0; ch < 3; ch++) {
        int c = tid + ch * 256;
        pbv[ch] = pb[c];
        #pragma unroll
        for (int k = 0; k < MIDn; k++) wr[ch][k] = __ldg(&pw[(size_t)c * MIDn + k]);
    }
    float mx[3] = {-1e30f, -1e30f, -1e30f};
    float sm[3] = {0.f, 0.f, 0.f};
    for (int j = s0; j < s1; j++) {
        int i = ord[j];
        const float4* ob = (const float4*)&o1[(size_t)i * MIDn];
        float4 o0 = __ldg(ob), o1v = __ldg(ob + 1), o2 = __ldg(ob + 2);
        float os[MIDn] = {o0.x, o0.y, o0.z, o0.w, o1v.x, o1v.y, o1v.z, o1v.w,
                          o2.x, o2.y, o2.z, o2.w};
        const float* xp = x2 + (size_t)featRow(i) * Cn;
        #pragma unroll
        for (int ch = 0; ch < 3; ch++) {
            float vv = pbv[ch] + xp[tid + ch * 256];
            #pragma unroll
            for (int k = 0; k < MIDn; k++) vv += os[k] * wr[ch][k];
            mx[ch] = fmaxf(mx[ch], vv);
            sm[ch] += vv;
        }
    }
    int cnt = s1 - s0;
    float inv = 1.f / (float)(cnt > 0 ? cnt : 1);
    float* op = g_scomb6 + ((size_t)v * D1n + r) * Cn;
    #pragma unroll
    for (int ch = 0; ch < 3; ch++)
        op[tid + ch * 256] = (cnt > 0 ? mx[ch] : 0.f) + sm[ch] * inv;
}
__global__ void colstats6()
{
    int col = blockIdx.x * blockDim.x + threadIdx.x;
    int v = blockIdx.z;
    if (col >= Cn) return;
    const int R = D1n;
    int chunk = (R + gridDim.y - 1) / gridDim.y;
    int r0 = blockIdx.y * chunk;
    int r1 = min(r0 + chunk, R);
    float sum = 0.f, sq = 0.f;
    const float* sc = g_scomb6 + (size_t)v * D1n * Cn;
    for (int r = r0; r < r1; r++) {
        float vv = sc[(size_t)r * Cn + col];
        sum += vv; sq += vv * vv;
    }
    atomicAdd(&g_colsum6[v * Cn + col], (double)sum);
    atomicAdd(&g_colsq6[v * Cn + col], (double)sq);
}
__global__ void colfinal6()
{
    int col = blockIdx.x * blockDim.x + threadIdx.x;
    int v = blockIdx.y;
    if (col >= Cn) return;
    double mean = g_colsum6[v * Cn + col] / D1n;
    double var = g_colsq6[v * Cn + col] / D1n - mean * mean;
    if (var < 0.0) var = 0.0;
    g_mean6[v * Cn + col] = (float)mean;
    g_rstd6[v * Cn + col] = rsqrtf((float)var + EPSf);
}
__global__ void bn_apply6(const float* __restrict__ bn1dg, const float* __restrict__ bn1db,
                          float* __restrict__ bview)
{
    int v = blockIdx.y;
    int i = blockIdx.x * blockDim.x + threadIdx.x;
    if (i >= D1n * Cn) return;
    int col = i % Cn;
    float vv = (g_scomb6[(size_t)v * D1n * Cn + i] - g_mean6[v * Cn + col]) * g_rstd6[v * Cn + col]
               * bn1dg[v * Cn + col] + bn1db[v * Cn + col];
    bview[(size_t)v * D1n * Cn + i] = gelu_exact(vv);
}

// ---------------- final fusion ----------------
__global__ void final_kernel(const float* __restrict__ x2, const float* __restrict__ g3,
                             const float* __restrict__ bview, const int* __restrict__ cluster,
                             const int* __restrict__ fgi, float* __restrict__ out)
{
    int i = blockIdx.x;
    int tid = threadIdx.x;
    size_t xrow = (size_t)featRow(i);
    __shared__ float x3[Cn];
    __shared__ float pv[NV][Cn];
    __shared__ float red[256];
    __shared__ float sims[NV];
    int cl = cluster[i];
    const float* x3p = g3 + (size_t)cl * Cn;
    for (int c = tid; c < Cn; c += 256) x3[c] = x3p[c];
    for (int v = 0; v < NV; v++) {
        int id = fgi[(size_t)v * BG + i];
        const float* pp = bview + ((size_t)v * D1n + id) * Cn;
        for (int c = tid; c < Cn; c += 256) pv[v][c] = pp[c];
    }
    __syncthreads();
    float p = 0.f;
    for (int c = tid; c < Cn; c += 256) p += x3[c] * x3[c];
    float nx3 = fmaxf(sqrtf(blockReduceSum256(p, red)), 1e-8f);
    for (int v = 0; v < NV; v++) {
        float d = 0.f, n = 0.f;
        for (int c = tid; c < Cn; c += 256) {
            float a = pv[v][c];
            d += a * x3[c]; n += a * a;
        }
        d = blockReduceSum256(d, red);
        n = blockReduceSum256(n, red);
        if (tid == 0) {
            float np = fmaxf(sqrtf(n), 1e-8f);
            float cs = d / (np * nx3);
            sims[v] = (cs + 1.f) * 0.5f;
        }
        __syncthreads();
    }
    float ssum = 0.f;
    #pragma unroll
    for (int v = 0; v < NV; v++) ssum += sims[v];
    float inv = 1.f / ssum;
    const float* x2p = x2 + xrow * Cn;
    float* op = out + xrow * Cn;
    for (int c = tid; c < Cn; c += 256) {
        float sup = 0.f;
        #pragma unroll
        for (int v = 0; v < NV; v++) sup += pv[v][c] * sims[v];
        op[c] = x2p[c] + 0.3f * sup * inv;
    }
}

__global__ void cls_copy(const float* __restrict__ x2, float* __restrict__ out)
{
    size_t row = (size_t)blockIdx.x * Tn;
    for (int c = threadIdx.x; c < Cn; c += blockDim.x)
        out[row * Cn + c] = x2[row * Cn + c];
}

// ---------------- host launch ----------------
extern "C" void kernel_launch(void* const* d_in, const int* in_sizes, int n_in,
                              void* d_out, int out_size)
{
    const float* x    = (const float*)d_in[0];
    const float* ln1g = (const float*)d_in[1];
    const float* ln1b = (const float*)d_in[2];
    const float* ln2g = (const float*)d_in[3];
    const float* ln2b = (const float*)d_in[4];
    const float* Wqkv = (const float*)d_in[5];
    const float* bqkv = (const float*)d_in[6];
    const float* Wo   = (const float*)d_in[7];
    const float* bo   = (const float*)d_in[8];
    const float* Wfc  = (const float*)d_in[9];
    const float* bfc  = (const float*)d_in[10];
    const float* Wproj= (const float*)d_in[11];
    const float* bproj= (const float*)d_in[12];
    const float* Wa1  = (const float*)d_in[13];
    const float* ba1  = (const float*)d_in[14];
    const float* Wa2  = (const float*)d_in[15];
    const float* ba2  = (const float*)d_in[16];
    const float* bn3dg= (const float*)d_in[17];
    const float* bn3db= (const float*)d_in[18];
    const float* bn1dg= (const float*)d_in[19];
    const float* bn1db= (const float*)d_in[20];
    const float* n3g  = (const float*)d_in[21];
    const float* n3b  = (const float*)d_in[22];
    const float* aqw  = (const float*)d_in[23];
    const float* aqb  = (const float*)d_in[24];
    const float* apw  = (const float*)d_in[25];
    const float* apb  = (const float*)d_in[26];
    const int*   cluster = (const int*)d_in[27];
    const int*   fgi  = (const int*)d_in[28];
    const unsigned char* mask = (const unsigned char*)d_in[29];
    float* out = (float*)d_out;

    float *y, *qkv, *att, *x1, *hfc, *xffn, *x2, *g3, *bview, *z, *qkv1, *weff, *beff;
    cudaGetSymbolAddress((void**)&y,     g_y);
    cudaGetSymbolAddress((void**)&qkv,   g_qkv);
    cudaGetSymbolAddress((void**)&att,   g_att);
    cudaGetSymbolAddress((void**)&x1,    g_x1);
    cudaGetSymbolAddress((void**)&hfc,   g_hfc);
    cudaGetSymbolAddress((void**)&xffn,  g_xffn);
    cudaGetSymbolAddress((void**)&x2,    g_x2);
    cudaGetSymbolAddress((void**)&g3,    g_g3);
    cudaGetSymbolAddress((void**)&bview, g_bview);
    cudaGetSymbolAddress((void**)&z,     g_z);
    cudaGetSymbolAddress((void**)&qkv1,  g_qkv1);
    cudaGetSymbolAddress((void**)&weff,  g_weff);
    cudaGetSymbolAddress((void**)&beff,  g_beff);

    cudaFuncSetAttribute(attn_tc, cudaFuncAttributeMaxDynamicSharedMemorySize, ATTN_SMEM);
    cudaFuncSetAttribute(gemm_tf32<0>, cudaFuncAttributeMaxDynamicSharedMemorySize, GEMM_SMEM);
    cudaFuncSetAttribute(gemm_tf32<1>, cudaFuncAttributeMaxDynamicSharedMemorySize, GEMM_SMEM);
    cudaFuncSetAttribute(gemm_tf32<2>, cudaFuncAttributeMaxDynamicSharedMemorySize, GEMM_SMEM);

    const int GMB = (MROWS + 127) / 128;  // 129

    // 1) LN1 -> y (tf32-rounded)
    ln_kernel<<<MROWS, 256>>>(x, ln1g, ln1b, y, 0);
    // 2) QKV GEMM (weights direct; HW truncation)
    gemm_tf32<0><<<dim3(GMB, (3 * Cn) / 128), 256, GEMM_SMEM>>>(y, Wqkv, bqkv, nullptr, qkv, MROWS, 3 * Cn, Cn);
    // 3) attention + tail
    attn_tc<<<dim3(4, Hn, Bn), 256, ATTN_SMEM>>>(qkv, att);
    attn_tail<<<dim3(Hn, Bn), 256>>>(qkv, att);
    // 4) output proj + residual
    gemm_tf32<2><<<dim3(GMB, Cn / 128), 256, GEMM_SMEM>>>(att, Wo, bo, x, x1, MROWS, Cn, Cn);
    // 5) LN2 -> y
    ln_kernel<<<MROWS, 256>>>(x1, ln2g, ln2b, y, 0);
    // 6) FC + quick_gelu
    gemm_tf32<1><<<dim3(GMB, FFn / 128), 256, GEMM_SMEM>>>(y, Wfc, bfc, nullptr, hfc, MROWS, FFn, Cn);
    // 7) proj
    gemm_tf32<0><<<dim3(GMB, Cn / 128), 256, GEMM_SMEM>>>(hfc, Wproj, bproj, nullptr, xffn, MROWS, Cn, FFn);
    // 8) adapter + residuals -> x2, fused plain LN -> z
    adapter_kernel<<<MROWS, 256>>>(xffn, x1, Wa1, ba1, Wa2, ba2, x2, z);

    // 9) 3d segment pool + BN over clusters
    {
        pool_init<<<(NCL + 1 + 255) / 256, 256>>>(NCL);
        hist_count<<<(BG + 255) / 256, 256>>>(cluster);
        scan_kernel<<<1, 1024>>>(NCL);
        seg_place<<<(BG + 255) / 256, 256>>>(cluster);
        seg_reduce<<<NCL, 256>>>(x2);
        colstats<<<dim3(3, 16), 256>>>(NCL);
        colfinal<<<3, 256>>>(NCL);
        bn_apply<<<(NCL * Cn + 255) / 256, 256>>>(bn3dg, bn3db, g3, NCL);
    }

    // 10) view branches (batched; z produced by adapter)
    wprep_kernel<<<NQ1, 256>>>(aqw, aqb, n3g, n3b);
    gemm_tf32<0><<<dim3(BG / 128, (NQ1 + 127) / 128), 256, GEMM_SMEM>>>(z, weff, beff, nullptr, qkv1,
                                                                        BG, NQ1, Cn);
    view_attn6<<<dim3(NB1, H1n, NV), N1n>>>(qkv1, mask);
    pool_init6<<<dim3((D1n + 1 + 255) / 256, NV), 256>>>();
    hist_count6<<<dim3((BG + 255) / 256, NV), 256>>>(fgi);
    scan6<<<NV, 1024>>>();
    seg_place6<<<dim3((BG + 255) / 256, NV), 256>>>(fgi);
    seg_reduce_view6<<<dim3(D1n, NV), 256>>>(apw, apb, x2);
    colstats6<<<dim3(3, 16, NV), 256>>>();
    colfinal6<<<dim3(3, NV), 256>>>();
    bn_apply6<<<dim3((D1n * Cn + 255) / 256, NV), 256>>>(bn1dg, bn1db, bview);

    // 11) cossim fusion + output
    final_kernel<<<BG, 256>>>(x2, g3, bview, cluster, fgi, out);
    cls_copy<<<Bn, 256>>>(x2, out);
}

// round 13
// speedup vs baseline: 1.1708x; 1.0002x over previous
#include <cuda_runtime.h>
#include <cuda_bf16.h>
#include <math.h>
#include <stdint.h>

// ---------------- problem constants ----------------
#define Bn    32
#define Gn    512
#define Cn    768
#define Hn    12
#define HD    64
#define Tn    513              // G+1
#define MROWS (Bn*Tn)          // 16416
#define BG    16384
#define FFn   3072
#define ADn   16
#define MIDn  12
#define H1n   6
#define N1n   128
#define NB1   (BG/N1n)         // 128
#define NCL   2048
#define D1n   6272
#define NV    6
#define NQ1   (NV*3*MIDn)      // 216
#define EPSf  1e-5f

// ---------------- scratch (device globals; no allocation) ----------------
__device__ float  g_y   [MROWS*Cn];
__device__ float  g_qkv [MROWS*3*Cn];
__device__ float  g_att [MROWS*Cn];
__device__ float  g_x1  [MROWS*Cn];
__device__ float  g_hfc [MROWS*FFn];
__device__ float  g_xffn[MROWS*Cn];
__device__ float  g_x2  [MROWS*Cn];
__device__ float  g_g3   [NCL*Cn];
__device__ float  g_bview[NV*D1n*Cn];
__device__ float  g_z    [BG*Cn];          // nhat (un-affined LN of feat)
__device__ float  g_qkv1 [BG*NQ1];
__device__ float  g_weff [NQ1*Cn];
__device__ float  g_beff [NQ1];
// cluster (3d) pooling buffers
__device__ float  g_scomb [NCL*Cn];
__device__ double g_colsum[Cn];
__device__ double g_colsq [Cn];
__device__ float  g_mean[Cn];
__device__ float  g_rstd[Cn];
__device__ int    g_hist[NCL+1];
__device__ int    g_off [NCL+1];
__device__ int    g_cur [NCL+1];
__device__ int    g_ord [BG];
// batched view pooling buffers
__device__ int    g_hist6[NV*(D1n+1)];
__device__ int    g_off6 [NV*(D1n+1)];
__device__ int    g_cur6 [NV*(D1n+1)];
__device__ int    g_ord6 [NV*BG];
__device__ float  g_scomb6[(size_t)NV*D1n*Cn];
__device__ double g_colsum6[NV*Cn];
__device__ double g_colsq6 [NV*Cn];
__device__ float  g_mean6[NV*Cn];
__device__ float  g_rstd6[NV*Cn];
__device__ float  g_o16  [NV*BG*MIDn];

// ---------------- helpers ----------------
__device__ __forceinline__ float blockReduceSum256(float v, float* red) {
    int tid = threadIdx.x;
    red[tid] = v; __syncthreads();
    #pragma unroll
    for (int o = 128; o > 0; o >>= 1) {
        if (tid < o) red[tid] += red[tid + o];
        __syncthreads();
    }
    float r = red[0];
    __syncthreads();
    return r;
}
__device__ __forceinline__ float blockReduceMax256(float v, float* red) {
    int tid = threadIdx.x;
    red[tid] = v; __syncthreads();
    #pragma unroll
    for (int o = 128; o > 0; o >>= 1) {
        if (tid < o) red[tid] = fmaxf(red[tid], red[tid + o]);
        __syncthreads();
    }
    float r = red[0];
    __syncthreads();
    return r;
}
__device__ __forceinline__ float quick_gelu(float x) {
    return x / (1.f + expf(-1.702f * x));
}
__device__ __forceinline__ float gelu_exact(float x) {
    return 0.5f * x * (1.f + erff(x * 0.70710678118654752f));
}
__device__ __forceinline__ int featRow(int i) {
    return (i >> 9) * Tn + 1 + (i & 511);
}
__device__ __forceinline__ float tf32r(float f) {
    uint32_t u;
    asm volatile("cvt.rna.tf32.f32 %0, %1;" : "=r"(u) : "f"(f));
    return __uint_as_float(u);
}

// ---------------- LayerNorm (tf32-rounded out) ----------------
__global__ void ln_kernel(const float* __restrict__ in, const float* __restrict__ g,
                          const float* __restrict__ b, float* __restrict__ out, int featmode)
{
    int r = blockIdx.x;
    int row = featmode ? featRow(r) : r;
    const float* x = in + (size_t)row * Cn;
    __shared__ float xs[Cn];
    __shared__ float red[256];
    int tid = threadIdx.x;
    float s0 = 0.f;
    for (int c = tid; c < Cn; c += 256) { float v = x[c]; xs[c] = v; s0 += v; }
    float mean = blockReduceSum256(s0, red) * (1.f / Cn);
    float s1 = 0.f;
    for (int c = tid; c < Cn; c += 256) { float d = xs[c] - mean; s1 += d * d; }
    float var = blockReduceSum256(s1, red) * (1.f / Cn);
    float inv = rsqrtf(var + EPSf);
    float* op = out + (size_t)r * Cn;
    for (int c = tid; c < Cn; c += 256)
        op[c] = tf32r((xs[c] - mean) * inv * g[c] + b[c]);
}

// ---------------- mma.sync tf32 NT GEMM, 3-stage cp.async pipeline (proven R4/R6) ----------------
#define GEMM_SMEM (3 * 2 * 128 * 20 * 4)   // 61440 bytes
template <int EPI>
__global__ void __launch_bounds__(256, 2) gemm_tf32(
    const float* __restrict__ A, const float* __restrict__ W,
    const float* __restrict__ bias, const float* __restrict__ res,
    float* __restrict__ C, int M, int N, int K)
{
    extern __shared__ float sm_[];
    int tid = threadIdx.x;
    int bm = blockIdx.x * 128, bn = blockIdx.y * 128;
    int lane = tid & 31, wid = tid >> 5;
    int wm = (wid & 1) * 64, wn = (wid >> 1) * 32;
    int gid = lane >> 2, tg = lane & 3;

    float acc[4][4][4];
    #pragma unroll
    for (int a = 0; a < 4; a++)
        #pragma unroll
        for (int b = 0; b < 4; b++)
            #pragma unroll
            for (int c = 0; c < 4; c++) acc[a][b][c] = 0.f;

    auto prefetch = [&](int kt, int s) {
        int k0 = kt * 16;
        float* As = sm_ + s * 2560;
        float* Bs = sm_ + 7680 + s * 2560;
        #pragma unroll
        for (int i = 0; i < 2; i++) {
            int r = (tid >> 2) + i * 64;
            int c = (tid & 3) * 4;
            int arow = bm + r;
            const float* asrc = A + (size_t)(arow < M ? arow : 0) * K + k0 + c;
            uint32_t adst = (uint32_t)__cvta_generic_to_shared(&As[r * 20 + c]);
            int asz = (arow < M) ? 16 : 0;
            asm volatile("cp.async.cg.shared.global [%0], [%1], 16, %2;\n"
                         :: "r"(adst), "l"(asrc), "r"(asz));
            int brow = bn + r;
            const float* bsrc = W + (size_t)(brow < N ? brow : 0) * K + k0 + c;
            uint32_t bdst = (uint32_t)__cvta_generic_to_shared(&Bs[r * 20 + c]);
            int bsz = (brow < N) ? 16 : 0;
            asm volatile("cp.async.cg.shared.global [%0], [%1], 16, %2;\n"
                         :: "r"(bdst), "l"(bsrc), "r"(bsz));
        }
    };

    int nt = K / 16;
    prefetch(0, 0);
    asm volatile("cp.async.commit_group;\n");
    if (nt > 1) prefetch(1, 1);
    asm volatile("cp.async.commit_group;\n");

    int buf = 0;
    for (int t = 0; t < nt; t++) {
        asm volatile("cp.async.wait_group 1;\n");
        __syncthreads();
        if (t + 2 < nt) prefetch(t + 2, (buf + 2) % 3);
        asm volatile("cp.async.commit_group;\n");
        const float* As = sm_ + buf * 2560;
        const float* Bs = sm_ + 7680 + buf * 2560;
        #pragma unroll
        for (int kk = 0; kk < 2; kk++) {
            int kb = kk * 8;
            uint32_t af[4][4], bf[4][2];
            #pragma unroll
            for (int mi = 0; mi < 4; mi++) {
                int r = wm + mi * 16 + gid;
                af[mi][0] = __float_as_uint(As[(r    ) * 20 + kb + tg    ]);
                af[mi][1] = __float_as_uint(As[(r + 8) * 20 + kb + tg    ]);
                af[mi][2] = __float_as_uint(As[(r    ) * 20 + kb + tg + 4]);
                af[mi][3] = __float_as_uint(As[(r + 8) * 20 + kb + tg + 4]);
            }
            #pragma unroll
            for (int ni = 0; ni < 4; ni++) {
                int n0 = wn + ni * 8 + gid;
                bf[ni][0] = __float_as_uint(Bs[n0 * 20 + kb + tg    ]);
                bf[ni][1] = __float_as_uint(Bs[n0 * 20 + kb + tg + 4]);
            }
            #pragma unroll
            for (int mi = 0; mi < 4; mi++)
                #pragma unroll
                for (int ni = 0; ni < 4; ni++)
                    asm volatile(
                        "mma.sync.aligned.m16n8k8.row.col.f32.tf32.tf32.f32 "
                        "{%0,%1,%2,%3}, {%4,%5,%6,%7}, {%8,%9}, {%0,%1,%2,%3};\n"
                        : "+f"(acc[mi][ni][0]), "+f"(acc[mi][ni][1]),
                          "+f"(acc[mi][ni][2]), "+f"(acc[mi][ni][3])
                        : "r"(af[mi][0]), "r"(af[mi][1]), "r"(af[mi][2]), "r"(af[mi][3]),
                          "r"(bf[ni][0]), "r"(bf[ni][1]));
        }
        __syncthreads();
        buf = (buf + 1) % 3;
    }

    #pragma unroll
    for (int mi = 0; mi < 4; mi++) {
        #pragma unroll
        for (int ni = 0; ni < 4; ni++) {
            int m0 = bm + wm + mi * 16 + gid;
            int n0 = bn + wn + ni * 8 + tg * 2;
            if (n0 >= N) continue;
            float b0 = bias[n0], b1 = bias[n0 + 1];
            #pragma unroll
            for (int hh = 0; hh < 2; hh++) {
                int m = m0 + hh * 8;
                if (m >= M) continue;
                float v0 = acc[mi][ni][hh * 2 + 0] + b0;
                float v1 = acc[mi][ni][hh * 2 + 1] + b1;
                if (EPI == 1) { v0 = tf32r(quick_gelu(v0)); v1 = tf32r(quick_gelu(v1)); }
                if (EPI == 2) {
                    float2 rr = *(const float2*)&res[(size_t)m * N + n0];
                    v0 += rr.x; v1 += rr.y;
                }
                float2 vv; vv.x = v0; vv.y = v1;
                *(float2*)&C[(size_t)m * N + n0] = vv;
            }
        }
    }
}

// ---------------- tensor-core flash attention (proven R6 version) ----------------
#define ATTN_SMEM ((128 + 64 + 64) * 68 * 4)
__global__ void __launch_bounds__(256) attn_tc(const float* __restrict__ qkv,
                                               float* __restrict__ out)
{
    extern __shared__ float sm[];
    float* Qs = sm;
    float* Ks = sm + 128 * 68;
    float* Vt = sm + 192 * 68;

    int qb = blockIdx.x, h = blockIdx.y, b = blockIdx.z;
    int tid = threadIdx.x, lane = tid & 31, wid = tid >> 5;
    int gid = lane >> 2, tg = lane & 3;
    int wm = wid * 16;
    int qbase = qb * 128;

    {
        int r = tid >> 1, c0 = (tid & 1) * 32;
        int t = qbase + r;
        bool valid = (t < Tn);
        const float* qp = qkv + (size_t)(b * Tn + (valid ? t : 0)) * (3 * Cn) + h * HD + c0;
        #pragma unroll
        for (int i = 0; i < 8; i++) {
            float4 v = *(const float4*)(qp + i * 4);
            float4 w;
            w.x = valid ? tf32r(v.x * 0.125f) : 0.f;
            w.y = valid ? tf32r(v.y * 0.125f) : 0.f;
            w.z = valid ? tf32r(v.z * 0.125f) : 0.f;
            w.w = valid ? tf32r(v.w * 0.125f) : 0.f;
            *(float4*)&Qs[r * 68 + c0 + i * 4] = w;
        }
    }

    float m0 = -1e30f, m1 = -1e30f, l0 = 0.f, l1 = 0.f;
    float o[8][4];
    #pragma unroll
    for (int ni = 0; ni < 8; ni++)
        #pragma unroll
        for (int j = 0; j < 4; j++) o[ni][j] = 0.f;

    for (int kb = 0; kb < 9; kb++) {
        int kbase = kb * 64;
        __syncthreads();
        {
            int r = tid >> 2, c0 = (tid & 3) * 16;
            int t = kbase + r;
            bool valid = (t < Tn);
            const float* kp = qkv + (size_t)(b * Tn + (valid ? t : 0)) * (3 * Cn) + Cn + h * HD + c0;
            const float* vp = kp + Cn;
            int low = r & 7;
            int pr = (r & ~7) | (((low & 3) << 1) | (low >> 2));
            #pragma unroll
            for (int i = 0; i < 16; i += 4) {
                float4 kv4 = *(const float4*)(kp + i);
                float4 w;
                w.x = valid ? tf32r(kv4.x) : 0.f;
                w.y = valid ? tf32r(kv4.y) : 0.f;
                w.z = valid ? tf32r(kv4.z) : 0.f;
                w.w = valid ? tf32r(kv4.w) : 0.f;
                *(float4*)&Ks[pr * 68 + c0 + i] = w;
            }
            #pragma unroll
            for (int i = 0; i < 16; i++)
                Vt[(c0 + i) * 68 + r] = valid ? tf32r(vp[i]) : 0.f;
        }
        __syncthreads();

        float s[8][4];
        #pragma unroll
        for (int ni = 0; ni < 8; ni++)
            #pragma unroll
            for (int j = 0; j < 4; j++) s[ni][j] = 0.f;
        #pragma unroll
        for (int ks = 0; ks < 8; ks++) {
            int k8 = ks * 8;
            uint32_t af[4];
            int r = wm + gid;
            af[0] = __float_as_uint(Qs[(r    ) * 68 + k8 + tg    ]);
            af[1] = __float_as_uint(Qs[(r + 8) * 68 + k8 + tg    ]);
            af[2] = __float_as_uint(Qs[(r    ) * 68 + k8 + tg + 4]);
            af[3] = __float_as_uint(Qs[(r + 8) * 68 + k8 + tg + 4]);
            #pragma unroll
            for (int ni = 0; ni < 8; ni++) {
                uint32_t b0 = __float_as_uint(Ks[(ni * 8 + gid) * 68 + k8 + tg    ]);
                uint32_t b1 = __float_as_uint(Ks[(ni * 8 + gid) * 68 + k8 + tg + 4]);
                asm volatile(
                    "mma.sync.aligned.m16n8k8.row.col.f32.tf32.tf32.f32 "
                    "{%0,%1,%2,%3}, {%4,%5,%6,%7}, {%8,%9}, {%0,%1,%2,%3};\n"
                    : "+f"(s[ni][0]), "+f"(s[ni][1]), "+f"(s[ni][2]), "+f"(s[ni][3])
                    : "r"(af[0]), "r"(af[1]), "r"(af[2]), "r"(af[3]),
                      "r"(b0), "r"(b1));
            }
        }

        float vmax0 = -1e30f, vmax1 = -1e30f;
        #pragma unroll
        for (int ni = 0; ni < 8; ni++) {
            if (kbase + ni * 8 + tg >= Tn)     { s[ni][0] = -1e30f; s[ni][2] = -1e30f; }
            if (kbase + ni * 8 + tg + 4 >= Tn) { s[ni][1] = -1e30f; s[ni][3] = -1e30f; }
            vmax0 = fmaxf(vmax0, fmaxf(s[ni][0], s[ni][1]));
            vmax1 = fmaxf(vmax1, fmaxf(s[ni][2], s[ni][3]));
        }
        vmax0 = fmaxf(vmax0, __shfl_xor_sync(0xffffffffu, vmax0, 1));
        vmax0 = fmaxf(vmax0, __shfl_xor_sync(0xffffffffu, vmax0, 2));
        vmax1 = fmaxf(vmax1, __shfl_xor_sync(0xffffffffu, vmax1, 1));
        vmax1 = fmaxf(vmax1, __shfl_xor_sync(0xffffffffu, vmax1, 2));
        float mn0 = fmaxf(m0, vmax0), mn1 = fmaxf(m1, vmax1);
        float sc0 = expf(m0 - mn0), sc1 = expf(m1 - mn1);
        float rs0 = 0.f, rs1 = 0.f;
        #pragma unroll
        for (int ni = 0; ni < 8; ni++) {
            s[ni][0] = expf(s[ni][0] - mn0); rs0 += s[ni][0];
            s[ni][1] = expf(s[ni][1] - mn0); rs0 += s[ni][1];
            s[ni][2] = expf(s[ni][2] - mn1); rs1 += s[ni][2];
            s[ni][3] = expf(s[ni][3] - mn1); rs1 += s[ni][3];
        }
        rs0 += __shfl_xor_sync(0xffffffffu, rs0, 1);
        rs0 += __shfl_xor_sync(0xffffffffu, rs0, 2);
        rs1 += __shfl_xor_sync(0xffffffffu, rs1, 1);
        rs1 += __shfl_xor_sync(0xffffffffu, rs1, 2);
        l0 = l0 * sc0 + rs0; m0 = mn0;
        l1 = l1 * sc1 + rs1; m1 = mn1;
        #pragma unroll
        for (int ni = 0; ni < 8; ni++) {
            o[ni][0] *= sc0; o[ni][1] *= sc0;
            o[ni][2] *= sc1; o[ni][3] *= sc1;
        }

        #pragma unroll
        for (int kb2 = 0; kb2 < 8; kb2++) {
            int k8 = kb2 * 8;
            uint32_t af[4];
            af[0] = __float_as_uint(s[kb2][0]);
            af[1] = __float_as_uint(s[kb2][2]);
            af[2] = __float_as_uint(s[kb2][1]);
            af[3] = __float_as_uint(s[kb2][3]);
            #pragma unroll
            for (int ni = 0; ni < 8; ni++) {
                uint32_t b0 = __float_as_uint(Vt[(ni * 8 + gid) * 68 + k8 + tg    ]);
                uint32_t b1 = __float_as_uint(Vt[(ni * 8 + gid) * 68 + k8 + tg + 4]);
                asm volatile(
                    "mma.sync.aligned.m16n8k8.row.col.f32.tf32.tf32.f32 "
                    "{%0,%1,%2,%3}, {%4,%5,%6,%7}, {%8,%9}, {%0,%1,%2,%3};\n"
                    : "+f"(o[ni][0]), "+f"(o[ni][1]), "+f"(o[ni][2]), "+f"(o[ni][3])
                    : "r"(af[0]), "r"(af[1]), "r"(af[2]), "r"(af[3]),
                      "r"(b0), "r"(b1));
            }
        }
    }

    float inv0 = 1.f / l0, inv1 = 1.f / l1;
    int t0 = qbase + wm + gid;
    int t1 = t0 + 8;
    #pragma unroll
    for (int ni = 0; ni < 8; ni++) {
        int c = h * HD + ni * 8 + tg * 2;
        if (t0 < Tn) {
            float2 vv;
            vv.x = tf32r(o[ni][0] * inv0);
            vv.y = tf32r(o[ni][1] * inv0);
            *(float2*)&out[(size_t)(b * Tn + t0) * Cn + c] = vv;
        }
        if (t1 < Tn) {
            float2 vv;
            vv.x = tf32r(o[ni][2] * inv1);
            vv.y = tf32r(o[ni][3] * inv1);
            *(float2*)&out[(size_t)(b * Tn + t1) * Cn + c] = vv;
        }
    }
}

// tail: q-row 512. Warp-per-key QK phase (coalesced), thread-per-d PV phase.
__global__ void attn_tail(const float* __restrict__ qkv, float* __restrict__ out)
{
    int h = blockIdx.x, b = blockIdx.y;
    int tid = threadIdx.x, lane = tid & 31, wid = tid >> 5;
    __shared__ float q[64];
    __shared__ float p[Tn];
    __shared__ float red[256];
    const float* qp = qkv + (size_t)(b * Tn + Tn - 1) * (3 * Cn) + h * HD;
    if (tid < 64) q[tid] = qp[tid] * 0.125f;
    __syncthreads();
    // QK: warp per key j; lanes cover d (coalesced)
    float q0 = q[lane], q1 = q[lane + 32];
    float lmax = -1e30f;
    for (int j = wid; j < Tn; j += 8) {
        const float* kp = qkv + (size_t)(b * Tn + j) * (3 * Cn) + Cn + h * HD;
        float s = q0 * kp[lane] + q1 * kp[lane + 32];
        #pragma unroll
        for (int off = 16; off > 0; off >>= 1)
            s += __shfl_xor_sync(0xffffffffu, s, off);
        if (lane == 0) p[j] = s;
        lmax = fmaxf(lmax, s);
    }
    float rmax = blockReduceMax256(lmax, red);
    float lsum = 0.f;
    for (int j = tid; j < Tn; j += 256) {
        float e = expf(p[j] - rmax);
        p[j] = e; lsum += e;
    }
    float rsum = blockReduceSum256(lsum, red);
    int d = tid & 63, part = tid >> 6;
    float acc = 0.f;
    for (int j = part; j < Tn; j += 4)
        acc += p[j] * qkv[(size_t)(b * Tn + j) * (3 * Cn) + 2 * Cn + h * HD + d];
    red[tid] = acc;
    __syncthreads();
    if (part == 0) {
        float v = red[d] + red[d + 64] + red[d + 128] + red[d + 192];
        out[(size_t)(b * Tn + Tn - 1) * Cn + h * HD + d] = tf32r(v / rsum);
    }
}

// ---------------- adapter (+ fused plain-LN producing z) ----------------
__global__ void adapter_kernel(const float* __restrict__ xffn, const float* __restrict__ x1,
                               const float* __restrict__ Wa1, const float* __restrict__ ba1,
                               const float* __restrict__ Wa2, const float* __restrict__ ba2,
                               float* __restrict__ x2, float* __restrict__ z)
{
    int r = blockIdx.x;
    int tid = threadIdx.x;
    __shared__ float xr[Cn];
    __shared__ float x2s[Cn];
    __shared__ float tg[ADn];
    __shared__ float red[256];
    const float* xp = xffn + (size_t)r * Cn;
    for (int c = tid; c < Cn; c += 256) xr[c] = xp[c];
    __syncthreads();
    int w = tid >> 5, lane = tid & 31;
    for (int a = w; a < ADn; a += 8) {
        float p = 0.f;
        const float* ww = Wa1 + (size_t)a * Cn;
        for (int c = lane; c < Cn; c += 32) p += xr[c] * ww[c];
        #pragma unroll
        for (int off = 16; off > 0; off >>= 1) p += __shfl_xor_sync(0xffffffffu, p, off);
        if (lane == 0) tg[a] = quick_gelu(p + ba1[a]);
    }
    __syncthreads();
    const float* x1p = x1 + (size_t)r * Cn;
    float s0 = 0.f;
    for (int c = tid; c < Cn; c += 256) {
        float acc = ba2[c];
        const float* w2 = Wa2 + (size_t)c * ADn;
        #pragma unroll
        for (int a = 0; a < ADn; a++) acc += tg[a] * w2[a];
        float v = x1p[c] + xr[c] + 0.5f * acc;
        x2s[c] = v;
        x2[(size_t)r * Cn + c] = v;
        s0 += v;
    }
    int t = r % Tn;
    if (t == 0) return;
    float mean = blockReduceSum256(s0, red) * (1.f / Cn);
    float s1 = 0.f;
    for (int c = tid; c < Cn; c += 256) { float d = x2s[c] - mean; s1 += d * d; }
    float var = blockReduceSum256(s1, red) * (1.f / Cn);
    float inv = rsqrtf(var + EPSf);
    int zi = (r / Tn) * 512 + (t - 1);
    float* zp = z + (size_t)zi * Cn;
    for (int c = tid; c < Cn; c += 256)
        zp[c] = tf32r((x2s[c] - mean) * inv);
}

// ---------------- view weight prep ----------------
__global__ void wprep_kernel(const float* __restrict__ aqw, const float* __restrict__ aqb,
                             const float* __restrict__ n3g, const float* __restrict__ n3b)
{
    int vj = blockIdx.x;
    int v = vj / 36;
    int tid = threadIdx.x;
    __shared__ float red[256];
    const float* w = aqw + (size_t)vj * Cn;
    const float* gg = n3g + (size_t)v * Cn;
    const float* bb = n3b + (size_t)v * Cn;
    float s = 0.f;
    for (int c = tid; c < Cn; c += 256) {
        float wv = w[c];
        g_weff[(size_t)vj * Cn + c] = tf32r(wv * gg[c]);
        s += wv * bb[c];
    }
    s = blockReduceSum256(s, red);
    if (tid == 0) g_beff[vj] = aqb[vj] + s;
}

// ---------------- cluster (3d) pooling chain ----------------
__global__ void pool_init(int R)
{
    int i = blockIdx.x * blockDim.x + threadIdx.x;
    if (i <= R) g_hist[i] = 0;
    if (i < Cn) { g_colsum[i] = 0.0; g_colsq[i] = 0.0; }
}
__global__ void hist_count(const int* __restrict__ idx)
{
    int i = blockIdx.x * blockDim.x + threadIdx.x;
    if (i < BG) atomicAdd(&g_hist[idx[i]], 1);
}
__global__ void scan_kernel(int R)
{
    __shared__ int part[1024];
    int tid = threadIdx.x;
    int chunk = (R + 1023) / 1024;
    int t0 = tid * chunk;
    int s = 0;
    for (int j = 0; j < chunk; j++)
        if (t0 + j < R) s += g_hist[t0 + j];
    part[tid] = s;
    __syncthreads();
    for (int off = 1; off < 1024; off <<= 1) {
        int v = (tid >= off) ? part[tid - off] : 0;
        __syncthreads();
        part[tid] += v;
        __syncthreads();
    }
    int run = (tid > 0) ? part[tid - 1] : 0;
    for (int j = 0; j < chunk; j++) {
        if (t0 + j < R) {
            int c = g_hist[t0 + j];
            g_off[t0 + j] = run;
            g_cur[t0 + j] = run;
            run += c;
        }
    }
    if (tid == 1023) g_off[R] = part[1023];
}
__global__ void seg_place(const int* __restrict__ idx)
{
    int i = blockIdx.x * blockDim.x + threadIdx.x;
    if (i >= BG) return;
    int p = atomicAdd(&g_cur[idx[i]], 1);
    g_ord[p] = i;
}
__global__ void seg_reduce(const float* __restrict__ src)
{
    int r = blockIdx.x;
    int tid = threadIdx.x;
    int s0 = g_off[r], s1 = g_off[r + 1];
    float mx0 = -1e30f, mx1 = -1e30f, mx2 = -1e30f;
    float sm0 = 0.f, sm1 = 0.f, sm2 = 0.f;
    for (int j = s0; j < s1; j++) {
        int i = g_ord[j];
        const float* p = src + (size_t)featRow(i) * Cn;
        float v0 = p[tid], v1 = p[tid + 256], v2 = p[tid + 512];
        mx0 = fmaxf(mx0, v0); sm0 += v0;
        mx1 = fmaxf(mx1, v1); sm1 += v1;
        mx2 = fmaxf(mx2, v2); sm2 += v2;
    }
    int cnt = s1 - s0;
    float inv = 1.f / (float)(cnt > 0 ? cnt : 1);
    float* op = g_scomb + (size_t)r * Cn;
    op[tid]       = (cnt > 0 ? mx0 : 0.f) + sm0 * inv;
    op[tid + 256] = (cnt > 0 ? mx1 : 0.f) + sm1 * inv;
    op[tid + 512] = (cnt > 0 ? mx2 : 0.f) + sm2 * inv;
}
__global__ void colstats(int R)
{
    int col = blockIdx.x * blockDim.x + threadIdx.x;
    if (col >= Cn) return;
    int chunk = (R + gridDim.y - 1) / gridDim.y;
    int r0 = blockIdx.y * chunk;
    int r1 = min(r0 + chunk, R);
    float sum = 0.f, sq = 0.f;
    for (int r = r0; r < r1; r++) {
        float v = g_scomb[(size_t)r * Cn + col];
        sum += v; sq += v * v;
    }
    atomicAdd(&g_colsum[col], (double)sum);
    atomicAdd(&g_colsq[col], (double)sq);
}
__global__ void colfinal(int R)
{
    int col = blockIdx.x * blockDim.x + threadIdx.x;
    if (col >= Cn) return;
    double mean = g_colsum[col] / R;
    double var = g_colsq[col] / R - mean * mean;
    if (var < 0.0) var = 0.0;
    g_mean[col] = (float)mean;
    g_rstd[col] = rsqrtf((float)var + EPSf);
}
__global__ void bn_apply(const float* __restrict__ gam, const float* __restrict__ bet,
                         float* __restrict__ out, int R)
{
    int i = blockIdx.x * blockDim.x + threadIdx.x;
    if (i >= R * Cn) return;
    int col = i % Cn;
    float v = (g_scomb[i] - g_mean[col]) * g_rstd[col] * gam[col] + bet[col];
    out[i] = gelu_exact(v);
}

// ---------------- batched (x6 views) pooling chain ----------------
__global__ void pool_init6()
{
    int v = blockIdx.y;
    int i = blockIdx.x * blockDim.x + threadIdx.x;
    if (i <= D1n) g_hist6[v * (D1n + 1) + i] = 0;
    if (i < Cn) { g_colsum6[v * Cn + i] = 0.0; g_colsq6[v * Cn + i] = 0.0; }
}
__global__ void hist_count6(const int* __restrict__ fgi)
{
    int v = blockIdx.y;
    int i = blockIdx.x * blockDim.x + threadIdx.x;
    if (i < BG) atomicAdd(&g_hist6[v * (D1n + 1) + fgi[(size_t)v * BG + i]], 1);
}
__global__ void scan6()
{
    int v = blockIdx.x;
    int* hist = g_hist6 + v * (D1n + 1);
    int* off  = g_off6  + v * (D1n + 1);
    int* cur  = g_cur6  + v * (D1n + 1);
    __shared__ int part[1024];
    int tid = threadIdx.x;
    const int R = D1n;
    int chunk = (R + 1023) / 1024;
    int t0 = tid * chunk;
    int s = 0;
    for (int j = 0; j < chunk; j++)
        if (t0 + j < R) s += hist[t0 + j];
    part[tid] = s;
    __syncthreads();
    for (int off2 = 1; off2 < 1024; off2 <<= 1) {
        int vv = (tid >= off2) ? part[tid - off2] : 0;
        __syncthreads();
        part[tid] += vv;
        __syncthreads();
    }
    int run = (tid > 0) ? part[tid - 1] : 0;
    for (int j = 0; j < chunk; j++) {
        if (t0 + j < R) {
            int c = hist[t0 + j];
            off[t0 + j] = run;
            cur[t0 + j] = run;
            run += c;
        }
    }
    if (tid == 1023) off[R] = part[1023];
}
__global__ void seg_place6(const int* __restrict__ fgi)
{
    int v = blockIdx.y;
    int i = blockIdx.x * blockDim.x + threadIdx.x;
    if (i >= BG) return;
    int p = atomicAdd(&g_cur6[v * (D1n + 1) + fgi[(size_t)v * BG + i]], 1);
    g_ord6[(size_t)v * BG + p] = i;
}
__global__ void view_attn6(const float* __restrict__ qkv1, const unsigned char* __restrict__ mask)
{
    int blk = blockIdx.x, h = blockIdx.y, v = blockIdx.z;
    int t = threadIdx.x;
    __shared__ float kk[N1n][2];
    __shared__ float vv[N1n][2];
    int row = blk * N1n + t;
    const float* base = qkv1 + (size_t)row * NQ1 + v * 36;
    float q0 = base[h * 2]     * 0.28867513459481287f;
    float q1 = base[h * 2 + 1] * 0.28867513459481287f;
    kk[t][0] = base[12 + h * 2]; kk[t][1] = base[13 + h * 2];
    vv[t][0] = base[24 + h * 2]; vv[t][1] = base[25 + h * 2];
    __syncthreads();
    const unsigned char* mrow = mask + (size_t)v * NB1 * N1n * N1n + ((size_t)blk * N1n + t) * N1n;
    float mmax = -1e30f;
    #pragma unroll 4
    for (int j = 0; j < N1n; j++) {
        float s = q0 * kk[j][0] + q1 * kk[j][1] + (mrow[j] ? -100000.f : 0.f);
        mmax = fmaxf(mmax, s);
    }
    float l = 0.f, a0 = 0.f, a1 = 0.f;
    #pragma unroll 4
    for (int j = 0; j < N1n; j++) {
        float s = q0 * kk[j][0] + q1 * kk[j][1] + (mrow[j] ? -100000.f : 0.f);
        float p = expf(s - mmax);
        l += p; a0 += p * vv[j][0]; a1 += p * vv[j][1];
    }
    float* o1 = g_o16 + (size_t)v * BG * MIDn;
    o1[(size_t)row * MIDn + h * 2]     = a0 / l;
    o1[(size_t)row * MIDn + h * 2 + 1] = a1 / l;
}
__global__ void seg_reduce_view6(const float* __restrict__ apw, const float* __restrict__ apb,
                                 const float* __restrict__ x2)
{
    int r = blockIdx.x, v = blockIdx.y;
    int tid = threadIdx.x;
    const int* off = g_off6 + v * (D1n + 1);
    const int* ord = g_ord6 + (size_t)v * BG;
    const float* o1 = g_o16 + (size_t)v * BG * MIDn;
    const float* pw = apw + (size_t)v * Cn * MIDn;
    const float* pb = apb + (size_t)v * Cn;
    int s0 = off[r], s1 = off[r + 1];
    float wr[3][MIDn], pbv[3];
    #pragma unroll
    for (int ch = 0; ch < 3; ch++) {
        int c = tid + ch * 256;
        pbv[ch] = pb[c];
        #pragma unroll
        for (int k = 0; k < MIDn; k++) wr[ch][k] = __ldg(&pw[(size_t)c * MIDn + k]);
    }
    float mx[3] = {-1e30f, -1e30f, -1e30f};
    float sm[3] = {0.f, 0.f, 0.f};
    for (int j = s0; j < s1; j++) {
        int i = ord[j];
        const float4* ob = (const float4*)&o1[(size_t)i * MIDn];
        float4 o0 = __ldg(ob), o1v = __ldg(ob + 1), o2 = __ldg(ob + 2);
        float os[MIDn] = {o0.x, o0.y, o0.z, o0.w, o1v.x, o1v.y, o1v.z, o1v.w,
                          o2.x, o2.y, o2.z, o2.w};
        const float* xp = x2 + (size_t)featRow(i) * Cn;
        #pragma unroll
        for (int ch = 0; ch < 3; ch++) {
            float vv = pbv[ch] + xp[tid + ch * 256];
            #pragma unroll
            for (int k = 0; k < MIDn; k++) vv += os[k] * wr[ch][k];
            mx[ch] = fmaxf(mx[ch], vv);
            sm[ch] += vv;
        }
    }
    int cnt = s1 - s0;
    float inv = 1.f / (float)(cnt > 0 ? cnt : 1);
    float* op = g_scomb6 + ((size_t)v * D1n + r) * Cn;
    #pragma unroll
    for (int ch = 0; ch < 3; ch++)
        op[tid + ch * 256] = (cnt > 0 ? mx[ch] : 0.f) + sm[ch] * inv;
}
__global__ void colstats6()
{
    int col = blockIdx.x * blockDim.x + threadIdx.x;
    int v = blockIdx.z;
    if (col >= Cn) return;
    const int R = D1n;
    int chunk = (R + gridDim.y - 1) / gridDim.y;
    int r0 = blockIdx.y * chunk;
    int r1 = min(r0 + chunk, R);
    float sum = 0.f, sq = 0.f;
    const float* sc = g_scomb6 + (size_t)v * D1n * Cn;
    for (int r = r0; r < r1; r++) {
        float vv = sc[(size_t)r * Cn + col];
        sum += vv; sq += vv * vv;
    }
    atomicAdd(&g_colsum6[v * Cn + col], (double)sum);
    atomicAdd(&g_colsq6[v * Cn + col], (double)sq);
}
__global__ void colfinal6()
{
    int col = blockIdx.x * blockDim.x + threadIdx.x;
    int v = blockIdx.y;
    if (col >= Cn) return;
    double mean = g_colsum6[v * Cn + col] / D1n;
    double var = g_colsq6[v * Cn + col] / D1n - mean * mean;
    if (var < 0.0) var = 0.0;
    g_mean6[v * Cn + col] = (float)mean;
    g_rstd6[v * Cn + col] = rsqrtf((float)var + EPSf);
}
__global__ void bn_apply6(const float* __restrict__ bn1dg, const float* __restrict__ bn1db,
                          float* __restrict__ bview)
{
    int v = blockIdx.y;
    int i = blockIdx.x * blockDim.x + threadIdx.x;
    if (i >= D1n * Cn) return;
    int col = i % Cn;
    float vv = (g_scomb6[(size_t)v * D1n * Cn + i] - g_mean6[v * Cn + col]) * g_rstd6[v * Cn + col]
               * bn1dg[v * Cn + col] + bn1db[v * Cn + col];
    bview[(size_t)v * D1n * Cn + i] = gelu_exact(vv);
}

// ---------------- final fusion ----------------
__global__ void final_kernel(const float* __restrict__ x2, const float* __restrict__ g3,
                             const float* __restrict__ bview, const int* __restrict__ cluster,
                             const int* __restrict__ fgi, float* __restrict__ out)
{
    int i = blockIdx.x;
    int tid = threadIdx.x;
    size_t xrow = (size_t)featRow(i);
    __shared__ float x3[Cn];
    __shared__ float pv[NV][Cn];
    __shared__ float red[256];
    __shared__ float sims[NV];
    int cl = cluster[i];
    const float* x3p = g3 + (size_t)cl * Cn;
    for (int c = tid; c < Cn; c += 256) x3[c] = x3p[c];
    for (int v = 0; v < NV; v++) {
        int id = fgi[(size_t)v * BG + i];
        const float* pp = bview + ((size_t)v * D1n + id) * Cn;
        for (int c = tid; c < Cn; c += 256) pv[v][c] = pp[c];
    }
    __syncthreads();
    float p = 0.f;
    for (int c = tid; c < Cn; c += 256) p += x3[c] * x3[c];
    float nx3 = fmaxf(sqrtf(blockReduceSum256(p, red)), 1e-8f);
    for (int v = 0; v < NV; v++) {
        float d = 0.f, n = 0.f;
        for (int c = tid; c < Cn; c += 256) {
            float a = pv[v][c];
            d += a * x3[c]; n += a * a;
        }
        d = blockReduceSum256(d, red);
        n = blockReduceSum256(n, red);
        if (tid == 0) {
            float np = fmaxf(sqrtf(n), 1e-8f);
            float cs = d / (np * nx3);
            sims[v] = (cs + 1.f) * 0.5f;
        }
        __syncthreads();
    }
    float ssum = 0.f;
    #pragma unroll
    for (int v = 0; v < NV; v++) ssum += sims[v];
    float inv = 1.f / ssum;
    const float* x2p = x2 + xrow * Cn;
    float* op = out + xrow * Cn;
    for (int c = tid; c < Cn; c += 256) {
        float sup = 0.f;
        #pragma unroll
        for (int v = 0; v < NV; v++) sup += pv[v][c] * sims[v];
        op[c] = x2p[c] + 0.3f * sup * inv;
    }
}

__global__ void cls_copy(const float* __restrict__ x2, float* __restrict__ out)
{
    size_t row = (size_t)blockIdx.x * Tn;
    for (int c = threadIdx.x; c < Cn; c += blockDim.x)
        out[row * Cn + c] = x2[row * Cn + c];
}

// ---------------- host launch ----------------
extern "C" void kernel_launch(void* const* d_in, const int* in_sizes, int n_in,
                              void* d_out, int out_size)
{
    const float* x    = (const float*)d_in[0];
    const float* ln1g = (const float*)d_in[1];
    const float* ln1b = (const float*)d_in[2];
    const float* ln2g = (const float*)d_in[3];
    const float* ln2b = (const float*)d_in[4];
    const float* Wqkv = (const float*)d_in[5];
    const float* bqkv = (const float*)d_in[6];
    const float* Wo   = (const float*)d_in[7];
    const float* bo   = (const float*)d_in[8];
    const float* Wfc  = (const float*)d_in[9];
    const float* bfc  = (const float*)d_in[10];
    const float* Wproj= (const float*)d_in[11];
    const float* bproj= (const float*)d_in[12];
    const float* Wa1  = (const float*)d_in[13];
    const float* ba1  = (const float*)d_in[14];
    const float* Wa2  = (const float*)d_in[15];
    const float* ba2  = (const float*)d_in[16];
    const float* bn3dg= (const float*)d_in[17];
    const float* bn3db= (const float*)d_in[18];
    const float* bn1dg= (const float*)d_in[19];
    const float* bn1db= (const float*)d_in[20];
    const float* n3g  = (const float*)d_in[21];
    const float* n3b  = (const float*)d_in[22];
    const float* aqw  = (const float*)d_in[23];
    const float* aqb  = (const float*)d_in[24];
    const float* apw  = (const float*)d_in[25];
    const float* apb  = (const float*)d_in[26];
    const int*   cluster = (const int*)d_in[27];
    const int*   fgi  = (const int*)d_in[28];
    const unsigned char* mask = (const unsigned char*)d_in[29];
    float* out = (float*)d_out;

    float *y, *qkv, *att, *x1, *hfc, *xffn, *x2, *g3, *bview, *z, *qkv1, *weff, *beff;
    cudaGetSymbolAddress((void**)&y,     g_y);
    cudaGetSymbolAddress((void**)&qkv,   g_qkv);
    cudaGetSymbolAddress((void**)&att,   g_att);
    cudaGetSymbolAddress((void**)&x1,    g_x1);
    cudaGetSymbolAddress((void**)&hfc,   g_hfc);
    cudaGetSymbolAddress((void**)&xffn,  g_xffn);
    cudaGetSymbolAddress((void**)&x2,    g_x2);
    cudaGetSymbolAddress((void**)&g3,    g_g3);
    cudaGetSymbolAddress((void**)&bview, g_bview);
    cudaGetSymbolAddress((void**)&z,     g_z);
    cudaGetSymbolAddress((void**)&qkv1,  g_qkv1);
    cudaGetSymbolAddress((void**)&weff,  g_weff);
    cudaGetSymbolAddress((void**)&beff,  g_beff);

    cudaFuncSetAttribute(attn_tc, cudaFuncAttributeMaxDynamicSharedMemorySize, ATTN_SMEM);
    cudaFuncSetAttribute(gemm_tf32<0>, cudaFuncAttributeMaxDynamicSharedMemorySize, GEMM_SMEM);
    cudaFuncSetAttribute(gemm_tf32<1>, cudaFuncAttributeMaxDynamicSharedMemorySize, GEMM_SMEM);
    cudaFuncSetAttribute(gemm_tf32<2>, cudaFuncAttributeMaxDynamicSharedMemorySize, GEMM_SMEM);

    const int GMB = (MROWS + 127) / 128;  // 129

    // 1) LN1 -> y (tf32-rounded)
    ln_kernel<<<MROWS, 256>>>(x, ln1g, ln1b, y, 0);
    // 2) QKV GEMM (weights direct; HW truncation)
    gemm_tf32<0><<<dim3(GMB, (3 * Cn) / 128), 256, GEMM_SMEM>>>(y, Wqkv, bqkv, nullptr, qkv, MROWS, 3 * Cn, Cn);
    // 3) attention + tail
    attn_tc<<<dim3(4, Hn, Bn), 256, ATTN_SMEM>>>(qkv, att);
    attn_tail<<<dim3(Hn, Bn), 256>>>(qkv, att);
    // 4) output proj + residual
    gemm_tf32<2><<<dim3(GMB, Cn / 128), 256, GEMM_SMEM>>>(att, Wo, bo, x, x1, MROWS, Cn, Cn);
    // 5) LN2 -> y
    ln_kernel<<<MROWS, 256>>>(x1, ln2g, ln2b, y, 0);
    // 6) FC + quick_gelu
    gemm_tf32<1><<<dim3(GMB, FFn / 128), 256, GEMM_SMEM>>>(y, Wfc, bfc, nullptr, hfc, MROWS, FFn, Cn);
    // 7) proj
    gemm_tf32<0><<<dim3(GMB, Cn / 128), 256, GEMM_SMEM>>>(hfc, Wproj, bproj, nullptr, xffn, MROWS, Cn, FFn);
    // 8) adapter + residuals -> x2, fused plain LN -> z
    adapter_kernel<<<MROWS, 256>>>(xffn, x1, Wa1, ba1, Wa2, ba2, x2, z);

    // 9) 3d segment pool + BN over clusters
    {
        pool_init<<<(NCL + 1 + 255) / 256, 256>>>(NCL);
        hist_count<<<(BG + 255) / 256, 256>>>(cluster);
        scan_kernel<<<1, 1024>>>(NCL);
        seg_place<<<(BG + 255) / 256, 256>>>(cluster);
        seg_reduce<<<NCL, 256>>>(x2);
        colstats<<<dim3(3, 16), 256>>>(NCL);
        colfinal<<<3, 256>>>(NCL);
        bn_apply<<<(NCL * Cn + 255) / 256, 256>>>(bn3dg, bn3db, g3, NCL);
    }

    // 10) view branches (batched; z produced by adapter)
    wprep_kernel<<<NQ1, 256>>>(aqw, aqb, n3g, n3b);
    gemm_tf32<0><<<dim3(BG / 128, (NQ1 + 127) / 128), 256, GEMM_SMEM>>>(z, weff, beff, nullptr, qkv1,
                                                                        BG, NQ1, Cn);
    view_attn6<<<dim3(NB1, H1n, NV), N1n>>>(qkv1, mask);
    pool_init6<<<dim3((D1n + 1 + 255) / 256, NV), 256>>>();
    hist_count6<<<dim3((BG + 255) / 256, NV), 256>>>(fgi);
    scan6<<<NV, 1024>>>();
    seg_place6<<<dim3((BG + 255) / 256, NV), 256>>>(fgi);
    seg_reduce_view6<<<dim3(D1n, NV), 256>>>(apw, apb, x2);
    colstats6<<<dim3(3, 16, NV), 256>>>();
    colfinal6<<<dim3(3, NV), 256>>>();
    bn_apply6<<<dim3((D1n * Cn + 255) / 256, NV), 256>>>(bn1dg, bn1db, bview);

    // 11) cossim fusion + output
    final_kernel<<<BG, 256>>>(x2, g3, bview, cluster, fgi, out);
    cls_copy<<<Bn, 256>>>(x2, out);
}

// round 14
// speedup vs baseline: 1.1773x; 1.0055x over previous
#include <cuda_runtime.h>
#include <cuda_bf16.h>
#include <math.h>
#include <stdint.h>

// ---------------- problem constants ----------------
#define Bn    32
#define Gn    512
#define Cn    768
#define Hn    12
#define HD    64
#define Tn    513              // G+1
#define MROWS (Bn*Tn)          // 16416
#define BG    16384
#define FFn   3072
#define ADn   16
#define MIDn  12
#define H1n   6
#define N1n   128
#define NB1   (BG/N1n)         // 128
#define NCL   2048
#define D1n   6272
#define NV    6
#define NQ1   (NV*3*MIDn)      // 216
#define EPSf  1e-5f

// ---------------- scratch (device globals; no allocation) ----------------
__device__ float  g_y   [MROWS*Cn];
__device__ float  g_qkv [MROWS*3*Cn];
__device__ float  g_att [MROWS*Cn];
__device__ float  g_x1  [MROWS*Cn];
__device__ float  g_hfc [MROWS*FFn];
__device__ float  g_xffn[MROWS*Cn];
__device__ float  g_x2  [MROWS*Cn];
__device__ float  g_g3   [NCL*Cn];
__device__ float  g_bview[NV*D1n*Cn];
__device__ float  g_z    [BG*Cn];          // nhat (un-affined LN of feat)
__device__ float  g_qkv1 [BG*NQ1];
__device__ float  g_weff [NQ1*Cn];
__device__ float  g_beff [NQ1];
// cluster (3d) pooling buffers
__device__ float  g_scomb [NCL*Cn];
__device__ double g_colsum[Cn];
__device__ double g_colsq [Cn];
__device__ float  g_mean[Cn];
__device__ float  g_rstd[Cn];
__device__ int    g_hist[NCL+1];
__device__ int    g_off [NCL+1];
__device__ int    g_cur [NCL+1];
__device__ int    g_ord [BG];
// batched view pooling buffers
__device__ int    g_hist6[NV*(D1n+1)];
__device__ int    g_off6 [NV*(D1n+1)];
__device__ int    g_cur6 [NV*(D1n+1)];
__device__ int    g_ord6 [NV*BG];
__device__ float  g_scomb6[(size_t)NV*D1n*Cn];
__device__ double g_colsum6[NV*Cn];
__device__ double g_colsq6 [NV*Cn];
__device__ float  g_mean6[NV*Cn];
__device__ float  g_rstd6[NV*Cn];
__device__ float  g_o16  [NV*BG*MIDn];

// ---------------- helpers ----------------
__device__ __forceinline__ float blockReduceSum256(float v, float* red) {
    int tid = threadIdx.x;
    red[tid] = v; __syncthreads();
    #pragma unroll
    for (int o = 128; o > 0; o >>= 1) {
        if (tid < o) red[tid] += red[tid + o];
        __syncthreads();
    }
    float r = red[0];
    __syncthreads();
    return r;
}
__device__ __forceinline__ float blockReduceMax256(float v, float* red) {
    int tid = threadIdx.x;
    red[tid] = v; __syncthreads();
    #pragma unroll
    for (int o = 128; o > 0; o >>= 1) {
        if (tid < o) red[tid] = fmaxf(red[tid], red[tid + o]);
        __syncthreads();
    }
    float r = red[0];
    __syncthreads();
    return r;
}
__device__ __forceinline__ float quick_gelu(float x) {
    return x / (1.f + expf(-1.702f * x));
}
__device__ __forceinline__ float gelu_exact(float x) {
    return 0.5f * x * (1.f + erff(x * 0.70710678118654752f));
}
__device__ __forceinline__ int featRow(int i) {
    return (i >> 9) * Tn + 1 + (i & 511);
}
__device__ __forceinline__ float tf32r(float f) {
    uint32_t u;
    asm volatile("cvt.rna.tf32.f32 %0, %1;" : "=r"(u) : "f"(f));
    return __uint_as_float(u);
}

// ---------------- LayerNorm (tf32-rounded out) ----------------
__global__ void ln_kernel(const float* __restrict__ in, const float* __restrict__ g,
                          const float* __restrict__ b, float* __restrict__ out, int featmode)
{
    int r = blockIdx.x;
    int row = featmode ? featRow(r) : r;
    const float* x = in + (size_t)row * Cn;
    __shared__ float xs[Cn];
    __shared__ float red[256];
    int tid = threadIdx.x;
    float s0 = 0.f;
    for (int c = tid; c < Cn; c += 256) { float v = x[c]; xs[c] = v; s0 += v; }
    float mean = blockReduceSum256(s0, red) * (1.f / Cn);
    float s1 = 0.f;
    for (int c = tid; c < Cn; c += 256) { float d = xs[c] - mean; s1 += d * d; }
    float var = blockReduceSum256(s1, red) * (1.f / Cn);
    float inv = rsqrtf(var + EPSf);
    float* op = out + (size_t)r * Cn;
    for (int c = tid; c < Cn; c += 256)
        op[c] = tf32r((xs[c] - mean) * inv * g[c] + b[c]);
}

// ---------------- mma.sync tf32 NT GEMM, 3-stage cp.async pipeline (proven R4/R6) ----------------
#define GEMM_SMEM (3 * 2 * 128 * 20 * 4)   // 61440 bytes
template <int EPI>
__global__ void __launch_bounds__(256, 2) gemm_tf32(
    const float* __restrict__ A, const float* __restrict__ W,
    const float* __restrict__ bias, const float* __restrict__ res,
    float* __restrict__ C, int M, int N, int K)
{
    extern __shared__ float sm_[];
    int tid = threadIdx.x;
    int bm = blockIdx.x * 128, bn = blockIdx.y * 128;
    int lane = tid & 31, wid = tid >> 5;
    int wm = (wid & 1) * 64, wn = (wid >> 1) * 32;
    int gid = lane >> 2, tg = lane & 3;

    float acc[4][4][4];
    #pragma unroll
    for (int a = 0; a < 4; a++)
        #pragma unroll
        for (int b = 0; b < 4; b++)
            #pragma unroll
            for (int c = 0; c < 4; c++) acc[a][b][c] = 0.f;

    auto prefetch = [&](int kt, int s) {
        int k0 = kt * 16;
        float* As = sm_ + s * 2560;
        float* Bs = sm_ + 7680 + s * 2560;
        #pragma unroll
        for (int i = 0; i < 2; i++) {
            int r = (tid >> 2) + i * 64;
            int c = (tid & 3) * 4;
            int arow = bm + r;
            const float* asrc = A + (size_t)(arow < M ? arow : 0) * K + k0 + c;
            uint32_t adst = (uint32_t)__cvta_generic_to_shared(&As[r * 20 + c]);
            int asz = (arow < M) ? 16 : 0;
            asm volatile("cp.async.cg.shared.global [%0], [%1], 16, %2;\n"
                         :: "r"(adst), "l"(asrc), "r"(asz));
            int brow = bn + r;
            const float* bsrc = W + (size_t)(brow < N ? brow : 0) * K + k0 + c;
            uint32_t bdst = (uint32_t)__cvta_generic_to_shared(&Bs[r * 20 + c]);
            int bsz = (brow < N) ? 16 : 0;
            asm volatile("cp.async.cg.shared.global [%0], [%1], 16, %2;\n"
                         :: "r"(bdst), "l"(bsrc), "r"(bsz));
        }
    };

    int nt = K / 16;
    prefetch(0, 0);
    asm volatile("cp.async.commit_group;\n");
    if (nt > 1) prefetch(1, 1);
    asm volatile("cp.async.commit_group;\n");

    int buf = 0;
    for (int t = 0; t < nt; t++) {
        asm volatile("cp.async.wait_group 1;\n");
        __syncthreads();
        if (t + 2 < nt) prefetch(t + 2, (buf + 2) % 3);
        asm volatile("cp.async.commit_group;\n");
        const float* As = sm_ + buf * 2560;
        const float* Bs = sm_ + 7680 + buf * 2560;
        #pragma unroll
        for (int kk = 0; kk < 2; kk++) {
            int kb = kk * 8;
            uint32_t af[4][4], bf[4][2];
            #pragma unroll
            for (int mi = 0; mi < 4; mi++) {
                int r = wm + mi * 16 + gid;
                af[mi][0] = __float_as_uint(As[(r    ) * 20 + kb + tg    ]);
                af[mi][1] = __float_as_uint(As[(r + 8) * 20 + kb + tg    ]);
                af[mi][2] = __float_as_uint(As[(r    ) * 20 + kb + tg + 4]);
                af[mi][3] = __float_as_uint(As[(r + 8) * 20 + kb + tg + 4]);
            }
            #pragma unroll
            for (int ni = 0; ni < 4; ni++) {
                int n0 = wn + ni * 8 + gid;
                bf[ni][0] = __float_as_uint(Bs[n0 * 20 + kb + tg    ]);
                bf[ni][1] = __float_as_uint(Bs[n0 * 20 + kb + tg + 4]);
            }
            #pragma unroll
            for (int mi = 0; mi < 4; mi++)
                #pragma unroll
                for (int ni = 0; ni < 4; ni++)
                    asm volatile(
                        "mma.sync.aligned.m16n8k8.row.col.f32.tf32.tf32.f32 "
                        "{%0,%1,%2,%3}, {%4,%5,%6,%7}, {%8,%9}, {%0,%1,%2,%3};\n"
                        : "+f"(acc[mi][ni][0]), "+f"(acc[mi][ni][1]),
                          "+f"(acc[mi][ni][2]), "+f"(acc[mi][ni][3])
                        : "r"(af[mi][0]), "r"(af[mi][1]), "r"(af[mi][2]), "r"(af[mi][3]),
                          "r"(bf[ni][0]), "r"(bf[ni][1]));
        }
        __syncthreads();
        buf = (buf + 1) % 3;
    }

    #pragma unroll
    for (int mi = 0; mi < 4; mi++) {
        #pragma unroll
        for (int ni = 0; ni < 4; ni++) {
            int m0 = bm + wm + mi * 16 + gid;
            int n0 = bn + wn + ni * 8 + tg * 2;
            if (n0 >= N) continue;
            float b0 = bias[n0], b1 = bias[n0 + 1];
            #pragma unroll
            for (int hh = 0; hh < 2; hh++) {
                int m = m0 + hh * 8;
                if (m >= M) continue;
                float v0 = acc[mi][ni][hh * 2 + 0] + b0;
                float v1 = acc[mi][ni][hh * 2 + 1] + b1;
                if (EPI == 1) { v0 = tf32r(quick_gelu(v0)); v1 = tf32r(quick_gelu(v1)); }
                if (EPI == 2) {
                    float2 rr = *(const float2*)&res[(size_t)m * N + n0];
                    v0 += rr.x; v1 += rr.y;
                }
                float2 vv; vv.x = v0; vv.y = v1;
                *(float2*)&C[(size_t)m * N + n0] = vv;
            }
        }
    }
}

// ---------------- tensor-core flash attention (proven R6 version) ----------------
#define ATTN_SMEM ((128 + 64 + 64) * 68 * 4)
__global__ void __launch_bounds__(256) attn_tc(const float* __restrict__ qkv,
                                               float* __restrict__ out)
{
    extern __shared__ float sm[];
    float* Qs = sm;
    float* Ks = sm + 128 * 68;
    float* Vt = sm + 192 * 68;

    int qb = blockIdx.x, h = blockIdx.y, b = blockIdx.z;
    int tid = threadIdx.x, lane = tid & 31, wid = tid >> 5;
    int gid = lane >> 2, tg = lane & 3;
    int wm = wid * 16;
    int qbase = qb * 128;

    {
        int r = tid >> 1, c0 = (tid & 1) * 32;
        int t = qbase + r;
        bool valid = (t < Tn);
        const float* qp = qkv + (size_t)(b * Tn + (valid ? t : 0)) * (3 * Cn) + h * HD + c0;
        #pragma unroll
        for (int i = 0; i < 8; i++) {
            float4 v = *(const float4*)(qp + i * 4);
            float4 w;
            w.x = valid ? tf32r(v.x * 0.125f) : 0.f;
            w.y = valid ? tf32r(v.y * 0.125f) : 0.f;
            w.z = valid ? tf32r(v.z * 0.125f) : 0.f;
            w.w = valid ? tf32r(v.w * 0.125f) : 0.f;
            *(float4*)&Qs[r * 68 + c0 + i * 4] = w;
        }
    }

    float m0 = -1e30f, m1 = -1e30f, l0 = 0.f, l1 = 0.f;
    float o[8][4];
    #pragma unroll
    for (int ni = 0; ni < 8; ni++)
        #pragma unroll
        for (int j = 0; j < 4; j++) o[ni][j] = 0.f;

    for (int kb = 0; kb < 9; kb++) {
        int kbase = kb * 64;
        __syncthreads();
        {
            int r = tid >> 2, c0 = (tid & 3) * 16;
            int t = kbase + r;
            bool valid = (t < Tn);
            const float* kp = qkv + (size_t)(b * Tn + (valid ? t : 0)) * (3 * Cn) + Cn + h * HD + c0;
            const float* vp = kp + Cn;
            int low = r & 7;
            int pr = (r & ~7) | (((low & 3) << 1) | (low >> 2));
            #pragma unroll
            for (int i = 0; i < 16; i += 4) {
                float4 kv4 = *(const float4*)(kp + i);
                float4 w;
                w.x = valid ? tf32r(kv4.x) : 0.f;
                w.y = valid ? tf32r(kv4.y) : 0.f;
                w.z = valid ? tf32r(kv4.z) : 0.f;
                w.w = valid ? tf32r(kv4.w) : 0.f;
                *(float4*)&Ks[pr * 68 + c0 + i] = w;
            }
            #pragma unroll
            for (int i = 0; i < 16; i++)
                Vt[(c0 + i) * 68 + r] = valid ? tf32r(vp[i]) : 0.f;
        }
        __syncthreads();

        float s[8][4];
        #pragma unroll
        for (int ni = 0; ni < 8; ni++)
            #pragma unroll
            for (int j = 0; j < 4; j++) s[ni][j] = 0.f;
        #pragma unroll
        for (int ks = 0; ks < 8; ks++) {
            int k8 = ks * 8;
            uint32_t af[4];
            int r = wm + gid;
            af[0] = __float_as_uint(Qs[(r    ) * 68 + k8 + tg    ]);
            af[1] = __float_as_uint(Qs[(r + 8) * 68 + k8 + tg    ]);
            af[2] = __float_as_uint(Qs[(r    ) * 68 + k8 + tg + 4]);
            af[3] = __float_as_uint(Qs[(r + 8) * 68 + k8 + tg + 4]);
            #pragma unroll
            for (int ni = 0; ni < 8; ni++) {
                uint32_t b0 = __float_as_uint(Ks[(ni * 8 + gid) * 68 + k8 + tg    ]);
                uint32_t b1 = __float_as_uint(Ks[(ni * 8 + gid) * 68 + k8 + tg + 4]);
                asm volatile(
                    "mma.sync.aligned.m16n8k8.row.col.f32.tf32.tf32.f32 "
                    "{%0,%1,%2,%3}, {%4,%5,%6,%7}, {%8,%9}, {%0,%1,%2,%3};\n"
                    : "+f"(s[ni][0]), "+f"(s[ni][1]), "+f"(s[ni][2]), "+f"(s[ni][3])
                    : "r"(af[0]), "r"(af[1]), "r"(af[2]), "r"(af[3]),
                      "r"(b0), "r"(b1));
            }
        }

        float vmax0 = -1e30f, vmax1 = -1e30f;
        #pragma unroll
        for (int ni = 0; ni < 8; ni++) {
            if (kbase + ni * 8 + tg >= Tn)     { s[ni][0] = -1e30f; s[ni][2] = -1e30f; }
            if (kbase + ni * 8 + tg + 4 >= Tn) { s[ni][1] = -1e30f; s[ni][3] = -1e30f; }
            vmax0 = fmaxf(vmax0, fmaxf(s[ni][0], s[ni][1]));
            vmax1 = fmaxf(vmax1, fmaxf(s[ni][2], s[ni][3]));
        }
        vmax0 = fmaxf(vmax0, __shfl_xor_sync(0xffffffffu, vmax0, 1));
        vmax0 = fmaxf(vmax0, __shfl_xor_sync(0xffffffffu, vmax0, 2));
        vmax1 = fmaxf(vmax1, __shfl_xor_sync(0xffffffffu, vmax1, 1));
        vmax1 = fmaxf(vmax1, __shfl_xor_sync(0xffffffffu, vmax1, 2));
        float mn0 = fmaxf(m0, vmax0), mn1 = fmaxf(m1, vmax1);
        float sc0 = expf(m0 - mn0), sc1 = expf(m1 - mn1);
        float rs0 = 0.f, rs1 = 0.f;
        #pragma unroll
        for (int ni = 0; ni < 8; ni++) {
            s[ni][0] = expf(s[ni][0] - mn0); rs0 += s[ni][0];
            s[ni][1] = expf(s[ni][1] - mn0); rs0 += s[ni][1];
            s[ni][2] = expf(s[ni][2] - mn1); rs1 += s[ni][2];
            s[ni][3] = expf(s[ni][3] - mn1); rs1 += s[ni][3];
        }
        rs0 += __shfl_xor_sync(0xffffffffu, rs0, 1);
        rs0 += __shfl_xor_sync(0xffffffffu, rs0, 2);
        rs1 += __shfl_xor_sync(0xffffffffu, rs1, 1);
        rs1 += __shfl_xor_sync(0xffffffffu, rs1, 2);
        l0 = l0 * sc0 + rs0; m0 = mn0;
        l1 = l1 * sc1 + rs1; m1 = mn1;
        #pragma unroll
        for (int ni = 0; ni < 8; ni++) {
            o[ni][0] *= sc0; o[ni][1] *= sc0;
            o[ni][2] *= sc1; o[ni][3] *= sc1;
        }

        #pragma unroll
        for (int kb2 = 0; kb2 < 8; kb2++) {
            int k8 = kb2 * 8;
            uint32_t af[4];
            af[0] = __float_as_uint(s[kb2][0]);
            af[1] = __float_as_uint(s[kb2][2]);
            af[2] = __float_as_uint(s[kb2][1]);
            af[3] = __float_as_uint(s[kb2][3]);
            #pragma unroll
            for (int ni = 0; ni < 8; ni++) {
                uint32_t b0 = __float_as_uint(Vt[(ni * 8 + gid) * 68 + k8 + tg    ]);
                uint32_t b1 = __float_as_uint(Vt[(ni * 8 + gid) * 68 + k8 + tg + 4]);
                asm volatile(
                    "mma.sync.aligned.m16n8k8.row.col.f32.tf32.tf32.f32 "
                    "{%0,%1,%2,%3}, {%4,%5,%6,%7}, {%8,%9}, {%0,%1,%2,%3};\n"
                    : "+f"(o[ni][0]), "+f"(o[ni][1]), "+f"(o[ni][2]), "+f"(o[ni][3])
                    : "r"(af[0]), "r"(af[1]), "r"(af[2]), "r"(af[3]),
                      "r"(b0), "r"(b1));
            }
        }
    }

    float inv0 = 1.f / l0, inv1 = 1.f / l1;
    int t0 = qbase + wm + gid;
    int t1 = t0 + 8;
    #pragma unroll
    for (int ni = 0; ni < 8; ni++) {
        int c = h * HD + ni * 8 + tg * 2;
        if (t0 < Tn) {
            float2 vv;
            vv.x = tf32r(o[ni][0] * inv0);
            vv.y = tf32r(o[ni][1] * inv0);
            *(float2*)&out[(size_t)(b * Tn + t0) * Cn + c] = vv;
        }
        if (t1 < Tn) {
            float2 vv;
            vv.x = tf32r(o[ni][2] * inv1);
            vv.y = tf32r(o[ni][3] * inv1);
            *(float2*)&out[(size_t)(b * Tn + t1) * Cn + c] = vv;
        }
    }
}

// tail: q-row 512. Warp-per-key QK with 4-way key ILP; thread-per-d PV phase.
__global__ void attn_tail(const float* __restrict__ qkv, float* __restrict__ out)
{
    int h = blockIdx.x, b = blockIdx.y;
    int tid = threadIdx.x, lane = tid & 31, wid = tid >> 5;
    __shared__ float q[64];
    __shared__ float p[Tn];
    __shared__ float red[256];
    const float* qp = qkv + (size_t)(b * Tn + Tn - 1) * (3 * Cn) + h * HD;
    if (tid < 64) q[tid] = qp[tid] * 0.125f;
    __syncthreads();
    // QK: warp per key j, 4 keys in flight per iteration
    float q0 = q[lane], q1 = q[lane + 32];
    const float* kbase = qkv + (size_t)b * Tn * (3 * Cn) + Cn + h * HD;
    float lmax = -1e30f;
    for (int j = wid; j < Tn; j += 32) {
        int j1 = j + 8, j2 = j + 16, j3 = j + 24;
        const float* kp0 = kbase + (size_t)j * (3 * Cn);
        float a0 = kp0[lane], b0v = kp0[lane + 32];
        float a1 = 0.f, b1v = 0.f, a2 = 0.f, b2v = 0.f, a3 = 0.f, b3v = 0.f;
        if (j1 < Tn) { const float* kp = kbase + (size_t)j1 * (3 * Cn); a1 = kp[lane]; b1v = kp[lane + 32]; }
        if (j2 < Tn) { const float* kp = kbase + (size_t)j2 * (3 * Cn); a2 = kp[lane]; b2v = kp[lane + 32]; }
        if (j3 < Tn) { const float* kp = kbase + (size_t)j3 * (3 * Cn); a3 = kp[lane]; b3v = kp[lane + 32]; }
        float s0 = q0 * a0 + q1 * b0v;
        float s1 = q0 * a1 + q1 * b1v;
        float s2 = q0 * a2 + q1 * b2v;
        float s3 = q0 * a3 + q1 * b3v;
        #pragma unroll
        for (int off = 16; off > 0; off >>= 1) {
            s0 += __shfl_xor_sync(0xffffffffu, s0, off);
            s1 += __shfl_xor_sync(0xffffffffu, s1, off);
            s2 += __shfl_xor_sync(0xffffffffu, s2, off);
            s3 += __shfl_xor_sync(0xffffffffu, s3, off);
        }
        if (lane == 0) {
            p[j] = s0;
            if (j1 < Tn) p[j1] = s1;
            if (j2 < Tn) p[j2] = s2;
            if (j3 < Tn) p[j3] = s3;
        }
        lmax = fmaxf(lmax, s0);
        if (j1 < Tn) lmax = fmaxf(lmax, s1);
        if (j2 < Tn) lmax = fmaxf(lmax, s2);
        if (j3 < Tn) lmax = fmaxf(lmax, s3);
    }
    float rmax = blockReduceMax256(lmax, red);
    float lsum = 0.f;
    for (int j = tid; j < Tn; j += 256) {
        float e = expf(p[j] - rmax);
        p[j] = e; lsum += e;
    }
    float rsum = blockReduceSum256(lsum, red);
    int d = tid & 63, part = tid >> 6;
    float acc = 0.f;
    for (int j = part; j < Tn; j += 4)
        acc += p[j] * qkv[(size_t)(b * Tn + j) * (3 * Cn) + 2 * Cn + h * HD + d];
    red[tid] = acc;
    __syncthreads();
    if (part == 0) {
        float v = red[d] + red[d + 64] + red[d + 128] + red[d + 192];
        out[(size_t)(b * Tn + Tn - 1) * Cn + h * HD + d] = tf32r(v / rsum);
    }
}

// ---------------- adapter (+ fused plain-LN producing z) ----------------
__global__ void adapter_kernel(const float* __restrict__ xffn, const float* __restrict__ x1,
                               const float* __restrict__ Wa1, const float* __restrict__ ba1,
                               const float* __restrict__ Wa2, const float* __restrict__ ba2,
                               float* __restrict__ x2, float* __restrict__ z)
{
    int r = blockIdx.x;
    int tid = threadIdx.x;
    __shared__ float xr[Cn];
    __shared__ float x2s[Cn];
    __shared__ float tg[ADn];
    __shared__ float red[256];
    const float* xp = xffn + (size_t)r * Cn;
    for (int c = tid; c < Cn; c += 256) xr[c] = xp[c];
    __syncthreads();
    int w = tid >> 5, lane = tid & 31;
    for (int a = w; a < ADn; a += 8) {
        float p = 0.f;
        const float* ww = Wa1 + (size_t)a * Cn;
        for (int c = lane; c < Cn; c += 32) p += xr[c] * ww[c];
        #pragma unroll
        for (int off = 16; off > 0; off >>= 1) p += __shfl_xor_sync(0xffffffffu, p, off);
        if (lane == 0) tg[a] = quick_gelu(p + ba1[a]);
    }
    __syncthreads();
    const float* x1p = x1 + (size_t)r * Cn;
    float s0 = 0.f;
    for (int c = tid; c < Cn; c += 256) {
        float acc = ba2[c];
        const float* w2 = Wa2 + (size_t)c * ADn;
        #pragma unroll
        for (int a = 0; a < ADn; a++) acc += tg[a] * w2[a];
        float v = x1p[c] + xr[c] + 0.5f * acc;
        x2s[c] = v;
        x2[(size_t)r * Cn + c] = v;
        s0 += v;
    }
    int t = r % Tn;
    if (t == 0) return;
    float mean = blockReduceSum256(s0, red) * (1.f / Cn);
    float s1 = 0.f;
    for (int c = tid; c < Cn; c += 256) { float d = x2s[c] - mean; s1 += d * d; }
    float var = blockReduceSum256(s1, red) * (1.f / Cn);
    float inv = rsqrtf(var + EPSf);
    int zi = (r / Tn) * 512 + (t - 1);
    float* zp = z + (size_t)zi * Cn;
    for (int c = tid; c < Cn; c += 256)
        zp[c] = tf32r((x2s[c] - mean) * inv);
}

// ---------------- view weight prep ----------------
__global__ void wprep_kernel(const float* __restrict__ aqw, const float* __restrict__ aqb,
                             const float* __restrict__ n3g, const float* __restrict__ n3b)
{
    int vj = blockIdx.x;
    int v = vj / 36;
    int tid = threadIdx.x;
    __shared__ float red[256];
    const float* w = aqw + (size_t)vj * Cn;
    const float* gg = n3g + (size_t)v * Cn;
    const float* bb = n3b + (size_t)v * Cn;
    float s = 0.f;
    for (int c = tid; c < Cn; c += 256) {
        float wv = w[c];
        g_weff[(size_t)vj * Cn + c] = tf32r(wv * gg[c]);
        s += wv * bb[c];
    }
    s = blockReduceSum256(s, red);
    if (tid == 0) g_beff[vj] = aqb[vj] + s;
}

// ---------------- cluster (3d) pooling chain ----------------
__global__ void pool_init(int R)
{
    int i = blockIdx.x * blockDim.x + threadIdx.x;
    if (i <= R) g_hist[i] = 0;
    if (i < Cn) { g_colsum[i] = 0.0; g_colsq[i] = 0.0; }
}
__global__ void hist_count(const int* __restrict__ idx)
{
    int i = blockIdx.x * blockDim.x + threadIdx.x;
    if (i < BG) atomicAdd(&g_hist[idx[i]], 1);
}
__global__ void scan_kernel(int R)
{
    __shared__ int part[1024];
    int tid = threadIdx.x;
    int chunk = (R + 1023) / 1024;
    int t0 = tid * chunk;
    int s = 0;
    for (int j = 0; j < chunk; j++)
        if (t0 + j < R) s += g_hist[t0 + j];
    part[tid] = s;
    __syncthreads();
    for (int off = 1; off < 1024; off <<= 1) {
        int v = (tid >= off) ? part[tid - off] : 0;
        __syncthreads();
        part[tid] += v;
        __syncthreads();
    }
    int run = (tid > 0) ? part[tid - 1] : 0;
    for (int j = 0; j < chunk; j++) {
        if (t0 + j < R) {
            int c = g_hist[t0 + j];
            g_off[t0 + j] = run;
            g_cur[t0 + j] = run;
            run += c;
        }
    }
    if (tid == 1023) g_off[R] = part[1023];
}
__global__ void seg_place(const int* __restrict__ idx)
{
    int i = blockIdx.x * blockDim.x + threadIdx.x;
    if (i >= BG) return;
    int p = atomicAdd(&g_cur[idx[i]], 1);
    g_ord[p] = i;
}
__global__ void seg_reduce(const float* __restrict__ src)
{
    int r = blockIdx.x;
    int tid = threadIdx.x;
    int s0 = g_off[r], s1 = g_off[r + 1];
    float mx0 = -1e30f, mx1 = -1e30f, mx2 = -1e30f;
    float sm0 = 0.f, sm1 = 0.f, sm2 = 0.f;
    for (int j = s0; j < s1; j++) {
        int i = g_ord[j];
        const float* p = src + (size_t)featRow(i) * Cn;
        float v0 = p[tid], v1 = p[tid + 256], v2 = p[tid + 512];
        mx0 = fmaxf(mx0, v0); sm0 += v0;
        mx1 = fmaxf(mx1, v1); sm1 += v1;
        mx2 = fmaxf(mx2, v2); sm2 += v2;
    }
    int cnt = s1 - s0;
    float inv = 1.f / (float)(cnt > 0 ? cnt : 1);
    float* op = g_scomb + (size_t)r * Cn;
    op[tid]       = (cnt > 0 ? mx0 : 0.f) + sm0 * inv;
    op[tid + 256] = (cnt > 0 ? mx1 : 0.f) + sm1 * inv;
    op[tid + 512] = (cnt > 0 ? mx2 : 0.f) + sm2 * inv;
}
__global__ void colstats(int R)
{
    int col = blockIdx.x * blockDim.x + threadIdx.x;
    if (col >= Cn) return;
    int chunk = (R + gridDim.y - 1) / gridDim.y;
    int r0 = blockIdx.y * chunk;
    int r1 = min(r0 + chunk, R);
    float sum = 0.f, sq = 0.f;
    for (int r = r0; r < r1; r++) {
        float v = g_scomb[(size_t)r * Cn + col];
        sum += v; sq += v * v;
    }
    atomicAdd(&g_colsum[col], (double)sum);
    atomicAdd(&g_colsq[col], (double)sq);
}
__global__ void colfinal(int R)
{
    int col = blockIdx.x * blockDim.x + threadIdx.x;
    if (col >= Cn) return;
    double mean = g_colsum[col] / R;
    double var = g_colsq[col] / R - mean * mean;
    if (var < 0.0) var = 0.0;
    g_mean[col] = (float)mean;
    g_rstd[col] = rsqrtf((float)var + EPSf);
}
__global__ void bn_apply(const float* __restrict__ gam, const float* __restrict__ bet,
                         float* __restrict__ out, int R)
{
    int i = blockIdx.x * blockDim.x + threadIdx.x;
    if (i >= R * Cn) return;
    int col = i % Cn;
    float v = (g_scomb[i] - g_mean[col]) * g_rstd[col] * gam[col] + bet[col];
    out[i] = gelu_exact(v);
}

// ---------------- batched (x6 views) pooling chain ----------------
__global__ void pool_init6()
{
    int v = blockIdx.y;
    int i = blockIdx.x * blockDim.x + threadIdx.x;
    if (i <= D1n) g_hist6[v * (D1n + 1) + i] = 0;
    if (i < Cn) { g_colsum6[v * Cn + i] = 0.0; g_colsq6[v * Cn + i] = 0.0; }
}
__global__ void hist_count6(const int* __restrict__ fgi)
{
    int v = blockIdx.y;
    int i = blockIdx.x * blockDim.x + threadIdx.x;
    if (i < BG) atomicAdd(&g_hist6[v * (D1n + 1) + fgi[(size_t)v * BG + i]], 1);
}
__global__ void scan6()
{
    int v = blockIdx.x;
    int* hist = g_hist6 + v * (D1n + 1);
    int* off  = g_off6  + v * (D1n + 1);
    int* cur  = g_cur6  + v * (D1n + 1);
    __shared__ int part[1024];
    int tid = threadIdx.x;
    const int R = D1n;
    int chunk = (R + 1023) / 1024;
    int t0 = tid * chunk;
    int s = 0;
    for (int j = 0; j < chunk; j++)
        if (t0 + j < R) s += hist[t0 + j];
    part[tid] = s;
    __syncthreads();
    for (int off2 = 1; off2 < 1024; off2 <<= 1) {
        int vv = (tid >= off2) ? part[tid - off2] : 0;
        __syncthreads();
        part[tid] += vv;
        __syncthreads();
    }
    int run = (tid > 0) ? part[tid - 1] : 0;
    for (int j = 0; j < chunk; j++) {
        if (t0 + j < R) {
            int c = hist[t0 + j];
            off[t0 + j] = run;
            cur[t0 + j] = run;
            run += c;
        }
    }
    if (tid == 1023) off[R] = part[1023];
}
__global__ void seg_place6(const int* __restrict__ fgi)
{
    int v = blockIdx.y;
    int i = blockIdx.x * blockDim.x + threadIdx.x;
    if (i >= BG) return;
    int p = atomicAdd(&g_cur6[v * (D1n + 1) + fgi[(size_t)v * BG + i]], 1);
    g_ord6[(size_t)v * BG + p] = i;
}
__global__ void view_attn6(const float* __restrict__ qkv1, const unsigned char* __restrict__ mask)
{
    int blk = blockIdx.x, h = blockIdx.y, v = blockIdx.z;
    int t = threadIdx.x;
    __shared__ float kk[N1n][2];
    __shared__ float vv[N1n][2];
    int row = blk * N1n + t;
    const float* base = qkv1 + (size_t)row * NQ1 + v * 36;
    float q0 = base[h * 2]     * 0.28867513459481287f;
    float q1 = base[h * 2 + 1] * 0.28867513459481287f;
    kk[t][0] = base[12 + h * 2]; kk[t][1] = base[13 + h * 2];
    vv[t][0] = base[24 + h * 2]; vv[t][1] = base[25 + h * 2];
    __syncthreads();
    const unsigned char* mrow = mask + (size_t)v * NB1 * N1n * N1n + ((size_t)blk * N1n + t) * N1n;
    float mmax = -1e30f;
    #pragma unroll 4
    for (int j = 0; j < N1n; j++) {
        float s = q0 * kk[j][0] + q1 * kk[j][1] + (mrow[j] ? -100000.f : 0.f);
        mmax = fmaxf(mmax, s);
    }
    float l = 0.f, a0 = 0.f, a1 = 0.f;
    #pragma unroll 4
    for (int j = 0; j < N1n; j++) {
        float s = q0 * kk[j][0] + q1 * kk[j][1] + (mrow[j] ? -100000.f : 0.f);
        float p = expf(s - mmax);
        l += p; a0 += p * vv[j][0]; a1 += p * vv[j][1];
    }
    float* o1 = g_o16 + (size_t)v * BG * MIDn;
    o1[(size_t)row * MIDn + h * 2]     = a0 / l;
    o1[(size_t)row * MIDn + h * 2 + 1] = a1 / l;
}
__global__ void seg_reduce_view6(const float* __restrict__ apw, const float* __restrict__ apb,
                                 const float* __restrict__ x2)
{
    int r = blockIdx.x, v = blockIdx.y;
    int tid = threadIdx.x;
    const int* off = g_off6 + v * (D1n + 1);
    const int* ord = g_ord6 + (size_t)v * BG;
    const float* o1 = g_o16 + (size_t)v * BG * MIDn;
    const float* pw = apw + (size_t)v * Cn * MIDn;
    const float* pb = apb + (size_t)v * Cn;
    int s0 = off[r], s1 = off[r + 1];
    float wr[3][MIDn], pbv[3];
    #pragma unroll
    for (int ch = 0; ch < 3; ch++) {
        int c = tid + ch * 256;
        pbv[ch] = pb[c];
        #pragma unroll
        for (int k = 0; k < MIDn; k++) wr[ch][k] = __ldg(&pw[(size_t)c * MIDn + k]);
    }
    float mx[3] = {-1e30f, -1e30f, -1e30f};
    float sm[3] = {0.f, 0.f, 0.f};
    for (int j = s0; j < s1; j++) {
        int i = ord[j];
        const float4* ob = (const float4*)&o1[(size_t)i * MIDn];
        float4 o0 = __ldg(ob), o1v = __ldg(ob + 1), o2 = __ldg(ob + 2);
        float os[MIDn] = {o0.x, o0.y, o0.z, o0.w, o1v.x, o1v.y, o1v.z, o1v.w,
                          o2.x, o2.y, o2.z, o2.w};
        const float* xp = x2 + (size_t)featRow(i) * Cn;
        #pragma unroll
        for (int ch = 0; ch < 3; ch++) {
            float vv = pbv[ch] + xp[tid + ch * 256];
            #pragma unroll
            for (int k = 0; k < MIDn; k++) vv += os[k] * wr[ch][k];
            mx[ch] = fmaxf(mx[ch], vv);
            sm[ch] += vv;
        }
    }
    int cnt = s1 - s0;
    float inv = 1.f / (float)(cnt > 0 ? cnt : 1);
    float* op = g_scomb6 + ((size_t)v * D1n + r) * Cn;
    #pragma unroll
    for (int ch = 0; ch < 3; ch++)
        op[tid + ch * 256] = (cnt > 0 ? mx[ch] : 0.f) + sm[ch] * inv;
}
__global__ void colstats6()
{
    int col = blockIdx.x * blockDim.x + threadIdx.x;
    int v = blockIdx.z;
    if (col >= Cn) return;
    const int R = D1n;
    int chunk = (R + gridDim.y - 1) / gridDim.y;
    int r0 = blockIdx.y * chunk;
    int r1 = min(r0 + chunk, R);
    float sum = 0.f, sq = 0.f;
    const float* sc = g_scomb6 + (size_t)v * D1n * Cn;
    for (int r = r0; r < r1; r++) {
        float vv = sc[(size_t)r * Cn + col];
        sum += vv; sq += vv * vv;
    }
    atomicAdd(&g_colsum6[v * Cn + col], (double)sum);
    atomicAdd(&g_colsq6[v * Cn + col], (double)sq);
}
__global__ void colfinal6()
{
    int col = blockIdx.x * blockDim.x + threadIdx.x;
    int v = blockIdx.y;
    if (col >= Cn) return;
    double mean = g_colsum6[v * Cn + col] / D1n;
    double var = g_colsq6[v * Cn + col] / D1n - mean * mean;
    if (var < 0.0) var = 0.0;
    g_mean6[v * Cn + col] = (float)mean;
    g_rstd6[v * Cn + col] = rsqrtf((float)var + EPSf);
}
__global__ void bn_apply6(const float* __restrict__ bn1dg, const float* __restrict__ bn1db,
                          float* __restrict__ bview)
{
    int v = blockIdx.y;
    int i = blockIdx.x * blockDim.x + threadIdx.x;
    if (i >= D1n * Cn) return;
    int col = i % Cn;
    float vv = (g_scomb6[(size_t)v * D1n * Cn + i] - g_mean6[v * Cn + col]) * g_rstd6[v * Cn + col]
               * bn1dg[v * Cn + col] + bn1db[v * Cn + col];
    bview[(size_t)v * D1n * Cn + i] = gelu_exact(vv);
}

// ---------------- final fusion ----------------
__global__ void final_kernel(const float* __restrict__ x2, const float* __restrict__ g3,
                             const float* __restrict__ bview, const int* __restrict__ cluster,
                             const int* __restrict__ fgi, float* __restrict__ out)
{
    int i = blockIdx.x;
    int tid = threadIdx.x;
    size_t xrow = (size_t)featRow(i);
    __shared__ float x3[Cn];
    __shared__ float pv[NV][Cn];
    __shared__ float red[256];
    __shared__ float sims[NV];
    int cl = cluster[i];
    const float* x3p = g3 + (size_t)cl * Cn;
    for (int c = tid; c < Cn; c += 256) x3[c] = x3p[c];
    for (int v = 0; v < NV; v++) {
        int id = fgi[(size_t)v * BG + i];
        const float* pp = bview + ((size_t)v * D1n + id) * Cn;
        for (int c = tid; c < Cn; c += 256) pv[v][c] = pp[c];
    }
    __syncthreads();
    float p = 0.f;
    for (int c = tid; c < Cn; c += 256) p += x3[c] * x3[c];
    float nx3 = fmaxf(sqrtf(blockReduceSum256(p, red)), 1e-8f);
    for (int v = 0; v < NV; v++) {
        float d = 0.f, n = 0.f;
        for (int c = tid; c < Cn; c += 256) {
            float a = pv[v][c];
            d += a * x3[c]; n += a * a;
        }
        d = blockReduceSum256(d, red);
        n = blockReduceSum256(n, red);
        if (tid == 0) {
            float np = fmaxf(sqrtf(n), 1e-8f);
            float cs = d / (np * nx3);
            sims[v] = (cs + 1.f) * 0.5f;
        }
        __syncthreads();
    }
    float ssum = 0.f;
    #pragma unroll
    for (int v = 0; v < NV; v++) ssum += sims[v];
    float inv = 1.f / ssum;
    const float* x2p = x2 + xrow * Cn;
    float* op = out + xrow * Cn;
    for (int c = tid; c < Cn; c += 256) {
        float sup = 0.f;
        #pragma unroll
        for (int v = 0; v < NV; v++) sup += pv[v][c] * sims[v];
        op[c] = x2p[c] + 0.3f * sup * inv;
    }
}

__global__ void cls_copy(const float* __restrict__ x2, float* __restrict__ out)
{
    size_t row = (size_t)blockIdx.x * Tn;
    for (int c = threadIdx.x; c < Cn; c += blockDim.x)
        out[row * Cn + c] = x2[row * Cn + c];
}

// ---------------- host launch ----------------
extern "C" void kernel_launch(void* const* d_in, const int* in_sizes, int n_in,
                              void* d_out, int out_size)
{
    const float* x    = (const float*)d_in[0];
    const float* ln1g = (const float*)d_in[1];
    const float* ln1b = (const float*)d_in[2];
    const float* ln2g = (const float*)d_in[3];
    const float* ln2b = (const float*)d_in[4];
    const float* Wqkv = (const float*)d_in[5];
    const float* bqkv = (const float*)d_in[6];
    const float* Wo   = (const float*)d_in[7];
    const float* bo   = (const float*)d_in[8];
    const float* Wfc  = (const float*)d_in[9];
    const float* bfc  = (const float*)d_in[10];
    const float* Wproj= (const float*)d_in[11];
    const float* bproj= (const float*)d_in[12];
    const float* Wa1  = (const float*)d_in[13];
    const float* ba1  = (const float*)d_in[14];
    const float* Wa2  = (const float*)d_in[15];
    const float* ba2  = (const float*)d_in[16];
    const float* bn3dg= (const float*)d_in[17];
    const float* bn3db= (const float*)d_in[18];
    const float* bn1dg= (const float*)d_in[19];
    const float* bn1db= (const float*)d_in[20];
    const float* n3g  = (const float*)d_in[21];
    const float* n3b  = (const float*)d_in[22];
    const float* aqw  = (const float*)d_in[23];
    const float* aqb  = (const float*)d_in[24];
    const float* apw  = (const float*)d_in[25];
    const float* apb  = (const float*)d_in[26];
    const int*   cluster = (const int*)d_in[27];
    const int*   fgi  = (const int*)d_in[28];
    const unsigned char* mask = (const unsigned char*)d_in[29];
    float* out = (float*)d_out;

    float *y, *qkv, *att, *x1, *hfc, *xffn, *x2, *g3, *bview, *z, *qkv1, *weff, *beff;
    cudaGetSymbolAddress((void**)&y,     g_y);
    cudaGetSymbolAddress((void**)&qkv,   g_qkv);
    cudaGetSymbolAddress((void**)&att,   g_att);
    cudaGetSymbolAddress((void**)&x1,    g_x1);
    cudaGetSymbolAddress((void**)&hfc,   g_hfc);
    cudaGetSymbolAddress((void**)&xffn,  g_xffn);
    cudaGetSymbolAddress((void**)&x2,    g_x2);
    cudaGetSymbolAddress((void**)&g3,    g_g3);
    cudaGetSymbolAddress((void**)&bview, g_bview);
    cudaGetSymbolAddress((void**)&z,     g_z);
    cudaGetSymbolAddress((void**)&qkv1,  g_qkv1);
    cudaGetSymbolAddress((void**)&weff,  g_weff);
    cudaGetSymbolAddress((void**)&beff,  g_beff);

    cudaFuncSetAttribute(attn_tc, cudaFuncAttributeMaxDynamicSharedMemorySize, ATTN_SMEM);
    cudaFuncSetAttribute(gemm_tf32<0>, cudaFuncAttributeMaxDynamicSharedMemorySize, GEMM_SMEM);
    cudaFuncSetAttribute(gemm_tf32<1>, cudaFuncAttributeMaxDynamicSharedMemorySize, GEMM_SMEM);
    cudaFuncSetAttribute(gemm_tf32<2>, cudaFuncAttributeMaxDynamicSharedMemorySize, GEMM_SMEM);

    const int GMB = (MROWS + 127) / 128;  // 129

    // 1) LN1 -> y (tf32-rounded)
    ln_kernel<<<MROWS, 256>>>(x, ln1g, ln1b, y, 0);
    // 2) QKV GEMM (weights direct; HW truncation)
    gemm_tf32<0><<<dim3(GMB, (3 * Cn) / 128), 256, GEMM_SMEM>>>(y, Wqkv, bqkv, nullptr, qkv, MROWS, 3 * Cn, Cn);
    // 3) attention + tail
    attn_tc<<<dim3(4, Hn, Bn), 256, ATTN_SMEM>>>(qkv, att);
    attn_tail<<<dim3(Hn, Bn), 256>>>(qkv, att);
    // 4) output proj + residual
    gemm_tf32<2><<<dim3(GMB, Cn / 128), 256, GEMM_SMEM>>>(att, Wo, bo, x, x1, MROWS, Cn, Cn);
    // 5) LN2 -> y
    ln_kernel<<<MROWS, 256>>>(x1, ln2g, ln2b, y, 0);
    // 6) FC + quick_gelu
    gemm_tf32<1><<<dim3(GMB, FFn / 128), 256, GEMM_SMEM>>>(y, Wfc, bfc, nullptr, hfc, MROWS, FFn, Cn);
    // 7) proj
    gemm_tf32<0><<<dim3(GMB, Cn / 128), 256, GEMM_SMEM>>>(hfc, Wproj, bproj, nullptr, xffn, MROWS, Cn, FFn);
    // 8) adapter + residuals -> x2, fused plain LN -> z
    adapter_kernel<<<MROWS, 256>>>(xffn, x1, Wa1, ba1, Wa2, ba2, x2, z);

    // 9) 3d segment pool + BN over clusters
    {
        pool_init<<<(NCL + 1 + 255) / 256, 256>>>(NCL);
        hist_count<<<(BG + 255) / 256, 256>>>(cluster);
        scan_kernel<<<1, 1024>>>(NCL);
        seg_place<<<(BG + 255) / 256, 256>>>(cluster);
        seg_reduce<<<NCL, 256>>>(x2);
        colstats<<<dim3(3, 16), 256>>>(NCL);
        colfinal<<<3, 256>>>(NCL);
        bn_apply<<<(NCL * Cn + 255) / 256, 256>>>(bn3dg, bn3db, g3, NCL);
    }

    // 10) view branches (batched; z produced by adapter)
    wprep_kernel<<<NQ1, 256>>>(aqw, aqb, n3g, n3b);
    gemm_tf32<0><<<dim3(BG / 128, (NQ1 + 127) / 128), 256, GEMM_SMEM>>>(z, weff, beff, nullptr, qkv1,
                                                                        BG, NQ1, Cn);
    view_attn6<<<dim3(NB1, H1n, NV), N1n>>>(qkv1, mask);
    pool_init6<<<dim3((D1n + 1 + 255) / 256, NV), 256>>>();
    hist_count6<<<dim3((BG + 255) / 256, NV), 256>>>(fgi);
    scan6<<<NV, 1024>>>();
    seg_place6<<<dim3((BG + 255) / 256, NV), 256>>>(fgi);
    seg_reduce_view6<<<dim3(D1n, NV), 256>>>(apw, apb, x2);
    colstats6<<<dim3(3, 16, NV), 256>>>();
    colfinal6<<<dim3(3, NV), 256>>>();
    bn_apply6<<<dim3((D1n * Cn + 255) / 256, NV), 256>>>(bn1dg, bn1db, bview);

    // 11) cossim fusion + output
    final_kernel<<<BG, 256>>>(x2, g3, bview, cluster, fgi, out);
    cls_copy<<<Bn, 256>>>(x2, out);
}

// round 15
// speedup vs baseline: 1.1926x; 1.0130x over previous
#include <cuda_runtime.h>
#include <cuda_bf16.h>
#include <math.h>
#include <stdint.h>

// ---------------- problem constants ----------------
#define Bn    32
#define Gn    512
#define Cn    768
#define Hn    12
#define HD    64
#define Tn    513              // G+1
#define MROWS (Bn*Tn)          // 16416
#define BG    16384
#define FFn   3072
#define ADn   16
#define MIDn  12
#define H1n   6
#define N1n   128
#define NB1   (BG/N1n)         // 128
#define NCL   2048
#define D1n   6272
#define NV    6
#define NQ1   (NV*3*MIDn)      // 216
#define EPSf  1e-5f

// ---------------- scratch (device globals; no allocation) ----------------
__device__ float  g_y   [MROWS*Cn];
__device__ float  g_qkv [MROWS*3*Cn];
__device__ float  g_att [MROWS*Cn];
__device__ float  g_x1  [MROWS*Cn];
__device__ float  g_hfc [MROWS*FFn];
__device__ float  g_xffn[MROWS*Cn];
__device__ float  g_x2  [MROWS*Cn];
__device__ float  g_g3   [NCL*Cn];
__device__ float  g_bview[NV*D1n*Cn];
__device__ float  g_z    [BG*Cn];          // nhat (un-affined LN of feat)
__device__ float  g_qkv1 [BG*NQ1];
__device__ float  g_weff [NQ1*Cn];
__device__ float  g_beff [NQ1];
// cluster (3d) pooling buffers
__device__ float  g_scomb [NCL*Cn];
__device__ double g_colsum[Cn];
__device__ double g_colsq [Cn];
__device__ float  g_mean[Cn];
__device__ float  g_rstd[Cn];
__device__ int    g_hist[NCL+1];
__device__ int    g_off [NCL+1];
__device__ int    g_cur [NCL+1];
__device__ int    g_ord [BG];
// batched view pooling buffers
__device__ int    g_hist6[NV*(D1n+1)];
__device__ int    g_off6 [NV*(D1n+1)];
__device__ int    g_cur6 [NV*(D1n+1)];
__device__ int    g_ord6 [NV*BG];
__device__ float  g_scomb6[(size_t)NV*D1n*Cn];
__device__ double g_colsum6[NV*Cn];
__device__ double g_colsq6 [NV*Cn];
__device__ float  g_mean6[NV*Cn];
__device__ float  g_rstd6[NV*Cn];
__device__ float  g_o16  [NV*BG*MIDn];

// ---------------- helpers ----------------
__device__ __forceinline__ float blockReduceSum256(float v, float* red) {
    int tid = threadIdx.x;
    red[tid] = v; __syncthreads();
    #pragma unroll
    for (int o = 128; o > 0; o >>= 1) {
        if (tid < o) red[tid] += red[tid + o];
        __syncthreads();
    }
    float r = red[0];
    __syncthreads();
    return r;
}
__device__ __forceinline__ float blockReduceMax256(float v, float* red) {
    int tid = threadIdx.x;
    red[tid] = v; __syncthreads();
    #pragma unroll
    for (int o = 128; o > 0; o >>= 1) {
        if (tid < o) red[tid] = fmaxf(red[tid], red[tid + o]);
        __syncthreads();
    }
    float r = red[0];
    __syncthreads();
    return r;
}
__device__ __forceinline__ float quick_gelu(float x) {
    return x / (1.f + expf(-1.702f * x));
}
__device__ __forceinline__ float gelu_exact(float x) {
    return 0.5f * x * (1.f + erff(x * 0.70710678118654752f));
}
__device__ __forceinline__ int featRow(int i) {
    return (i >> 9) * Tn + 1 + (i & 511);
}
__device__ __forceinline__ float tf32r(float f) {
    uint32_t u;
    asm volatile("cvt.rna.tf32.f32 %0, %1;" : "=r"(u) : "f"(f));
    return __uint_as_float(u);
}

// ---------------- LayerNorm (tf32-rounded out) ----------------
__global__ void ln_kernel(const float* __restrict__ in, const float* __restrict__ g,
                          const float* __restrict__ b, float* __restrict__ out, int featmode)
{
    int r = blockIdx.x;
    int row = featmode ? featRow(r) : r;
    const float* x = in + (size_t)row * Cn;
    __shared__ float xs[Cn];
    __shared__ float red[256];
    int tid = threadIdx.x;
    float s0 = 0.f;
    for (int c = tid; c < Cn; c += 256) { float v = x[c]; xs[c] = v; s0 += v; }
    float mean = blockReduceSum256(s0, red) * (1.f / Cn);
    float s1 = 0.f;
    for (int c = tid; c < Cn; c += 256) { float d = xs[c] - mean; s1 += d * d; }
    float var = blockReduceSum256(s1, red) * (1.f / Cn);
    float inv = rsqrtf(var + EPSf);
    float* op = out + (size_t)r * Cn;
    for (int c = tid; c < Cn; c += 256)
        op[c] = tf32r((xs[c] - mean) * inv * g[c] + b[c]);
}

// ---------------- mma.sync tf32 NT GEMM, 3-stage cp.async pipeline (proven R4/R6) ----------------
#define GEMM_SMEM (3 * 2 * 128 * 20 * 4)   // 61440 bytes
template <int EPI>
__global__ void __launch_bounds__(256, 2) gemm_tf32(
    const float* __restrict__ A, const float* __restrict__ W,
    const float* __restrict__ bias, const float* __restrict__ res,
    float* __restrict__ C, int M, int N, int K)
{
    extern __shared__ float sm_[];
    int tid = threadIdx.x;
    int bm = blockIdx.x * 128, bn = blockIdx.y * 128;
    int lane = tid & 31, wid = tid >> 5;
    int wm = (wid & 1) * 64, wn = (wid >> 1) * 32;
    int gid = lane >> 2, tg = lane & 3;

    float acc[4][4][4];
    #pragma unroll
    for (int a = 0; a < 4; a++)
        #pragma unroll
        for (int b = 0; b < 4; b++)
            #pragma unroll
            for (int c = 0; c < 4; c++) acc[a][b][c] = 0.f;

    auto prefetch = [&](int kt, int s) {
        int k0 = kt * 16;
        float* As = sm_ + s * 2560;
        float* Bs = sm_ + 7680 + s * 2560;
        #pragma unroll
        for (int i = 0; i < 2; i++) {
            int r = (tid >> 2) + i * 64;
            int c = (tid & 3) * 4;
            int arow = bm + r;
            const float* asrc = A + (size_t)(arow < M ? arow : 0) * K + k0 + c;
            uint32_t adst = (uint32_t)__cvta_generic_to_shared(&As[r * 20 + c]);
            int asz = (arow < M) ? 16 : 0;
            asm volatile("cp.async.cg.shared.global [%0], [%1], 16, %2;\n"
                         :: "r"(adst), "l"(asrc), "r"(asz));
            int brow = bn + r;
            const float* bsrc = W + (size_t)(brow < N ? brow : 0) * K + k0 + c;
            uint32_t bdst = (uint32_t)__cvta_generic_to_shared(&Bs[r * 20 + c]);
            int bsz = (brow < N) ? 16 : 0;
            asm volatile("cp.async.cg.shared.global [%0], [%1], 16, %2;\n"
                         :: "r"(bdst), "l"(bsrc), "r"(bsz));
        }
    };

    int nt = K / 16;
    prefetch(0, 0);
    asm volatile("cp.async.commit_group;\n");
    if (nt > 1) prefetch(1, 1);
    asm volatile("cp.async.commit_group;\n");

    int buf = 0;
    for (int t = 0; t < nt; t++) {
        asm volatile("cp.async.wait_group 1;\n");
        __syncthreads();
        if (t + 2 < nt) prefetch(t + 2, (buf + 2) % 3);
        asm volatile("cp.async.commit_group;\n");
        const float* As = sm_ + buf * 2560;
        const float* Bs = sm_ + 7680 + buf * 2560;
        #pragma unroll
        for (int kk = 0; kk < 2; kk++) {
            int kb = kk * 8;
            uint32_t af[4][4], bf[4][2];
            #pragma unroll
            for (int mi = 0; mi < 4; mi++) {
                int r = wm + mi * 16 + gid;
                af[mi][0] = __float_as_uint(As[(r    ) * 20 + kb + tg    ]);
                af[mi][1] = __float_as_uint(As[(r + 8) * 20 + kb + tg    ]);
                af[mi][2] = __float_as_uint(As[(r    ) * 20 + kb + tg + 4]);
                af[mi][3] = __float_as_uint(As[(r + 8) * 20 + kb + tg + 4]);
            }
            #pragma unroll
            for (int ni = 0; ni < 4; ni++) {
                int n0 = wn + ni * 8 + gid;
                bf[ni][0] = __float_as_uint(Bs[n0 * 20 + kb + tg    ]);
                bf[ni][1] = __float_as_uint(Bs[n0 * 20 + kb + tg + 4]);
            }
            #pragma unroll
            for (int mi = 0; mi < 4; mi++)
                #pragma unroll
                for (int ni = 0; ni < 4; ni++)
                    asm volatile(
                        "mma.sync.aligned.m16n8k8.row.col.f32.tf32.tf32.f32 "
                        "{%0,%1,%2,%3}, {%4,%5,%6,%7}, {%8,%9}, {%0,%1,%2,%3};\n"
                        : "+f"(acc[mi][ni][0]), "+f"(acc[mi][ni][1]),
                          "+f"(acc[mi][ni][2]), "+f"(acc[mi][ni][3])
                        : "r"(af[mi][0]), "r"(af[mi][1]), "r"(af[mi][2]), "r"(af[mi][3]),
                          "r"(bf[ni][0]), "r"(bf[ni][1]));
        }
        __syncthreads();
        buf = (buf + 1) % 3;
    }

    #pragma unroll
    for (int mi = 0; mi < 4; mi++) {
        #pragma unroll
        for (int ni = 0; ni < 4; ni++) {
            int m0 = bm + wm + mi * 16 + gid;
            int n0 = bn + wn + ni * 8 + tg * 2;
            if (n0 >= N) continue;
            float b0 = bias[n0], b1 = bias[n0 + 1];
            #pragma unroll
            for (int hh = 0; hh < 2; hh++) {
                int m = m0 + hh * 8;
                if (m >= M) continue;
                float v0 = acc[mi][ni][hh * 2 + 0] + b0;
                float v1 = acc[mi][ni][hh * 2 + 1] + b1;
                if (EPI == 1) { v0 = tf32r(quick_gelu(v0)); v1 = tf32r(quick_gelu(v1)); }
                if (EPI == 2) {
                    float2 rr = *(const float2*)&res[(size_t)m * N + n0];
                    v0 += rr.x; v1 += rr.y;
                }
                float2 vv; vv.x = v0; vv.y = v1;
                *(float2*)&C[(size_t)m * N + n0] = vv;
            }
        }
    }
}

// ---------------- tensor-core flash attention + fused tail (one launch) ----------------
// grid.x in [0,4]: qb<4 -> 128-q-row tensor-core tiles; qb==4 -> tail row 512 (SIMT).
#define ATTN_SMEM ((128 + 64 + 64) * 68 * 4)
__global__ void __launch_bounds__(256) attn_tc(const float* __restrict__ qkv,
                                               float* __restrict__ out)
{
    extern __shared__ float sm[];
    int qb = blockIdx.x, h = blockIdx.y, b = blockIdx.z;
    int tid = threadIdx.x, lane = tid & 31, wid = tid >> 5;

    if (qb == 4) {
        // ---- tail: q-row 512, warp-per-key QK with 4-way ILP ----
        float* q   = sm;                 // [64]
        float* p   = sm + 64;            // [Tn]
        float* red = sm + 64 + 640;      // [256]
        const float* qp = qkv + (size_t)(b * Tn + Tn - 1) * (3 * Cn) + h * HD;
        if (tid < 64) q[tid] = qp[tid] * 0.125f;
        __syncthreads();
        float q0 = q[lane], q1 = q[lane + 32];
        const float* kbase = qkv + (size_t)b * Tn * (3 * Cn) + Cn + h * HD;
        float lmax = -1e30f;
        for (int j = wid; j < Tn; j += 32) {
            int j1 = j + 8, j2 = j + 16, j3 = j + 24;
            const float* kp0 = kbase + (size_t)j * (3 * Cn);
            float a0 = kp0[lane], b0v = kp0[lane + 32];
            float a1 = 0.f, b1v = 0.f, a2 = 0.f, b2v = 0.f, a3 = 0.f, b3v = 0.f;
            if (j1 < Tn) { const float* kp = kbase + (size_t)j1 * (3 * Cn); a1 = kp[lane]; b1v = kp[lane + 32]; }
            if (j2 < Tn) { const float* kp = kbase + (size_t)j2 * (3 * Cn); a2 = kp[lane]; b2v = kp[lane + 32]; }
            if (j3 < Tn) { const float* kp = kbase + (size_t)j3 * (3 * Cn); a3 = kp[lane]; b3v = kp[lane + 32]; }
            float s0 = q0 * a0 + q1 * b0v;
            float s1 = q0 * a1 + q1 * b1v;
            float s2 = q0 * a2 + q1 * b2v;
            float s3 = q0 * a3 + q1 * b3v;
            #pragma unroll
            for (int off = 16; off > 0; off >>= 1) {
                s0 += __shfl_xor_sync(0xffffffffu, s0, off);
                s1 += __shfl_xor_sync(0xffffffffu, s1, off);
                s2 += __shfl_xor_sync(0xffffffffu, s2, off);
                s3 += __shfl_xor_sync(0xffffffffu, s3, off);
            }
            if (lane == 0) {
                p[j] = s0;
                if (j1 < Tn) p[j1] = s1;
                if (j2 < Tn) p[j2] = s2;
                if (j3 < Tn) p[j3] = s3;
            }
            lmax = fmaxf(lmax, s0);
            if (j1 < Tn) lmax = fmaxf(lmax, s1);
            if (j2 < Tn) lmax = fmaxf(lmax, s2);
            if (j3 < Tn) lmax = fmaxf(lmax, s3);
        }
        float rmax = blockReduceMax256(lmax, red);
        float lsum = 0.f;
        for (int j = tid; j < Tn; j += 256) {
            float e = expf(p[j] - rmax);
            p[j] = e; lsum += e;
        }
        float rsum = blockReduceSum256(lsum, red);
        int d = tid & 63, part = tid >> 6;
        float acc = 0.f;
        for (int j = part; j < Tn; j += 4)
            acc += p[j] * qkv[(size_t)(b * Tn + j) * (3 * Cn) + 2 * Cn + h * HD + d];
        red[tid] = acc;
        __syncthreads();
        if (part == 0) {
            float v = red[d] + red[d + 64] + red[d + 128] + red[d + 192];
            out[(size_t)(b * Tn + Tn - 1) * Cn + h * HD + d] = tf32r(v / rsum);
        }
        return;
    }

    float* Qs = sm;
    float* Ks = sm + 128 * 68;
    float* Vt = sm + 192 * 68;

    int gid = lane >> 2, tg = lane & 3;
    int wm = wid * 16;
    int qbase = qb * 128;

    {
        int r = tid >> 1, c0 = (tid & 1) * 32;
        int t = qbase + r;
        bool valid = (t < Tn);
        const float* qp = qkv + (size_t)(b * Tn + (valid ? t : 0)) * (3 * Cn) + h * HD + c0;
        #pragma unroll
        for (int i = 0; i < 8; i++) {
            float4 v = *(const float4*)(qp + i * 4);
            float4 w;
            w.x = valid ? tf32r(v.x * 0.125f) : 0.f;
            w.y = valid ? tf32r(v.y * 0.125f) : 0.f;
            w.z = valid ? tf32r(v.z * 0.125f) : 0.f;
            w.w = valid ? tf32r(v.w * 0.125f) : 0.f;
            *(float4*)&Qs[r * 68 + c0 + i * 4] = w;
        }
    }

    float m0 = -1e30f, m1 = -1e30f, l0 = 0.f, l1 = 0.f;
    float o[8][4];
    #pragma unroll
    for (int ni = 0; ni < 8; ni++)
        #pragma unroll
        for (int j = 0; j < 4; j++) o[ni][j] = 0.f;

    for (int kb = 0; kb < 9; kb++) {
        int kbase = kb * 64;
        __syncthreads();
        {
            int r = tid >> 2, c0 = (tid & 3) * 16;
            int t = kbase + r;
            bool valid = (t < Tn);
            const float* kp = qkv + (size_t)(b * Tn + (valid ? t : 0)) * (3 * Cn) + Cn + h * HD + c0;
            const float* vp = kp + Cn;
            int low = r & 7;
            int pr = (r & ~7) | (((low & 3) << 1) | (low >> 2));
            #pragma unroll
            for (int i = 0; i < 16; i += 4) {
                float4 kv4 = *(const float4*)(kp + i);
                float4 w;
                w.x = valid ? tf32r(kv4.x) : 0.f;
                w.y = valid ? tf32r(kv4.y) : 0.f;
                w.z = valid ? tf32r(kv4.z) : 0.f;
                w.w = valid ? tf32r(kv4.w) : 0.f;
                *(float4*)&Ks[pr * 68 + c0 + i] = w;
            }
            #pragma unroll
            for (int i = 0; i < 16; i++)
                Vt[(c0 + i) * 68 + r] = valid ? tf32r(vp[i]) : 0.f;
        }
        __syncthreads();

        float s[8][4];
        #pragma unroll
        for (int ni = 0; ni < 8; ni++)
            #pragma unroll
            for (int j = 0; j < 4; j++) s[ni][j] = 0.f;
        #pragma unroll
        for (int ks = 0; ks < 8; ks++) {
            int k8 = ks * 8;
            uint32_t af[4];
            int r = wm + gid;
            af[0] = __float_as_uint(Qs[(r    ) * 68 + k8 + tg    ]);
            af[1] = __float_as_uint(Qs[(r + 8) * 68 + k8 + tg    ]);
            af[2] = __float_as_uint(Qs[(r    ) * 68 + k8 + tg + 4]);
            af[3] = __float_as_uint(Qs[(r + 8) * 68 + k8 + tg + 4]);
            #pragma unroll
            for (int ni = 0; ni < 8; ni++) {
                uint32_t b0 = __float_as_uint(Ks[(ni * 8 + gid) * 68 + k8 + tg    ]);
                uint32_t b1 = __float_as_uint(Ks[(ni * 8 + gid) * 68 + k8 + tg + 4]);
                asm volatile(
                    "mma.sync.aligned.m16n8k8.row.col.f32.tf32.tf32.f32 "
                    "{%0,%1,%2,%3}, {%4,%5,%6,%7}, {%8,%9}, {%0,%1,%2,%3};\n"
                    : "+f"(s[ni][0]), "+f"(s[ni][1]), "+f"(s[ni][2]), "+f"(s[ni][3])
                    : "r"(af[0]), "r"(af[1]), "r"(af[2]), "r"(af[3]),
                      "r"(b0), "r"(b1));
            }
        }

        float vmax0 = -1e30f, vmax1 = -1e30f;
        #pragma unroll
        for (int ni = 0; ni < 8; ni++) {
            if (kbase + ni * 8 + tg >= Tn)     { s[ni][0] = -1e30f; s[ni][2] = -1e30f; }
            if (kbase + ni * 8 + tg + 4 >= Tn) { s[ni][1] = -1e30f; s[ni][3] = -1e30f; }
            vmax0 = fmaxf(vmax0, fmaxf(s[ni][0], s[ni][1]));
            vmax1 = fmaxf(vmax1, fmaxf(s[ni][2], s[ni][3]));
        }
        vmax0 = fmaxf(vmax0, __shfl_xor_sync(0xffffffffu, vmax0, 1));
        vmax0 = fmaxf(vmax0, __shfl_xor_sync(0xffffffffu, vmax0, 2));
        vmax1 = fmaxf(vmax1, __shfl_xor_sync(0xffffffffu, vmax1, 1));
        vmax1 = fmaxf(vmax1, __shfl_xor_sync(0xffffffffu, vmax1, 2));
        float mn0 = fmaxf(m0, vmax0), mn1 = fmaxf(m1, vmax1);
        float sc0 = expf(m0 - mn0), sc1 = expf(m1 - mn1);
        float rs0 = 0.f, rs1 = 0.f;
        #pragma unroll
        for (int ni = 0; ni < 8; ni++) {
            s[ni][0] = expf(s[ni][0] - mn0); rs0 += s[ni][0];
            s[ni][1] = expf(s[ni][1] - mn0); rs0 += s[ni][1];
            s[ni][2] = expf(s[ni][2] - mn1); rs1 += s[ni][2];
            s[ni][3] = expf(s[ni][3] - mn1); rs1 += s[ni][3];
        }
        rs0 += __shfl_xor_sync(0xffffffffu, rs0, 1);
        rs0 += __shfl_xor_sync(0xffffffffu, rs0, 2);
        rs1 += __shfl_xor_sync(0xffffffffu, rs1, 1);
        rs1 += __shfl_xor_sync(0xffffffffu, rs1, 2);
        l0 = l0 * sc0 + rs0; m0 = mn0;
        l1 = l1 * sc1 + rs1; m1 = mn1;
        #pragma unroll
        for (int ni = 0; ni < 8; ni++) {
            o[ni][0] *= sc0; o[ni][1] *= sc0;
            o[ni][2] *= sc1; o[ni][3] *= sc1;
        }

        #pragma unroll
        for (int kb2 = 0; kb2 < 8; kb2++) {
            int k8 = kb2 * 8;
            uint32_t af[4];
            af[0] = __float_as_uint(s[kb2][0]);
            af[1] = __float_as_uint(s[kb2][2]);
            af[2] = __float_as_uint(s[kb2][1]);
            af[3] = __float_as_uint(s[kb2][3]);
            #pragma unroll
            for (int ni = 0; ni < 8; ni++) {
                uint32_t b0 = __float_as_uint(Vt[(ni * 8 + gid) * 68 + k8 + tg    ]);
                uint32_t b1 = __float_as_uint(Vt[(ni * 8 + gid) * 68 + k8 + tg + 4]);
                asm volatile(
                    "mma.sync.aligned.m16n8k8.row.col.f32.tf32.tf32.f32 "
                    "{%0,%1,%2,%3}, {%4,%5,%6,%7}, {%8,%9}, {%0,%1,%2,%3};\n"
                    : "+f"(o[ni][0]), "+f"(o[ni][1]), "+f"(o[ni][2]), "+f"(o[ni][3])
                    : "r"(af[0]), "r"(af[1]), "r"(af[2]), "r"(af[3]),
                      "r"(b0), "r"(b1));
            }
        }
    }

    float inv0 = 1.f / l0, inv1 = 1.f / l1;
    int t0 = qbase + wm + gid;
    int t1 = t0 + 8;
    #pragma unroll
    for (int ni = 0; ni < 8; ni++) {
        int c = h * HD + ni * 8 + tg * 2;
        if (t0 < Tn) {
            float2 vv;
            vv.x = tf32r(o[ni][0] * inv0);
            vv.y = tf32r(o[ni][1] * inv0);
            *(float2*)&out[(size_t)(b * Tn + t0) * Cn + c] = vv;
        }
        if (t1 < Tn) {
            float2 vv;
            vv.x = tf32r(o[ni][2] * inv1);
            vv.y = tf32r(o[ni][3] * inv1);
            *(float2*)&out[(size_t)(b * Tn + t1) * Cn + c] = vv;
        }
    }
}

// ---------------- adapter (+ fused plain-LN producing z) ----------------
__global__ void adapter_kernel(const float* __restrict__ xffn, const float* __restrict__ x1,
                               const float* __restrict__ Wa1, const float* __restrict__ ba1,
                               const float* __restrict__ Wa2, const float* __restrict__ ba2,
                               float* __restrict__ x2, float* __restrict__ z)
{
    int r = blockIdx.x;
    int tid = threadIdx.x;
    __shared__ float xr[Cn];
    __shared__ float x2s[Cn];
    __shared__ float tg[ADn];
    __shared__ float red[256];
    const float* xp = xffn + (size_t)r * Cn;
    for (int c = tid; c < Cn; c += 256) xr[c] = xp[c];
    __syncthreads();
    int w = tid >> 5, lane = tid & 31;
    for (int a = w; a < ADn; a += 8) {
        float p = 0.f;
        const float* ww = Wa1 + (size_t)a * Cn;
        for (int c = lane; c < Cn; c += 32) p += xr[c] * ww[c];
        #pragma unroll
        for (int off = 16; off > 0; off >>= 1) p += __shfl_xor_sync(0xffffffffu, p, off);
        if (lane == 0) tg[a] = quick_gelu(p + ba1[a]);
    }
    __syncthreads();
    const float* x1p = x1 + (size_t)r * Cn;
    float s0 = 0.f;
    for (int c = tid; c < Cn; c += 256) {
        float acc = ba2[c];
        const float* w2 = Wa2 + (size_t)c * ADn;
        #pragma unroll
        for (int a = 0; a < ADn; a++) acc += tg[a] * w2[a];
        float v = x1p[c] + xr[c] + 0.5f * acc;
        x2s[c] = v;
        x2[(size_t)r * Cn + c] = v;
        s0 += v;
    }
    int t = r % Tn;
    if (t == 0) return;
    float mean = blockReduceSum256(s0, red) * (1.f / Cn);
    float s1 = 0.f;
    for (int c = tid; c < Cn; c += 256) { float d = x2s[c] - mean; s1 += d * d; }
    float var = blockReduceSum256(s1, red) * (1.f / Cn);
    float inv = rsqrtf(var + EPSf);
    int zi = (r / Tn) * 512 + (t - 1);
    float* zp = z + (size_t)zi * Cn;
    for (int c = tid; c < Cn; c += 256)
        zp[c] = tf32r((x2s[c] - mean) * inv);
}

// ---------------- view weight prep ----------------
__global__ void wprep_kernel(const float* __restrict__ aqw, const float* __restrict__ aqb,
                             const float* __restrict__ n3g, const float* __restrict__ n3b)
{
    int vj = blockIdx.x;
    int v = vj / 36;
    int tid = threadIdx.x;
    __shared__ float red[256];
    const float* w = aqw + (size_t)vj * Cn;
    const float* gg = n3g + (size_t)v * Cn;
    const float* bb = n3b + (size_t)v * Cn;
    float s = 0.f;
    for (int c = tid; c < Cn; c += 256) {
        float wv = w[c];
        g_weff[(size_t)vj * Cn + c] = tf32r(wv * gg[c]);
        s += wv * bb[c];
    }
    s = blockReduceSum256(s, red);
    if (tid == 0) g_beff[vj] = aqb[vj] + s;
}

// ---------------- cluster (3d) pooling chain ----------------
__global__ void pool_init(int R)
{
    int i = blockIdx.x * blockDim.x + threadIdx.x;
    if (i <= R) g_hist[i] = 0;
    if (i < Cn) { g_colsum[i] = 0.0; g_colsq[i] = 0.0; }
}
__global__ void hist_count(const int* __restrict__ idx)
{
    int i = blockIdx.x * blockDim.x + threadIdx.x;
    if (i < BG) atomicAdd(&g_hist[idx[i]], 1);
}
__global__ void scan_kernel(int R)
{
    __shared__ int part[1024];
    int tid = threadIdx.x;
    int chunk = (R + 1023) / 1024;
    int t0 = tid * chunk;
    int s = 0;
    for (int j = 0; j < chunk; j++)
        if (t0 + j < R) s += g_hist[t0 + j];
    part[tid] = s;
    __syncthreads();
    for (int off = 1; off < 1024; off <<= 1) {
        int v = (tid >= off) ? part[tid - off] : 0;
        __syncthreads();
        part[tid] += v;
        __syncthreads();
    }
    int run = (tid > 0) ? part[tid - 1] : 0;
    for (int j = 0; j < chunk; j++) {
        if (t0 + j < R) {
            int c = g_hist[t0 + j];
            g_off[t0 + j] = run;
            g_cur[t0 + j] = run;
            run += c;
        }
    }
    if (tid == 1023) g_off[R] = part[1023];
}
__global__ void seg_place(const int* __restrict__ idx)
{
    int i = blockIdx.x * blockDim.x + threadIdx.x;
    if (i >= BG) return;
    int p = atomicAdd(&g_cur[idx[i]], 1);
    g_ord[p] = i;
}
__global__ void seg_reduce(const float* __restrict__ src)
{
    int r = blockIdx.x;
    int tid = threadIdx.x;
    int s0 = g_off[r], s1 = g_off[r + 1];
    float mx0 = -1e30f, mx1 = -1e30f, mx2 = -1e30f;
    float sm0 = 0.f, sm1 = 0.f, sm2 = 0.f;
    for (int j = s0; j < s1; j++) {
        int i = g_ord[j];
        const float* p = src + (size_t)featRow(i) * Cn;
        float v0 = p[tid], v1 = p[tid + 256], v2 = p[tid + 512];
        mx0 = fmaxf(mx0, v0); sm0 += v0;
        mx1 = fmaxf(mx1, v1); sm1 += v1;
        mx2 = fmaxf(mx2, v2); sm2 += v2;
    }
    int cnt = s1 - s0;
    float inv = 1.f / (float)(cnt > 0 ? cnt : 1);
    float* op = g_scomb + (size_t)r * Cn;
    op[tid]       = (cnt > 0 ? mx0 : 0.f) + sm0 * inv;
    op[tid + 256] = (cnt > 0 ? mx1 : 0.f) + sm1 * inv;
    op[tid + 512] = (cnt > 0 ? mx2 : 0.f) + sm2 * inv;
}
__global__ void colstats(int R)
{
    int col = blockIdx.x * blockDim.x + threadIdx.x;
    if (col >= Cn) return;
    int chunk = (R + gridDim.y - 1) / gridDim.y;
    int r0 = blockIdx.y * chunk;
    int r1 = min(r0 + chunk, R);
    float sum = 0.f, sq = 0.f;
    for (int r = r0; r < r1; r++) {
        float v = g_scomb[(size_t)r * Cn + col];
        sum += v; sq += v * v;
    }
    atomicAdd(&g_colsum[col], (double)sum);
    atomicAdd(&g_colsq[col], (double)sq);
}
__global__ void colfinal(int R)
{
    int col = blockIdx.x * blockDim.x + threadIdx.x;
    if (col >= Cn) return;
    double mean = g_colsum[col] / R;
    double var = g_colsq[col] / R - mean * mean;
    if (var < 0.0) var = 0.0;
    g_mean[col] = (float)mean;
    g_rstd[col] = rsqrtf((float)var + EPSf);
}
__global__ void bn_apply(const float* __restrict__ gam, const float* __restrict__ bet,
                         float* __restrict__ out, int R)
{
    int i = blockIdx.x * blockDim.x + threadIdx.x;
    if (i >= R * Cn) return;
    int col = i % Cn;
    float v = (g_scomb[i] - g_mean[col]) * g_rstd[col] * gam[col] + bet[col];
    out[i] = gelu_exact(v);
}

// ---------------- batched (x6 views) pooling chain ----------------
__global__ void pool_init6()
{
    int v = blockIdx.y;
    int i = blockIdx.x * blockDim.x + threadIdx.x;
    if (i <= D1n) g_hist6[v * (D1n + 1) + i] = 0;
    if (i < Cn) { g_colsum6[v * Cn + i] = 0.0; g_colsq6[v * Cn + i] = 0.0; }
}
__global__ void hist_count6(const int* __restrict__ fgi)
{
    int v = blockIdx.y;
    int i = blockIdx.x * blockDim.x + threadIdx.x;
    if (i < BG) atomicAdd(&g_hist6[v * (D1n + 1) + fgi[(size_t)v * BG + i]], 1);
}
__global__ void scan6()
{
    int v = blockIdx.x;
    int* hist = g_hist6 + v * (D1n + 1);
    int* off  = g_off6  + v * (D1n + 1);
    int* cur  = g_cur6  + v * (D1n + 1);
    __shared__ int part[1024];
    int tid = threadIdx.x;
    const int R = D1n;
    int chunk = (R + 1023) / 1024;
    int t0 = tid * chunk;
    int s = 0;
    for (int j = 0; j < chunk; j++)
        if (t0 + j < R) s += hist[t0 + j];
    part[tid] = s;
    __syncthreads();
    for (int off2 = 1; off2 < 1024; off2 <<= 1) {
        int vv = (tid >= off2) ? part[tid - off2] : 0;
        __syncthreads();
        part[tid] += vv;
        __syncthreads();
    }
    int run = (tid > 0) ? part[tid - 1] : 0;
    for (int j = 0; j < chunk; j++) {
        if (t0 + j < R) {
            int c = hist[t0 + j];
            off[t0 + j] = run;
            cur[t0 + j] = run;
            run += c;
        }
    }
    if (tid == 1023) off[R] = part[1023];
}
__global__ void seg_place6(const int* __restrict__ fgi)
{
    int v = blockIdx.y;
    int i = blockIdx.x * blockDim.x + threadIdx.x;
    if (i >= BG) return;
    int p = atomicAdd(&g_cur6[v * (D1n + 1) + fgi[(size_t)v * BG + i]], 1);
    g_ord6[(size_t)v * BG + p] = i;
}
__global__ void view_attn6(const float* __restrict__ qkv1, const unsigned char* __restrict__ mask)
{
    int blk = blockIdx.x, h = blockIdx.y, v = blockIdx.z;
    int t = threadIdx.x;
    __shared__ float kk[N1n][2];
    __shared__ float vv[N1n][2];
    int row = blk * N1n + t;
    const float* base = qkv1 + (size_t)row * NQ1 + v * 36;
    float q0 = base[h * 2]     * 0.28867513459481287f;
    float q1 = base[h * 2 + 1] * 0.28867513459481287f;
    kk[t][0] = base[12 + h * 2]; kk[t][1] = base[13 + h * 2];
    vv[t][0] = base[24 + h * 2]; vv[t][1] = base[25 + h * 2];
    __syncthreads();
    const unsigned char* mrow = mask + (size_t)v * NB1 * N1n * N1n + ((size_t)blk * N1n + t) * N1n;
    float mmax = -1e30f;
    #pragma unroll 4
    for (int j = 0; j < N1n; j++) {
        float s = q0 * kk[j][0] + q1 * kk[j][1] + (mrow[j] ? -100000.f : 0.f);
        mmax = fmaxf(mmax, s);
    }
    float l = 0.f, a0 = 0.f, a1 = 0.f;
    #pragma unroll 4
    for (int j = 0; j < N1n; j++) {
        float s = q0 * kk[j][0] + q1 * kk[j][1] + (mrow[j] ? -100000.f : 0.f);
        float p = expf(s - mmax);
        l += p; a0 += p * vv[j][0]; a1 += p * vv[j][1];
    }
    float* o1 = g_o16 + (size_t)v * BG * MIDn;
    o1[(size_t)row * MIDn + h * 2]     = a0 / l;
    o1[(size_t)row * MIDn + h * 2 + 1] = a1 / l;
}
__global__ void seg_reduce_view6(const float* __restrict__ apw, const float* __restrict__ apb,
                                 const float* __restrict__ x2)
{
    int r = blockIdx.x, v = blockIdx.y;
    int tid = threadIdx.x;
    const int* off = g_off6 + v * (D1n + 1);
    const int* ord = g_ord6 + (size_t)v * BG;
    const float* o1 = g_o16 + (size_t)v * BG * MIDn;
    const float* pw = apw + (size_t)v * Cn * MIDn;
    const float* pb = apb + (size_t)v * Cn;
    int s0 = off[r], s1 = off[r + 1];
    float wr[3][MIDn], pbv[3];
    #pragma unroll
    for (int ch = 0; ch < 3; ch++) {
        int c = tid + ch * 256;
        pbv[ch] = pb[c];
        #pragma unroll
        for (int k = 0; k < MIDn; k++) wr[ch][k] = __ldg(&pw[(size_t)c * MIDn + k]);
    }
    float mx[3] = {-1e30f, -1e30f, -1e30f};
    float sm[3] = {0.f, 0.f, 0.f};
    for (int j = s0; j < s1; j++) {
        int i = ord[j];
        const float4* ob = (const float4*)&o1[(size_t)i * MIDn];
        float4 o0 = __ldg(ob), o1v = __ldg(ob + 1), o2 = __ldg(ob + 2);
        float os[MIDn] = {o0.x, o0.y, o0.z, o0.w, o1v.x, o1v.y, o1v.z, o1v.w,
                          o2.x, o2.y, o2.z, o2.w};
        const float* xp = x2 + (size_t)featRow(i) * Cn;
        #pragma unroll
        for (int ch = 0; ch < 3; ch++) {
            float vv = pbv[ch] + xp[tid + ch * 256];
            #pragma unroll
            for (int k = 0; k < MIDn; k++) vv += os[k] * wr[ch][k];
            mx[ch] = fmaxf(mx[ch], vv);
            sm[ch] += vv;
        }
    }
    int cnt = s1 - s0;
    float inv = 1.f / (float)(cnt > 0 ? cnt : 1);
    float* op = g_scomb6 + ((size_t)v * D1n + r) * Cn;
    #pragma unroll
    for (int ch = 0; ch < 3; ch++)
        op[tid + ch * 256] = (cnt > 0 ? mx[ch] : 0.f) + sm[ch] * inv;
}
__global__ void colstats6()
{
    int col = blockIdx.x * blockDim.x + threadIdx.x;
    int v = blockIdx.z;
    if (col >= Cn) return;
    const int R = D1n;
    int chunk = (R + gridDim.y - 1) / gridDim.y;
    int r0 = blockIdx.y * chunk;
    int r1 = min(r0 + chunk, R);
    float sum = 0.f, sq = 0.f;
    const float* sc = g_scomb6 + (size_t)v * D1n * Cn;
    for (int r = r0; r < r1; r++) {
        float vv = sc[(size_t)r * Cn + col];
        sum += vv; sq += vv * vv;
    }
    atomicAdd(&g_colsum6[v * Cn + col], (double)sum);
    atomicAdd(&g_colsq6[v * Cn + col], (double)sq);
}
__global__ void colfinal6()
{
    int col = blockIdx.x * blockDim.x + threadIdx.x;
    int v = blockIdx.y;
    if (col >= Cn) return;
    double mean = g_colsum6[v * Cn + col] / D1n;
    double var = g_colsq6[v * Cn + col] / D1n - mean * mean;
    if (var < 0.0) var = 0.0;
    g_mean6[v * Cn + col] = (float)mean;
    g_rstd6[v * Cn + col] = rsqrtf((float)var + EPSf);
}
__global__ void bn_apply6(const float* __restrict__ bn1dg, const float* __restrict__ bn1db,
                          float* __restrict__ bview)
{
    int v = blockIdx.y;
    int i = blockIdx.x * blockDim.x + threadIdx.x;
    if (i >= D1n * Cn) return;
    int col = i % Cn;
    float vv = (g_scomb6[(size_t)v * D1n * Cn + i] - g_mean6[v * Cn + col]) * g_rstd6[v * Cn + col]
               * bn1dg[v * Cn + col] + bn1db[v * Cn + col];
    bview[(size_t)v * D1n * Cn + i] = gelu_exact(vv);
}

// ---------------- final fusion ----------------
__global__ void final_kernel(const float* __restrict__ x2, const float* __restrict__ g3,
                             const float* __restrict__ bview, const int* __restrict__ cluster,
                             const int* __restrict__ fgi, float* __restrict__ out)
{
    int i = blockIdx.x;
    int tid = threadIdx.x;
    size_t xrow = (size_t)featRow(i);
    __shared__ float x3[Cn];
    __shared__ float pv[NV][Cn];
    __shared__ float red[256];
    __shared__ float sims[NV];
    int cl = cluster[i];
    const float* x3p = g3 + (size_t)cl * Cn;
    for (int c = tid; c < Cn; c += 256) x3[c] = x3p[c];
    for (int v = 0; v < NV; v++) {
        int id = fgi[(size_t)v * BG + i];
        const float* pp = bview + ((size_t)v * D1n + id) * Cn;
        for (int c = tid; c < Cn; c += 256) pv[v][c] = pp[c];
    }
    __syncthreads();
    float p = 0.f;
    for (int c = tid; c < Cn; c += 256) p += x3[c] * x3[c];
    float nx3 = fmaxf(sqrtf(blockReduceSum256(p, red)), 1e-8f);
    for (int v = 0; v < NV; v++) {
        float d = 0.f, n = 0.f;
        for (int c = tid; c < Cn; c += 256) {
            float a = pv[v][c];
            d += a * x3[c]; n += a * a;
        }
        d = blockReduceSum256(d, red);
        n = blockReduceSum256(n, red);
        if (tid == 0) {
            float np = fmaxf(sqrtf(n), 1e-8f);
            float cs = d / (np * nx3);
            sims[v] = (cs + 1.f) * 0.5f;
        }
        __syncthreads();
    }
    float ssum = 0.f;
    #pragma unroll
    for (int v = 0; v < NV; v++) ssum += sims[v];
    float inv = 1.f / ssum;
    const float* x2p = x2 + xrow * Cn;
    float* op = out + xrow * Cn;
    for (int c = tid; c < Cn; c += 256) {
        float sup = 0.f;
        #pragma unroll
        for (int v = 0; v < NV; v++) sup += pv[v][c] * sims[v];
        op[c] = x2p[c] + 0.3f * sup * inv;
    }
}

__global__ void cls_copy(const float* __restrict__ x2, float* __restrict__ out)
{
    size_t row = (size_t)blockIdx.x * Tn;
    for (int c = threadIdx.x; c < Cn; c += blockDim.x)
        out[row * Cn + c] = x2[row * Cn + c];
}

// ---------------- host launch ----------------
extern "C" void kernel_launch(void* const* d_in, const int* in_sizes, int n_in,
                              void* d_out, int out_size)
{
    const float* x    = (const float*)d_in[0];
    const float* ln1g = (const float*)d_in[1];
    const float* ln1b = (const float*)d_in[2];
    const float* ln2g = (const float*)d_in[3];
    const float* ln2b = (const float*)d_in[4];
    const float* Wqkv = (const float*)d_in[5];
    const float* bqkv = (const float*)d_in[6];
    const float* Wo   = (const float*)d_in[7];
    const float* bo   = (const float*)d_in[8];
    const float* Wfc  = (const float*)d_in[9];
    const float* bfc  = (const float*)d_in[10];
    const float* Wproj= (const float*)d_in[11];
    const float* bproj= (const float*)d_in[12];
    const float* Wa1  = (const float*)d_in[13];
    const float* ba1  = (const float*)d_in[14];
    const float* Wa2  = (const float*)d_in[15];
    const float* ba2  = (const float*)d_in[16];
    const float* bn3dg= (const float*)d_in[17];
    const float* bn3db= (const float*)d_in[18];
    const float* bn1dg= (const float*)d_in[19];
    const float* bn1db= (const float*)d_in[20];
    const float* n3g  = (const float*)d_in[21];
    const float* n3b  = (const float*)d_in[22];
    const float* aqw  = (const float*)d_in[23];
    const float* aqb  = (const float*)d_in[24];
    const float* apw  = (const float*)d_in[25];
    const float* apb  = (const float*)d_in[26];
    const int*   cluster = (const int*)d_in[27];
    const int*   fgi  = (const int*)d_in[28];
    const unsigned char* mask = (const unsigned char*)d_in[29];
    float* out = (float*)d_out;

    float *y, *qkv, *att, *x1, *hfc, *xffn, *x2, *g3, *bview, *z, *qkv1, *weff, *beff;
    cudaGetSymbolAddress((void**)&y,     g_y);
    cudaGetSymbolAddress((void**)&qkv,   g_qkv);
    cudaGetSymbolAddress((void**)&att,   g_att);
    cudaGetSymbolAddress((void**)&x1,    g_x1);
    cudaGetSymbolAddress((void**)&hfc,   g_hfc);
    cudaGetSymbolAddress((void**)&xffn,  g_xffn);
    cudaGetSymbolAddress((void**)&x2,    g_x2);
    cudaGetSymbolAddress((void**)&g3,    g_g3);
    cudaGetSymbolAddress((void**)&bview, g_bview);
    cudaGetSymbolAddress((void**)&z,     g_z);
    cudaGetSymbolAddress((void**)&qkv1,  g_qkv1);
    cudaGetSymbolAddress((void**)&weff,  g_weff);
    cudaGetSymbolAddress((void**)&beff,  g_beff);

    cudaFuncSetAttribute(attn_tc, cudaFuncAttributeMaxDynamicSharedMemorySize, ATTN_SMEM);
    cudaFuncSetAttribute(gemm_tf32<0>, cudaFuncAttributeMaxDynamicSharedMemorySize, GEMM_SMEM);
    cudaFuncSetAttribute(gemm_tf32<1>, cudaFuncAttributeMaxDynamicSharedMemorySize, GEMM_SMEM);
    cudaFuncSetAttribute(gemm_tf32<2>, cudaFuncAttributeMaxDynamicSharedMemorySize, GEMM_SMEM);

    const int GMB = (MROWS + 127) / 128;  // 129

    // 1) LN1 -> y (tf32-rounded)
    ln_kernel<<<MROWS, 256>>>(x, ln1g, ln1b, y, 0);
    // 2) QKV GEMM (weights direct; HW truncation)
    gemm_tf32<0><<<dim3(GMB, (3 * Cn) / 128), 256, GEMM_SMEM>>>(y, Wqkv, bqkv, nullptr, qkv, MROWS, 3 * Cn, Cn);
    // 3) attention (tail fused into same launch as qb==4 blocks)
    attn_tc<<<dim3(5, Hn, Bn), 256, ATTN_SMEM>>>(qkv, att);
    // 4) output proj + residual
    gemm_tf32<2><<<dim3(GMB, Cn / 128), 256, GEMM_SMEM>>>(att, Wo, bo, x, x1, MROWS, Cn, Cn);
    // 5) LN2 -> y
    ln_kernel<<<MROWS, 256>>>(x1, ln2g, ln2b, y, 0);
    // 6) FC + quick_gelu
    gemm_tf32<1><<<dim3(GMB, FFn / 128), 256, GEMM_SMEM>>>(y, Wfc, bfc, nullptr, hfc, MROWS, FFn, Cn);
    // 7) proj
    gemm_tf32<0><<<dim3(GMB, Cn / 128), 256, GEMM_SMEM>>>(hfc, Wproj, bproj, nullptr, xffn, MROWS, Cn, FFn);
    // 8) adapter + residuals -> x2, fused plain LN -> z
    adapter_kernel<<<MROWS, 256>>>(xffn, x1, Wa1, ba1, Wa2, ba2, x2, z);

    // 9) 3d segment pool + BN over clusters
    {
        pool_init<<<(NCL + 1 + 255) / 256, 256>>>(NCL);
        hist_count<<<(BG + 255) / 256, 256>>>(cluster);
        scan_kernel<<<1, 1024>>>(NCL);
        seg_place<<<(BG + 255) / 256, 256>>>(cluster);
        seg_reduce<<<NCL, 256>>>(x2);
        colstats<<<dim3(3, 16), 256>>>(NCL);
        colfinal<<<3, 256>>>(NCL);
        bn_apply<<<(NCL * Cn + 255) / 256, 256>>>(bn3dg, bn3db, g3, NCL);
    }

    // 10) view branches (batched; z produced by adapter)
    wprep_kernel<<<NQ1, 256>>>(aqw, aqb, n3g, n3b);
    gemm_tf32<0><<<dim3(BG / 128, (NQ1 + 127) / 128), 256, GEMM_SMEM>>>(z, weff, beff, nullptr, qkv1,
                                                                        BG, NQ1, Cn);
    view_attn6<<<dim3(NB1, H1n, NV), N1n>>>(qkv1, mask);
    pool_init6<<<dim3((D1n + 1 + 255) / 256, NV), 256>>>();
    hist_count6<<<dim3((BG + 255) / 256, NV), 256>>>(fgi);
    scan6<<<NV, 1024>>>();
    seg_place6<<<dim3((BG + 255) / 256, NV), 256>>>(fgi);
    seg_reduce_view6<<<dim3(D1n, NV), 256>>>(apw, apb, x2);
    colstats6<<<dim3(3, 16, NV), 256>>>();
    colfinal6<<<dim3(3, NV), 256>>>();
    bn_apply6<<<dim3((D1n * Cn + 255) / 256, NV), 256>>>(bn1dg, bn1db, bview);

    // 11) cossim fusion + output
    final_kernel<<<BG, 256>>>(x2, g3, bview, cluster, fgi, out);
    cls_copy<<<Bn, 256>>>(x2, out);
}